// round 5
// baseline (speedup 1.0000x reference)
#include <cuda_runtime.h>
#include <cstdint>
#include <cstddef>

// Problem constants
#define NB   4096
#define NN   29
#define NC   6
#define CDIM 16
#define DD   22
#define HDIM 64
#define NL   2
#define NOUT 24
#define OUTROW 12
#define ZROW 25
#define PROW 76     // pi/pj row stride (19 float4 -> conflict-free LDS.128)
#define CATW 100
#define ATROW 68    // A-tile row stride: 17 float4 (STS.128 perfect), lq*4+cq banks (LDS.32 perfect)

// Shared memory layout (float offsets)
#define OFF_Z    0        // 800
#define OFF_ZN   800      // 800
#define OFF_PI   1600     // 2432
#define OFF_PJ   4032     // 2432
#define OFF_EW1  6464     // 2816
#define OFF_MAGG 9280     // 2048
#define OFF_H    11328    // 2048
#define OFF_GPB  13376    // 512
#define OFF_EBG  13888    // 128
#define OFF_AT   14016    // 4*32*68 = 8704 (A tiles, one per node in i-group)
#define SMEM_FLOATS 22720 // 90880 bytes
// catsh [32][100]=3200 aliases OFF_PI (piR+pjR dead after tile loop)

__device__ __forceinline__ float tanhfast(float x) {
    float y;
    asm("tanh.approx.f32 %0, %1;" : "=f"(y) : "f"(x));
    return y;
}
__device__ __forceinline__ float silu_t(float v) {
    float h = 0.5f * v;
    return fmaf(h, tanhfast(h), h);
}
__device__ __forceinline__ float sigm_t(float v) {
    return fmaf(0.5f, tanhfast(0.5f * v), 0.5f);
}
__device__ __forceinline__ uint32_t tf32_rna(float x) {
    uint32_t u;
    asm("cvt.rna.tf32.f32 %0, %1;" : "=r"(u) : "f"(x));
    return u;
}
__device__ __forceinline__ void mma_tf32(float c[4], uint32_t a0, uint32_t a1,
                                         uint32_t a2, uint32_t a3,
                                         uint32_t b0, uint32_t b1) {
    asm volatile(
        "mma.sync.aligned.m16n8k8.row.col.f32.tf32.tf32.f32 "
        "{%0,%1,%2,%3}, {%4,%5,%6,%7}, {%8,%9}, {%0,%1,%2,%3};\n"
        : "+f"(c[0]), "+f"(c[1]), "+f"(c[2]), "+f"(c[3])
        : "r"(a0), "r"(a1), "r"(a2), "r"(a3), "r"(b0), "r"(b1));
}

extern "C" __global__ void __launch_bounds__(256, 2)
gnn_kernel(const float* __restrict__ x,   const float* __restrict__ ctx,
           const float* __restrict__ eW1, const float* __restrict__ eb1,
           const float* __restrict__ eW2, const float* __restrict__ eb2,
           const float* __restrict__ gW,  const float* __restrict__ gb,
           const float* __restrict__ lng, const float* __restrict__ lnb,
           const float* __restrict__ nW1, const float* __restrict__ nb1,
           const float* __restrict__ nW2, const float* __restrict__ nb2,
           const float* __restrict__ hW1, const float* __restrict__ hb1,
           const float* __restrict__ hW2, const float* __restrict__ hb2,
           float* __restrict__ out)
{
    extern __shared__ float sh[];
    float* zsh   = sh + OFF_Z;
    float* znsh  = sh + OFF_ZN;
    float* piR   = sh + OFF_PI;    // [32][76]
    float* pjR   = sh + OFF_PJ;    // [32][76]
    float* ew1sh = sh + OFF_EW1;   // [44][64]
    float* magg  = sh + OFF_MAGG;  // [32][64]
    float* hbuf  = sh + OFF_H;     // [32][64]
    float* gpb   = sh + OFF_GPB;   // [par][ch][i_sel][32]
    float* ebg   = sh + OFF_EBG;   // [eb2(64) | gW(64)]
    float* atile = sh + OFF_AT;    // [4 nodes][32 rows][68] tf32 silu values
    float* catsh = sh + OFF_PI;    // [32][100] (aliases piR/pjR)

    const int b = blockIdx.x;
    const int t = threadIdx.x;
    const int w = t >> 5;
    const int lane = t & 31;
    const int lq = lane >> 2;
    const int cq = lane & 3;
    const int i_sel = w & 3;       // node within i-group
    const int ch = w >> 2;         // column half / build K-half

    // ---- load z = concat(x, context) ----
    for (int idx = t; idx < NN * DD; idx += 256) {
        int i = idx / DD, d = idx - i * DD;
        float v = (d < NC) ? x[(b * NN + i) * NC + d]
                           : ctx[(b * NN + i) * CDIM + (d - NC)];
        zsh[i * ZROW + d] = v;
    }
    __syncthreads();

    for (int l = 0; l < NL; ++l) {
        const float* eW1l = eW1 + l * 2 * DD * HDIM;
        const float* eb1l = eb1 + l * HDIM;
        const float* eW2l = eW2 + l * HDIM * HDIM;
        const float* eb2l = eb2 + l * HDIM;
        const float* gWl  = gW  + l * HDIM;
        const float  gbl  = gb[l];
        const float* lngl = lng + l * DD;
        const float* lnbl = lnb + l * DD;
        const float* nW1l = nW1 + l * (DD + HDIM) * HDIM;
        const float* nb1l = nb1 + l * HDIM;
        const float* nW2l = nW2 + l * HDIM * DD;
        const float* nb2l = nb2 + l * DD;

        // ---- B fragments in registers, once per layer (L2-hot) ----
        uint32_t breg[8][4][2];
        #pragma unroll
        for (int kk = 0; kk < 8; ++kk)
            #pragma unroll
            for (int nf = 0; nf < 4; ++nf) {
                int col = ch * 32 + nf * 8 + lq;
                breg[kk][nf][0] = tf32_rna(__ldg(eW2l + (kk * 8 + cq) * HDIM + col));
                breg[kk][nf][1] = tf32_rna(__ldg(eW2l + (kk * 8 + cq + 4) * HDIM + col));
            }

        // ---- stage eW1 + epilogue constants ----
        for (int idx = t; idx < 2 * DD * HDIM; idx += 256) ew1sh[idx] = eW1l[idx];
        if (t < HDIM) { ebg[t] = eb2l[t]; ebg[HDIM + t] = gWl[t]; }
        __syncthreads();

        // ---- pi / pj projections ----
        for (int idx = t; idx < 32 * HDIM; idx += 256) {
            int i = idx >> 6, k = idx & 63;
            float aI = 0.f, aJ = 0.f;
            if (i < NN) {
                #pragma unroll
                for (int d = 0; d < DD; ++d) {
                    float zv = zsh[i * ZROW + d];
                    aI += zv * ew1sh[d * HDIM + k];
                    aJ += zv * ew1sh[(DD + d) * HDIM + k];
                }
                aI += eb1l[k];
            }
            piR[i * PROW + k] = aI;
            pjR[i * PROW + k] = aJ;
        }
        // ---- layernorm ----
        if (t < NN) {
            float mu = 0.f, sq = 0.f;
            #pragma unroll
            for (int d = 0; d < DD; ++d) {
                float v = zsh[t * ZROW + d];
                mu += v; sq += v * v;
            }
            mu *= (1.0f / DD);
            float var = sq * (1.0f / DD) - mu * mu;
            float rs = rsqrtf(var + 1e-5f);
            #pragma unroll
            for (int d = 0; d < DD; ++d)
                znsh[t * ZROW + d] = (zsh[t * ZROW + d] - mu) * rs * lngl[d] + lnbl[d];
        }
        __syncthreads();

        // ---- 8 tiles: warp = (node, colhalf); A built once in SMEM, B in regs ----
        float* atn_w = atile + i_sel * (32 * ATROW);     // this node's A tile
        const float* pjrow = pjR + lane * PROW + ch * 32;
        float* dstrow = atn_w + lane * ATROW + ch * 32;

        for (int ig = 0; ig < 8; ++ig) {
            const int node = ig * 4 + i_sel;

            // ---- build: this warp fills rows=lane, k = ch*32..+31 ----
            {
                const float* pirow = piR + node * PROW + ch * 32;
                #pragma unroll
                for (int q = 0; q < 8; ++q) {
                    float4 pj4 = *(const float4*)(pjrow + q * 4);
                    float4 pi4 = *(const float4*)(pirow + q * 4);
                    float4 o;
                    o.x = __uint_as_float(tf32_rna(silu_t(pi4.x + pj4.x)));
                    o.y = __uint_as_float(tf32_rna(silu_t(pi4.y + pj4.y)));
                    o.z = __uint_as_float(tf32_rna(silu_t(pi4.z + pj4.z)));
                    o.w = __uint_as_float(tf32_rna(silu_t(pi4.w + pj4.w)));
                    *(float4*)(dstrow + q * 4) = o;
                }
            }
            asm volatile("bar.sync %0, %1;" :: "r"(i_sel + 1), "r"(64) : "memory");

            // ---- mainloop: 32 rows x 32 cols, K=64, A from SMEM, B from regs ----
            float acc[2][4][4];
            #pragma unroll
            for (int f = 0; f < 2; ++f)
                #pragma unroll
                for (int nf = 0; nf < 4; ++nf)
                    #pragma unroll
                    for (int e = 0; e < 4; ++e) acc[f][nf][e] = 0.f;

            #pragma unroll
            for (int kk = 0; kk < 8; ++kk) {
                const float* c0 = atn_w + kk * 8 + cq;
                uint32_t a00 = __float_as_uint(c0[lq * ATROW]);
                uint32_t a01 = __float_as_uint(c0[(lq + 8) * ATROW]);
                uint32_t a02 = __float_as_uint(c0[lq * ATROW + 4]);
                uint32_t a03 = __float_as_uint(c0[(lq + 8) * ATROW + 4]);
                uint32_t a10 = __float_as_uint(c0[(lq + 16) * ATROW]);
                uint32_t a11 = __float_as_uint(c0[(lq + 24) * ATROW]);
                uint32_t a12 = __float_as_uint(c0[(lq + 16) * ATROW + 4]);
                uint32_t a13 = __float_as_uint(c0[(lq + 24) * ATROW + 4]);
                #pragma unroll
                for (int nf = 0; nf < 4; ++nf) {
                    mma_tf32(acc[0][nf], a00, a01, a02, a03,
                             breg[kk][nf][0], breg[kk][nf][1]);
                    mma_tf32(acc[1][nf], a10, a11, a12, a13,
                             breg[kk][nf][0], breg[kk][nf][1]);
                }
            }

            // ---- epilogue: silu+bias, gate partials over our 32 cols ----
            float gp[4] = {0.f, 0.f, 0.f, 0.f};   // rows m*8+lq
            #pragma unroll
            for (int f = 0; f < 2; ++f)
                #pragma unroll
                for (int nf = 0; nf < 4; ++nf) {
                    float2 e2 = *(const float2*)(ebg + ch * 32 + nf * 8 + 2 * cq);
                    float2 g2 = *(const float2*)(ebg + HDIM + ch * 32 + nf * 8 + 2 * cq);
                    float v0 = silu_t(acc[f][nf][0] + e2.x);
                    float v1 = silu_t(acc[f][nf][1] + e2.y);
                    float v2 = silu_t(acc[f][nf][2] + e2.x);
                    float v3 = silu_t(acc[f][nf][3] + e2.y);
                    acc[f][nf][0] = v0; acc[f][nf][1] = v1;
                    acc[f][nf][2] = v2; acc[f][nf][3] = v3;
                    gp[f * 2]     = fmaf(v0, g2.x, fmaf(v1, g2.y, gp[f * 2]));
                    gp[f * 2 + 1] = fmaf(v2, g2.x, fmaf(v3, g2.y, gp[f * 2 + 1]));
                }
            #pragma unroll
            for (int m = 0; m < 4; ++m) {
                gp[m] += __shfl_xor_sync(0xffffffffu, gp[m], 1);
                gp[m] += __shfl_xor_sync(0xffffffffu, gp[m], 2);
            }
            // exchange gate partials with colhalf twin (also consume-done fence)
            float* slot = gpb + (ig & 1) * 256 + ch * 128 + i_sel * 32;
            if (cq == 0) {
                #pragma unroll
                for (int m = 0; m < 4; ++m) slot[m * 8 + lq] = gp[m];
            }
            asm volatile("bar.sync %0, %1;" :: "r"(i_sel + 1), "r"(64) : "memory");
            const float* pslot = gpb + (ig & 1) * 256 + (1 - ch) * 128 + i_sel * 32;
            float g[4];
            #pragma unroll
            for (int m = 0; m < 4; ++m) {
                int row = m * 8 + lq;
                float gt = sigm_t(gp[m] + pslot[row] + gbl);
                g[m] = (row < NN) ? gt : 0.f;
            }

            // ---- weighted j-aggregate, value-splitting reduction over lq ----
            float s8[8];
            #pragma unroll
            for (int nf = 0; nf < 4; ++nf) {
                s8[nf * 2] = fmaf(acc[0][nf][0], g[0],
                             fmaf(acc[0][nf][2], g[1],
                             fmaf(acc[1][nf][0], g[2], acc[1][nf][2] * g[3])));
                s8[nf * 2 + 1] = fmaf(acc[0][nf][1], g[0],
                                 fmaf(acc[0][nf][3], g[1],
                                 fmaf(acc[1][nf][1], g[2], acc[1][nf][3] * g[3])));
            }
            float v4[4];
            {
                int bb = lq & 1;
                #pragma unroll
                for (int j = 0; j < 4; ++j) {
                    float keep = bb ? s8[4 + j] : s8[j];
                    float send = bb ? s8[j]     : s8[4 + j];
                    v4[j] = keep + __shfl_xor_sync(0xffffffffu, send, 4);
                }
            }
            float v2a[2];
            {
                int bb = (lq >> 1) & 1;
                #pragma unroll
                for (int j = 0; j < 2; ++j) {
                    float keep = bb ? v4[2 + j] : v4[j];
                    float send = bb ? v4[j]     : v4[2 + j];
                    v2a[j] = keep + __shfl_xor_sync(0xffffffffu, send, 8);
                }
            }
            float v1f;
            {
                int bb = lq >> 2;
                float keep = bb ? v2a[1] : v2a[0];
                float send = bb ? v2a[0] : v2a[1];
                v1f = keep + __shfl_xor_sync(0xffffffffu, send, 16);
            }
            int nf_f = (lq & 1) * 2 + ((lq >> 1) & 1);
            int col = ch * 32 + nf_f * 8 + 2 * cq + (lq >> 2);
            magg[node * HDIM + col] = v1f;
        }
        __syncthreads();

        // ---- build concat buffer: [zn | m_i | 0-pad] ----
        for (int idx = t; idx < 32 * HDIM; idx += 256) {
            int i = idx >> 6, c = idx & 63;
            catsh[i * CATW + DD + c] = (i < NN) ? magg[idx] : 0.f;
        }
        for (int idx = t; idx < 32 * DD; idx += 256) {
            int i = idx / DD, d = idx - i * DD;
            catsh[i * CATW + d] = (i < NN) ? znsh[i * ZROW + d] : 0.f;
        }
        if (t < 64) catsh[(t >> 1) * CATW + 86 + (t & 1)] = 0.f;
        __syncthreads();

        // ---- node MLP layer 1 via MMA: [32 x 88] @ [86 x 64] ----
        {
            const int mh  = w & 1;
            const int nh4 = w >> 1;
            const int row0 = mh * 16 + lq, row1 = row0 + 8;
            float c2[2][4];
            #pragma unroll
            for (int nfi = 0; nfi < 2; ++nfi)
                #pragma unroll
                for (int e = 0; e < 4; ++e) c2[nfi][e] = 0.f;

            #pragma unroll
            for (int kk = 0; kk < 11; ++kk) {
                const int k0 = kk * 8 + cq, k1 = k0 + 4;
                uint32_t a0 = tf32_rna(catsh[row0 * CATW + k0]);
                uint32_t a1 = tf32_rna(catsh[row1 * CATW + k0]);
                uint32_t a2 = tf32_rna(catsh[row0 * CATW + k1]);
                uint32_t a3 = tf32_rna(catsh[row1 * CATW + k1]);
                #pragma unroll
                for (int nfi = 0; nfi < 2; ++nfi) {
                    const int col = (nh4 * 2 + nfi) * 8 + lq;
                    uint32_t b0 = tf32_rna(nW1l[k0 * HDIM + col]);
                    uint32_t b1 = (k1 < DD + HDIM)
                                ? tf32_rna(nW1l[k1 * HDIM + col]) : 0u;
                    mma_tf32(c2[nfi], a0, a1, a2, a3, b0, b1);
                }
            }
            #pragma unroll
            for (int nfi = 0; nfi < 2; ++nfi) {
                const int colb = (nh4 * 2 + nfi) * 8 + 2 * cq;
                float2 nb = *(const float2*)(nb1l + colb);
                *(float2*)(hbuf + row0 * HDIM + colb) =
                    make_float2(silu_t(c2[nfi][0] + nb.x), silu_t(c2[nfi][1] + nb.y));
                *(float2*)(hbuf + row1 * HDIM + colb) =
                    make_float2(silu_t(c2[nfi][2] + nb.x), silu_t(c2[nfi][3] + nb.y));
            }
        }
        __syncthreads();

        // ---- node MLP layer 2 + residual ----
        for (int idx = t; idx < NN * DD; idx += 256) {
            int i = idx / DD, d = idx - i * DD;
            float a = nb2l[d];
            #pragma unroll 8
            for (int m2 = 0; m2 < HDIM; ++m2)
                a += hbuf[i * HDIM + m2] * nW2l[m2 * DD + d];
            zsh[i * ZROW + d] += a;
        }
        __syncthreads();
    }

    // ---- mean pool ----
    if (t < DD) {
        float s = 0.f;
        #pragma unroll
        for (int i = 0; i < NN; ++i) s += zsh[i * ZROW + t];
        znsh[t] = s * (1.0f / NN);
    }
    __syncthreads();

    // ---- head MLP ----
    if (t < HDIM) {
        float a = hb1[t];
        #pragma unroll
        for (int d = 0; d < DD; ++d) a += znsh[d] * hW1[d * HDIM + t];
        hbuf[t] = fmaxf(a, 0.f);
    }
    __syncthreads();

    float* ob = out + (size_t)b * (NN * OUTROW);
    for (int idx = t; idx < NN * OUTROW; idx += 256) {
        float v = 0.f;
        if (idx < NOUT) {
            v = hb2[idx];
            #pragma unroll
            for (int m2 = 0; m2 < HDIM; ++m2)
                v += hbuf[m2] * hW2[m2 * NOUT + idx];
        }
        ob[idx] = v;
    }
}

extern "C" void kernel_launch(void* const* d_in, const int* in_sizes, int n_in,
                              void* d_out, int out_size) {
    (void)in_sizes; (void)n_in; (void)out_size;
    const float* x    = (const float*)d_in[0];
    const float* ctx  = (const float*)d_in[1];
    const float* eW1  = (const float*)d_in[2];
    const float* eb1  = (const float*)d_in[3];
    const float* eW2  = (const float*)d_in[4];
    const float* eb2  = (const float*)d_in[5];
    const float* gW   = (const float*)d_in[6];
    const float* gb   = (const float*)d_in[7];
    const float* lng  = (const float*)d_in[8];
    const float* lnb  = (const float*)d_in[9];
    const float* nW1  = (const float*)d_in[10];
    const float* nb1  = (const float*)d_in[11];
    const float* nW2  = (const float*)d_in[12];
    const float* nb2  = (const float*)d_in[13];
    const float* hW1  = (const float*)d_in[14];
    const float* hb1  = (const float*)d_in[15];
    const float* hW2  = (const float*)d_in[16];
    const float* hb2  = (const float*)d_in[17];
    float* out = (float*)d_out;

    cudaFuncSetAttribute(gnn_kernel, cudaFuncAttributeMaxDynamicSharedMemorySize,
                         SMEM_FLOATS * sizeof(float));
    gnn_kernel<<<NB, 256, SMEM_FLOATS * sizeof(float)>>>(
        x, ctx, eW1, eb1, eW2, eb2, gW, gb, lng, lnb,
        nW1, nb1, nW2, nb2, hW1, hb1, hW2, hb2, out);
}

// round 6
// speedup vs baseline: 1.3949x; 1.3949x over previous
#include <cuda_runtime.h>
#include <cuda_fp16.h>
#include <cstdint>
#include <cstddef>

// Problem constants
#define NB   4096
#define NN   29
#define NC   6
#define CDIM 16
#define DD   22
#define HDIM 64
#define NL   2
#define NOUT 24
#define OUTROW 12
#define ZROW 25
#define PROW 72     // pi/pj row stride: 36 float2-pairs; 36 % 16 == 4 -> conflict-free LDS.64
#define CATW 100
#define W2HW 136    // fp16 W2 row stride in floats: 34 float4; 136 % 32 == 8 -> LDS.128 phase-perfect

// Shared memory layout (float offsets)
#define OFF_Z    0        // 800
#define OFF_ZN   800      // 800
#define OFF_PI   1600     // 32*72 = 2304
#define OFF_PJ   3904     // 2304
#define OFF_W2H  6208     // 32*136 = 4352  (W2 as half2-packed float4 groups)
#define OFF_EW1  10560    // 44*64 = 2816
#define OFF_MAGG 13376    // 2*32*64 = 4096
#define OFF_H    17472    // 2048
#define SMEM_FLOATS 19520 // 78080 bytes
// catsh [32][100]=3200 aliases OFF_PI..(piR+pjR dead after tile loop; ends 4800 < 6208)

__device__ __forceinline__ float tanhfast(float x) {
    float y;
    asm("tanh.approx.f32 %0, %1;" : "=f"(y) : "f"(x));
    return y;
}
__device__ __forceinline__ float silu_t(float v) {
    float h = 0.5f * v;
    return fmaf(h, tanhfast(h), h);
}
__device__ __forceinline__ float sigm_t(float v) {
    return fmaf(0.5f, tanhfast(0.5f * v), 0.5f);
}
__device__ __forceinline__ uint32_t tf32_rna(float x) {
    uint32_t u;
    asm("cvt.rna.tf32.f32 %0, %1;" : "=r"(u) : "f"(x));
    return u;
}
__device__ __forceinline__ uint32_t pack_h2(float lo, float hi) {
    __half2 h = __floats2half2_rn(lo, hi);
    uint32_t u;
    asm("mov.b32 %0, %1;" : "=r"(u) : "r"(*(uint32_t*)&h));
    return u;
}
__device__ __forceinline__ void mma_f16(float c[4], uint32_t a0, uint32_t a1,
                                        uint32_t a2, uint32_t a3,
                                        uint32_t b0, uint32_t b1) {
    asm volatile(
        "mma.sync.aligned.m16n8k16.row.col.f32.f16.f16.f32 "
        "{%0,%1,%2,%3}, {%4,%5,%6,%7}, {%8,%9}, {%0,%1,%2,%3};\n"
        : "+f"(c[0]), "+f"(c[1]), "+f"(c[2]), "+f"(c[3])
        : "r"(a0), "r"(a1), "r"(a2), "r"(a3), "r"(b0), "r"(b1));
}
__device__ __forceinline__ void mma_tf32(float c[4], uint32_t a0, uint32_t a1,
                                         uint32_t a2, uint32_t a3,
                                         uint32_t b0, uint32_t b1) {
    asm volatile(
        "mma.sync.aligned.m16n8k8.row.col.f32.tf32.tf32.f32 "
        "{%0,%1,%2,%3}, {%4,%5,%6,%7}, {%8,%9}, {%0,%1,%2,%3};\n"
        : "+f"(c[0]), "+f"(c[1]), "+f"(c[2]), "+f"(c[3])
        : "r"(a0), "r"(a1), "r"(a2), "r"(a3), "r"(b0), "r"(b1));
}

extern "C" __global__ void __launch_bounds__(256, 2)
gnn_kernel(const float* __restrict__ x,   const float* __restrict__ ctx,
           const float* __restrict__ eW1, const float* __restrict__ eb1,
           const float* __restrict__ eW2, const float* __restrict__ eb2,
           const float* __restrict__ gW,  const float* __restrict__ gb,
           const float* __restrict__ lng, const float* __restrict__ lnb,
           const float* __restrict__ nW1, const float* __restrict__ nb1,
           const float* __restrict__ nW2, const float* __restrict__ nb2,
           const float* __restrict__ hW1, const float* __restrict__ hb1,
           const float* __restrict__ hW2, const float* __restrict__ hb2,
           float* __restrict__ out)
{
    extern __shared__ float sh[];
    float* zsh   = sh + OFF_Z;
    float* znsh  = sh + OFF_ZN;
    float* piR   = sh + OFF_PI;    // [32][72]
    float* pjR   = sh + OFF_PJ;    // [32][72]
    float* w2h   = sh + OFF_W2H;   // [32 kp][34 float4] half2-packed
    float* ew1sh = sh + OFF_EW1;   // [44][64]
    float* magg  = sh + OFF_MAGG;  // [2][32][64]
    float* hbuf  = sh + OFF_H;     // [32][64]
    float* catsh = sh + OFF_PI;    // [32][100] (aliases piR/pjR)

    const int b = blockIdx.x;
    const int t = threadIdx.x;
    const int w = t >> 5;
    const int lane = t & 31;
    const int lq = lane >> 2;      // groupID 0..7
    const int cq = lane & 3;       // threadID-in-group 0..3
    const int i_sel = w >> 1;      // node within i-group (0..3)
    const int jh = w & 1;          // jj half
    const int r0 = jh * 16 + lq;   // always < NN
    const int r1 = r0 + 8;         // masked when >= NN

    // ---- load z = concat(x, context) ----
    for (int idx = t; idx < NN * DD; idx += 256) {
        int i = idx / DD, d = idx - i * DD;
        float v = (d < NC) ? x[(b * NN + i) * NC + d]
                           : ctx[(b * NN + i) * CDIM + (d - NC)];
        zsh[i * ZROW + d] = v;
    }
    __syncthreads();

    for (int l = 0; l < NL; ++l) {
        const float* eW1l = eW1 + l * 2 * DD * HDIM;
        const float* eb1l = eb1 + l * HDIM;
        const float* eW2l = eW2 + l * HDIM * HDIM;
        const float* eb2l = eb2 + l * HDIM;
        const float* gWl  = gW  + l * HDIM;
        const float  gbl  = gb[l];
        const float* lngl = lng + l * DD;
        const float* lnbl = lnb + l * DD;
        const float* nW1l = nW1 + l * (DD + HDIM) * HDIM;
        const float* nb1l = nb1 + l * HDIM;
        const float* nW2l = nW2 + l * HDIM * DD;
        const float* nb2l = nb2 + l * DD;

        // ---- stage W2 as half2-packed float4 groups ----
        // For kp = kk*4+cqv (k0 = kk*16+2cqv), c in 0..31:
        //   float4 = { h2(W2[k0][c],W2[k0+1][c]), h2(W2[k0+8][c],W2[k0+9][c]),
        //              h2(W2[k0][c+32],..+1),     h2(W2[k0+8][c+32],..+9) }
        for (int e = t; e < 1024; e += 256) {
            int kp = e >> 5, c = e & 31;
            int kk = kp >> 2, cqv = kp & 3;
            int k0 = kk * 16 + 2 * cqv;
            float4 q;
            q.x = __uint_as_float(pack_h2(eW2l[k0 * 64 + c],        eW2l[(k0 + 1) * 64 + c]));
            q.y = __uint_as_float(pack_h2(eW2l[(k0 + 8) * 64 + c],  eW2l[(k0 + 9) * 64 + c]));
            q.z = __uint_as_float(pack_h2(eW2l[k0 * 64 + c + 32],   eW2l[(k0 + 1) * 64 + c + 32]));
            q.w = __uint_as_float(pack_h2(eW2l[(k0 + 8) * 64 + c + 32], eW2l[(k0 + 9) * 64 + c + 32]));
            *(float4*)(w2h + kp * W2HW + c * 4) = q;
        }
        for (int idx = t; idx < 2 * DD * HDIM; idx += 256) ew1sh[idx] = eW1l[idx];
        __syncthreads();

        // ---- pi / pj projections ----
        for (int idx = t; idx < 32 * HDIM; idx += 256) {
            int i = idx >> 6, k = idx & 63;
            float aI = 0.f, aJ = 0.f;
            if (i < NN) {
                #pragma unroll
                for (int d = 0; d < DD; ++d) {
                    float zv = zsh[i * ZROW + d];
                    aI += zv * ew1sh[d * HDIM + k];
                    aJ += zv * ew1sh[(DD + d) * HDIM + k];
                }
                aI += eb1l[k];
            }
            piR[i * PROW + k] = aI;
            pjR[i * PROW + k] = aJ;
        }
        // ---- layernorm ----
        if (t < NN) {
            float mu = 0.f, sq = 0.f;
            #pragma unroll
            for (int d = 0; d < DD; ++d) {
                float v = zsh[t * ZROW + d];
                mu += v; sq += v * v;
            }
            mu *= (1.0f / DD);
            float var = sq * (1.0f / DD) - mu * mu;
            float rs = rsqrtf(var + 1e-5f);
            #pragma unroll
            for (int d = 0; d < DD; ++d)
                znsh[t * ZROW + d] = (zsh[t * ZROW + d] - mu) * rs * lngl[d] + lnbl[d];
        }
        __syncthreads();

        // per-thread epilogue constants: cols nf*8 + 2cq (+1), nf 0..7
        float eb2v[16], gwv[16];
        #pragma unroll
        for (int nf = 0; nf < 8; ++nf) {
            int c = nf * 8 + cq * 2;
            float2 e2 = *(const float2*)(eb2l + c);
            float2 g2 = *(const float2*)(gWl + c);
            eb2v[nf * 2] = e2.x; eb2v[nf * 2 + 1] = e2.y;
            gwv[nf * 2]  = g2.x; gwv[nf * 2 + 1]  = g2.y;
        }

        const float* pj0b = pjR + r0 * PROW;
        const float* pj1b = pjR + r1 * PROW;

        // ---- 8 tiles; warp = (node, jj-half), full 64 cols, ZERO intra-tile syncs ----
        for (int ig = 0; ig < 8; ++ig) {
            const int node = ig * 4 + i_sel;
            const float* pib = piR + node * PROW;

            float acc[8][4];
            #pragma unroll
            for (int nf = 0; nf < 8; ++nf)
                #pragma unroll
                for (int e = 0; e < 4; ++e) acc[nf][e] = 0.f;

            #pragma unroll
            for (int kk = 0; kk < 4; ++kk) {
                const int ka = kk * 16 + 2 * cq;
                float2 pi0  = *(const float2*)(pib + ka);
                float2 pi1  = *(const float2*)(pib + ka + 8);
                float2 pj00 = *(const float2*)(pj0b + ka);
                float2 pj01 = *(const float2*)(pj0b + ka + 8);
                float2 pj10 = *(const float2*)(pj1b + ka);
                float2 pj11 = *(const float2*)(pj1b + ka + 8);
                uint32_t a0 = pack_h2(silu_t(pi0.x + pj00.x), silu_t(pi0.y + pj00.y)); // r0,k
                uint32_t a1 = pack_h2(silu_t(pi0.x + pj10.x), silu_t(pi0.y + pj10.y)); // r1,k
                uint32_t a2 = pack_h2(silu_t(pi1.x + pj01.x), silu_t(pi1.y + pj01.y)); // r0,k+8
                uint32_t a3 = pack_h2(silu_t(pi1.x + pj11.x), silu_t(pi1.y + pj11.y)); // r1,k+8
                const float* wb = w2h + (kk * 4 + cq) * W2HW + lq * 4;
                #pragma unroll
                for (int nf = 0; nf < 4; ++nf) {
                    float4 q = *(const float4*)(wb + nf * 32);
                    mma_f16(acc[nf],     a0, a1, a2, a3,
                            __float_as_uint(q.x), __float_as_uint(q.y));
                    mma_f16(acc[nf + 4], a0, a1, a2, a3,
                            __float_as_uint(q.z), __float_as_uint(q.w));
                }
            }

            // ---- epilogue: silu+bias, in-warp gate ----
            float gp0 = 0.f, gp1 = 0.f;
            #pragma unroll
            for (int nf = 0; nf < 8; ++nf) {
                float v0 = silu_t(acc[nf][0] + eb2v[nf * 2]);
                float v1 = silu_t(acc[nf][1] + eb2v[nf * 2 + 1]);
                float v2 = silu_t(acc[nf][2] + eb2v[nf * 2]);
                float v3 = silu_t(acc[nf][3] + eb2v[nf * 2 + 1]);
                acc[nf][0] = v0; acc[nf][1] = v1; acc[nf][2] = v2; acc[nf][3] = v3;
                gp0 = fmaf(v0, gwv[nf * 2], fmaf(v1, gwv[nf * 2 + 1], gp0));
                gp1 = fmaf(v2, gwv[nf * 2], fmaf(v3, gwv[nf * 2 + 1], gp1));
            }
            gp0 += __shfl_xor_sync(0xffffffffu, gp0, 1);
            gp0 += __shfl_xor_sync(0xffffffffu, gp0, 2);
            gp1 += __shfl_xor_sync(0xffffffffu, gp1, 1);
            gp1 += __shfl_xor_sync(0xffffffffu, gp1, 2);
            float g0 = sigm_t(gp0 + gbl);                     // r0 < NN always
            float g1 = (r1 < NN) ? sigm_t(gp1 + gbl) : 0.f;

            // ---- weighted j-aggregate ----
            float s16[16];
            #pragma unroll
            for (int nf = 0; nf < 8; ++nf) {
                s16[nf * 2]     = fmaf(acc[nf][0], g0, acc[nf][2] * g1);
                s16[nf * 2 + 1] = fmaf(acc[nf][1], g0, acc[nf][3] * g1);
            }
            // value-splitting reduction over the 8 lq lanes (14 shuffles)
            const int bb0 = lq & 1, bb1 = (lq >> 1) & 1, bb2 = (lq >> 2) & 1;
            float v8[8];
            #pragma unroll
            for (int j = 0; j < 8; ++j) {
                float keep = bb0 ? s16[8 + j] : s16[j];
                float send = bb0 ? s16[j]     : s16[8 + j];
                v8[j] = keep + __shfl_xor_sync(0xffffffffu, send, 4);
            }
            float v4a[4];
            #pragma unroll
            for (int j = 0; j < 4; ++j) {
                float keep = bb1 ? v8[4 + j] : v8[j];
                float send = bb1 ? v8[j]     : v8[4 + j];
                v4a[j] = keep + __shfl_xor_sync(0xffffffffu, send, 8);
            }
            float v2a[2];
            #pragma unroll
            for (int j = 0; j < 2; ++j) {
                float keep = bb2 ? v4a[2 + j] : v4a[j];
                float send = bb2 ? v4a[j]     : v4a[2 + j];
                v2a[j] = keep + __shfl_xor_sync(0xffffffffu, send, 16);
            }
            // lane holds cols nfv*8 + 2cq + {0,1}
            const int nfv = bb0 * 4 + bb1 * 2 + bb2;
            *(float2*)(magg + jh * 2048 + node * HDIM + nfv * 8 + 2 * cq) =
                make_float2(v2a[0], v2a[1]);
        }
        __syncthreads();

        // ---- build concat buffer: [zn | m_i | 0-pad] (combines jh halves) ----
        for (int idx = t; idx < 32 * HDIM; idx += 256) {
            int i = idx >> 6, c = idx & 63;
            float v = (i < NN) ? magg[idx] + magg[2048 + idx] : 0.f;
            catsh[i * CATW + DD + c] = v;
        }
        for (int idx = t; idx < 32 * DD; idx += 256) {
            int i = idx / DD, d = idx - i * DD;
            catsh[i * CATW + d] = (i < NN) ? znsh[i * ZROW + d] : 0.f;
        }
        if (t < 64) catsh[(t >> 1) * CATW + 86 + (t & 1)] = 0.f;
        __syncthreads();

        // ---- node MLP layer 1 via MMA: [32 x 88] @ [86 x 64] ----
        {
            const int mh  = w & 1;
            const int nh4 = w >> 1;
            const int row0 = mh * 16 + lq, row1 = row0 + 8;
            float c2[2][4];
            #pragma unroll
            for (int nfi = 0; nfi < 2; ++nfi)
                #pragma unroll
                for (int e = 0; e < 4; ++e) c2[nfi][e] = 0.f;

            #pragma unroll
            for (int kk = 0; kk < 11; ++kk) {
                const int k0 = kk * 8 + cq, k1 = k0 + 4;
                uint32_t a0 = tf32_rna(catsh[row0 * CATW + k0]);
                uint32_t a1 = tf32_rna(catsh[row1 * CATW + k0]);
                uint32_t a2 = tf32_rna(catsh[row0 * CATW + k1]);
                uint32_t a3 = tf32_rna(catsh[row1 * CATW + k1]);
                #pragma unroll
                for (int nfi = 0; nfi < 2; ++nfi) {
                    const int col = (nh4 * 2 + nfi) * 8 + lq;
                    uint32_t b0 = tf32_rna(nW1l[k0 * HDIM + col]);
                    uint32_t b1 = (k1 < DD + HDIM)
                                ? tf32_rna(nW1l[k1 * HDIM + col]) : 0u;
                    mma_tf32(c2[nfi], a0, a1, a2, a3, b0, b1);
                }
            }
            #pragma unroll
            for (int nfi = 0; nfi < 2; ++nfi) {
                const int colb = (nh4 * 2 + nfi) * 8 + 2 * cq;
                float2 nb = *(const float2*)(nb1l + colb);
                *(float2*)(hbuf + row0 * HDIM + colb) =
                    make_float2(silu_t(c2[nfi][0] + nb.x), silu_t(c2[nfi][1] + nb.y));
                *(float2*)(hbuf + row1 * HDIM + colb) =
                    make_float2(silu_t(c2[nfi][2] + nb.x), silu_t(c2[nfi][3] + nb.y));
            }
        }
        __syncthreads();

        // ---- node MLP layer 2 + residual ----
        for (int idx = t; idx < NN * DD; idx += 256) {
            int i = idx / DD, d = idx - i * DD;
            float a = nb2l[d];
            #pragma unroll 8
            for (int m2 = 0; m2 < HDIM; ++m2)
                a += hbuf[i * HDIM + m2] * nW2l[m2 * DD + d];
            zsh[i * ZROW + d] += a;
        }
        __syncthreads();
    }

    // ---- mean pool ----
    if (t < DD) {
        float s = 0.f;
        #pragma unroll
        for (int i = 0; i < NN; ++i) s += zsh[i * ZROW + t];
        znsh[t] = s * (1.0f / NN);
    }
    __syncthreads();

    // ---- head MLP ----
    if (t < HDIM) {
        float a = hb1[t];
        #pragma unroll
        for (int d = 0; d < DD; ++d) a += znsh[d] * hW1[d * HDIM + t];
        hbuf[t] = fmaxf(a, 0.f);
    }
    __syncthreads();

    float* ob = out + (size_t)b * (NN * OUTROW);
    for (int idx = t; idx < NN * OUTROW; idx += 256) {
        float v = 0.f;
        if (idx < NOUT) {
            v = hb2[idx];
            #pragma unroll
            for (int m2 = 0; m2 < HDIM; ++m2)
                v += hbuf[m2] * hW2[m2 * NOUT + idx];
        }
        ob[idx] = v;
    }
}

extern "C" void kernel_launch(void* const* d_in, const int* in_sizes, int n_in,
                              void* d_out, int out_size) {
    (void)in_sizes; (void)n_in; (void)out_size;
    const float* x    = (const float*)d_in[0];
    const float* ctx  = (const float*)d_in[1];
    const float* eW1  = (const float*)d_in[2];
    const float* eb1  = (const float*)d_in[3];
    const float* eW2  = (const float*)d_in[4];
    const float* eb2  = (const float*)d_in[5];
    const float* gW   = (const float*)d_in[6];
    const float* gb   = (const float*)d_in[7];
    const float* lng  = (const float*)d_in[8];
    const float* lnb  = (const float*)d_in[9];
    const float* nW1  = (const float*)d_in[10];
    const float* nb1  = (const float*)d_in[11];
    const float* nW2  = (const float*)d_in[12];
    const float* nb2  = (const float*)d_in[13];
    const float* hW1  = (const float*)d_in[14];
    const float* hb1  = (const float*)d_in[15];
    const float* hW2  = (const float*)d_in[16];
    const float* hb2  = (const float*)d_in[17];
    float* out = (float*)d_out;

    cudaFuncSetAttribute(gnn_kernel, cudaFuncAttributeMaxDynamicSharedMemorySize,
                         SMEM_FLOATS * sizeof(float));
    gnn_kernel<<<NB, 256, SMEM_FLOATS * sizeof(float)>>>(
        x, ctx, eW1, eb1, eW2, eb2, gW, gb, lng, lnb,
        nW1, nb1, nW2, nb2, hW1, hb1, hW2, hb2, out);
}

// round 7
// speedup vs baseline: 1.5662x; 1.1228x over previous
#include <cuda_runtime.h>
#include <cuda_fp16.h>
#include <cstdint>
#include <cstddef>

// Problem constants
#define NB   4096
#define NN   29
#define NC   6
#define CDIM 16
#define DD   22
#define HDIM 64
#define NL   2
#define NOUT 24
#define OUTROW 12
#define ZROW 25
#define PROW 72     // pi/pj row stride
#define CATW 100
#define W2HW 136    // fp16 W2 row stride (floats): 136 % 32 == 8 -> LDS.128 phase-perfect
#define ZTW  52     // zt row stride: 52 % 32 == 20 -> conflict-free A frags
#define E1W  136    // ew1T row stride: offsets {0,8,16,24}+lq -> disjoint
#define HROW 68     // hbuf row stride: 68 % 32 == 4 -> conflict-free A frags
#define NW2W 24     // nw2s row stride: offsets {0,24,16,8}+lq -> disjoint

// Shared memory layout (float offsets)
#define OFF_Z    0        // 800
#define OFF_ZN   800      // 800
#define OFF_PI   1600     // 32*72 = 2304
#define OFF_PJ   3904     // 2304
#define OFF_W2H  6208     // 32*136 = 4352
#define OFF_EW1T 10560    // 48*136 = 6528
#define OFF_ZT   17088    // 32*52 = 1664
#define OFF_MAGG 18752    // 2*32*64 = 4096
#define OFF_H    22848    // 32*68 = 2176
#define OFF_NW2  25024    // 64*24 = 1536
#define SMEM_FLOATS 26560 // 106240 bytes (2 CTAs/SM: 207.5 KB)
// catsh [32][100]=3200 aliases OFF_PI..OFF_PI+4608 (piR+pjR dead after tile loop)

__device__ __forceinline__ float tanhfast(float x) {
    float y;
    asm("tanh.approx.f32 %0, %1;" : "=f"(y) : "f"(x));
    return y;
}
__device__ __forceinline__ float silu_t(float v) {
    float h = 0.5f * v;
    return fmaf(h, tanhfast(h), h);
}
__device__ __forceinline__ float sigm_t(float v) {
    return fmaf(0.5f, tanhfast(0.5f * v), 0.5f);
}
__device__ __forceinline__ uint32_t tf32_rna(float x) {
    uint32_t u;
    asm("cvt.rna.tf32.f32 %0, %1;" : "=r"(u) : "f"(x));
    return u;
}
__device__ __forceinline__ uint32_t pack_h2(float lo, float hi) {
    __half2 h = __floats2half2_rn(lo, hi);
    return *(uint32_t*)&h;
}
__device__ __forceinline__ void mma_f16(float c[4], uint32_t a0, uint32_t a1,
                                        uint32_t a2, uint32_t a3,
                                        uint32_t b0, uint32_t b1) {
    asm volatile(
        "mma.sync.aligned.m16n8k16.row.col.f32.f16.f16.f32 "
        "{%0,%1,%2,%3}, {%4,%5,%6,%7}, {%8,%9}, {%0,%1,%2,%3};\n"
        : "+f"(c[0]), "+f"(c[1]), "+f"(c[2]), "+f"(c[3])
        : "r"(a0), "r"(a1), "r"(a2), "r"(a3), "r"(b0), "r"(b1));
}
__device__ __forceinline__ void mma_tf32(float c[4], uint32_t a0, uint32_t a1,
                                         uint32_t a2, uint32_t a3,
                                         uint32_t b0, uint32_t b1) {
    asm volatile(
        "mma.sync.aligned.m16n8k8.row.col.f32.tf32.tf32.f32 "
        "{%0,%1,%2,%3}, {%4,%5,%6,%7}, {%8,%9}, {%0,%1,%2,%3};\n"
        : "+f"(c[0]), "+f"(c[1]), "+f"(c[2]), "+f"(c[3])
        : "r"(a0), "r"(a1), "r"(a2), "r"(a3), "r"(b0), "r"(b1));
}

extern "C" __global__ void __launch_bounds__(256, 2)
gnn_kernel(const float* __restrict__ x,   const float* __restrict__ ctx,
           const float* __restrict__ eW1, const float* __restrict__ eb1,
           const float* __restrict__ eW2, const float* __restrict__ eb2,
           const float* __restrict__ gW,  const float* __restrict__ gb,
           const float* __restrict__ lng, const float* __restrict__ lnb,
           const float* __restrict__ nW1, const float* __restrict__ nb1,
           const float* __restrict__ nW2, const float* __restrict__ nb2,
           const float* __restrict__ hW1, const float* __restrict__ hb1,
           const float* __restrict__ hW2, const float* __restrict__ hb2,
           float* __restrict__ out)
{
    extern __shared__ float sh[];
    float* zsh   = sh + OFF_Z;
    float* znsh  = sh + OFF_ZN;
    float* piR   = sh + OFF_PI;    // [32][72]
    float* pjR   = sh + OFF_PJ;    // [32][72]
    float* w2h   = sh + OFF_W2H;   // [32][136] half2-packed fp16 W2
    float* ew1T  = sh + OFF_EW1T;  // [48][136] tf32, cols = [pi(64) | pj(64)]
    float* zt    = sh + OFF_ZT;    // [32][52] tf32 z, zero-padded
    float* magg  = sh + OFF_MAGG;  // [2][32][64]
    float* hbuf  = sh + OFF_H;     // [32][68] tf32
    float* nw2s  = sh + OFF_NW2;   // [64][24] tf32
    float* catsh = sh + OFF_PI;    // [32][100] aliases piR/pjR

    const int b = blockIdx.x;
    const int t = threadIdx.x;
    const int w = t >> 5;
    const int lane = t & 31;
    const int lq = lane >> 2;
    const int cq = lane & 3;
    const int i_sel = w >> 1;      // node within i-group
    const int jh = w & 1;          // jj half
    const int r0 = jh * 16 + lq;
    const int r1 = r0 + 8;

    // ---- load z = concat(x, context) ----
    for (int idx = t; idx < NN * DD; idx += 256) {
        int i = idx / DD, d = idx - i * DD;
        float v = (d < NC) ? x[(b * NN + i) * NC + d]
                           : ctx[(b * NN + i) * CDIM + (d - NC)];
        zsh[i * ZROW + d] = v;
    }
    __syncthreads();

    for (int l = 0; l < NL; ++l) {
        const float* eW1l = eW1 + l * 2 * DD * HDIM;
        const float* eb1l = eb1 + l * HDIM;
        const float* eW2l = eW2 + l * HDIM * HDIM;
        const float* eb2l = eb2 + l * HDIM;
        const float* gWl  = gW  + l * HDIM;
        const float  gbl  = gb[l];
        const float* lngl = lng + l * DD;
        const float* lnbl = lnb + l * DD;
        const float* nW1l = nW1 + l * (DD + HDIM) * HDIM;
        const float* nb1l = nb1 + l * HDIM;
        const float* nW2l = nW2 + l * HDIM * DD;
        const float* nb2l = nb2 + l * DD;

        // ======== staging: w2h, ew1T, zt, nw2s ========
        for (int e = t; e < 1024; e += 256) {
            int kp = e >> 5, c = e & 31;
            int kk = kp >> 2, cqv = kp & 3;
            int k0 = kk * 16 + 2 * cqv;
            float4 q;
            q.x = __uint_as_float(pack_h2(eW2l[k0 * 64 + c],        eW2l[(k0 + 1) * 64 + c]));
            q.y = __uint_as_float(pack_h2(eW2l[(k0 + 8) * 64 + c],  eW2l[(k0 + 9) * 64 + c]));
            q.z = __uint_as_float(pack_h2(eW2l[k0 * 64 + c + 32],   eW2l[(k0 + 1) * 64 + c + 32]));
            q.w = __uint_as_float(pack_h2(eW2l[(k0 + 8) * 64 + c + 32], eW2l[(k0 + 9) * 64 + c + 32]));
            *(float4*)(w2h + kp * W2HW + c * 4) = q;
        }
        for (int idx = t; idx < 48 * 128; idx += 256) {
            int d = idx >> 7, c = idx & 127;
            float v = 0.f;
            if (d < DD) v = (c < 64) ? eW1l[d * 64 + c] : eW1l[(DD + d) * 64 + c - 64];
            ew1T[d * E1W + c] = __uint_as_float(tf32_rna(v));
        }
        for (int idx = t; idx < 32 * 48; idx += 256) {
            int i = idx / 48, k = idx - i * 48;
            float v = (i < NN && k < DD) ? zsh[i * ZROW + k] : 0.f;
            zt[i * ZTW + k] = __uint_as_float(tf32_rna(v));
        }
        for (int idx = t; idx < 64 * NW2W; idx += 256) {
            int k = idx / NW2W, d = idx - k * NW2W;
            nw2s[idx] = (d < DD) ? __uint_as_float(tf32_rna(nW2l[k * DD + d])) : 0.f;
        }
        __syncthreads();

        // ======== projections via MMA: [32x48] @ [48x128] -> piR|pjR ========
        {
            float pacc[2][2][4];
            #pragma unroll
            for (int mf = 0; mf < 2; ++mf)
                #pragma unroll
                for (int nfi = 0; nfi < 2; ++nfi)
                    #pragma unroll
                    for (int e = 0; e < 4; ++e) pacc[mf][nfi][e] = 0.f;

            #pragma unroll
            for (int kk = 0; kk < 6; ++kk) {
                const int k0 = kk * 8 + cq, k1 = k0 + 4;
                uint32_t a00 = __float_as_uint(zt[lq * ZTW + k0]);
                uint32_t a01 = __float_as_uint(zt[(lq + 8) * ZTW + k0]);
                uint32_t a02 = __float_as_uint(zt[lq * ZTW + k1]);
                uint32_t a03 = __float_as_uint(zt[(lq + 8) * ZTW + k1]);
                uint32_t a10 = __float_as_uint(zt[(lq + 16) * ZTW + k0]);
                uint32_t a11 = __float_as_uint(zt[(lq + 24) * ZTW + k0]);
                uint32_t a12 = __float_as_uint(zt[(lq + 16) * ZTW + k1]);
                uint32_t a13 = __float_as_uint(zt[(lq + 24) * ZTW + k1]);
                #pragma unroll
                for (int nfi = 0; nfi < 2; ++nfi) {
                    const int col = w * 16 + nfi * 8 + lq;
                    uint32_t b0 = __float_as_uint(ew1T[k0 * E1W + col]);
                    uint32_t b1 = __float_as_uint(ew1T[k1 * E1W + col]);
                    mma_tf32(pacc[0][nfi], a00, a01, a02, a03, b0, b1);
                    mma_tf32(pacc[1][nfi], a10, a11, a12, a13, b0, b1);
                }
            }
            float* dst = (w < 4) ? piR : pjR;
            const int cb = (w < 4) ? w * 16 : w * 16 - 64;
            #pragma unroll
            for (int nfi = 0; nfi < 2; ++nfi) {
                float ex = 0.f, ey = 0.f;
                if (w < 4) {
                    float2 e2 = *(const float2*)(eb1l + w * 16 + nfi * 8 + 2 * cq);
                    ex = e2.x; ey = e2.y;
                }
                const int col = cb + nfi * 8 + 2 * cq;
                #pragma unroll
                for (int mf = 0; mf < 2; ++mf) {
                    int r = mf * 16 + lq;
                    *(float2*)(dst + r * PROW + col) =
                        make_float2(pacc[mf][nfi][0] + ex, pacc[mf][nfi][1] + ey);
                    *(float2*)(dst + (r + 8) * PROW + col) =
                        make_float2(pacc[mf][nfi][2] + ex, pacc[mf][nfi][3] + ey);
                }
            }
        }
        // ---- layernorm (independent of piR/pjR) ----
        if (t < NN) {
            float mu = 0.f, sq = 0.f;
            #pragma unroll
            for (int d = 0; d < DD; ++d) {
                float v = zsh[t * ZROW + d];
                mu += v; sq += v * v;
            }
            mu *= (1.0f / DD);
            float var = sq * (1.0f / DD) - mu * mu;
            float rs = rsqrtf(var + 1e-5f);
            #pragma unroll
            for (int d = 0; d < DD; ++d)
                znsh[t * ZROW + d] = (zsh[t * ZROW + d] - mu) * rs * lngl[d] + lnbl[d];
        }
        __syncthreads();

        // per-thread epilogue constants
        float eb2v[16], gwv[16];
        #pragma unroll
        for (int nf = 0; nf < 8; ++nf) {
            int c = nf * 8 + cq * 2;
            float2 e2 = *(const float2*)(eb2l + c);
            float2 g2 = *(const float2*)(gWl + c);
            eb2v[nf * 2] = e2.x; eb2v[nf * 2 + 1] = e2.y;
            gwv[nf * 2]  = g2.x; gwv[nf * 2 + 1]  = g2.y;
        }

        const float* pj0b = pjR + r0 * PROW;
        const float* pj1b = pjR + r1 * PROW;

        // ======== 8 edge tiles (fp16 MMA), zero intra-tile syncs ========
        for (int ig = 0; ig < 8; ++ig) {
            const int node = ig * 4 + i_sel;
            const float* pib = piR + node * PROW;

            float acc[8][4];
            #pragma unroll
            for (int nf = 0; nf < 8; ++nf)
                #pragma unroll
                for (int e = 0; e < 4; ++e) acc[nf][e] = 0.f;

            #pragma unroll
            for (int kk = 0; kk < 4; ++kk) {
                const int ka = kk * 16 + 2 * cq;
                float2 pi0  = *(const float2*)(pib + ka);
                float2 pi1  = *(const float2*)(pib + ka + 8);
                float2 pj00 = *(const float2*)(pj0b + ka);
                float2 pj01 = *(const float2*)(pj0b + ka + 8);
                float2 pj10 = *(const float2*)(pj1b + ka);
                float2 pj11 = *(const float2*)(pj1b + ka + 8);
                uint32_t a0 = pack_h2(silu_t(pi0.x + pj00.x), silu_t(pi0.y + pj00.y));
                uint32_t a1 = pack_h2(silu_t(pi0.x + pj10.x), silu_t(pi0.y + pj10.y));
                uint32_t a2 = pack_h2(silu_t(pi1.x + pj01.x), silu_t(pi1.y + pj01.y));
                uint32_t a3 = pack_h2(silu_t(pi1.x + pj11.x), silu_t(pi1.y + pj11.y));
                const float* wb = w2h + (kk * 4 + cq) * W2HW + lq * 4;
                #pragma unroll
                for (int nf = 0; nf < 4; ++nf) {
                    float4 q = *(const float4*)(wb + nf * 32);
                    mma_f16(acc[nf],     a0, a1, a2, a3,
                            __float_as_uint(q.x), __float_as_uint(q.y));
                    mma_f16(acc[nf + 4], a0, a1, a2, a3,
                            __float_as_uint(q.z), __float_as_uint(q.w));
                }
            }

            // epilogue: silu+bias, in-warp gate
            float gp0 = 0.f, gp1 = 0.f;
            #pragma unroll
            for (int nf = 0; nf < 8; ++nf) {
                float v0 = silu_t(acc[nf][0] + eb2v[nf * 2]);
                float v1 = silu_t(acc[nf][1] + eb2v[nf * 2 + 1]);
                float v2 = silu_t(acc[nf][2] + eb2v[nf * 2]);
                float v3 = silu_t(acc[nf][3] + eb2v[nf * 2 + 1]);
                acc[nf][0] = v0; acc[nf][1] = v1; acc[nf][2] = v2; acc[nf][3] = v3;
                gp0 = fmaf(v0, gwv[nf * 2], fmaf(v1, gwv[nf * 2 + 1], gp0));
                gp1 = fmaf(v2, gwv[nf * 2], fmaf(v3, gwv[nf * 2 + 1], gp1));
            }
            gp0 += __shfl_xor_sync(0xffffffffu, gp0, 1);
            gp0 += __shfl_xor_sync(0xffffffffu, gp0, 2);
            gp1 += __shfl_xor_sync(0xffffffffu, gp1, 1);
            gp1 += __shfl_xor_sync(0xffffffffu, gp1, 2);
            float g0 = sigm_t(gp0 + gbl);
            float g1 = (r1 < NN) ? sigm_t(gp1 + gbl) : 0.f;

            float s16[16];
            #pragma unroll
            for (int nf = 0; nf < 8; ++nf) {
                s16[nf * 2]     = fmaf(acc[nf][0], g0, acc[nf][2] * g1);
                s16[nf * 2 + 1] = fmaf(acc[nf][1], g0, acc[nf][3] * g1);
            }
            const int bb0 = lq & 1, bb1 = (lq >> 1) & 1, bb2 = (lq >> 2) & 1;
            float v8[8];
            #pragma unroll
            for (int j = 0; j < 8; ++j) {
                float keep = bb0 ? s16[8 + j] : s16[j];
                float send = bb0 ? s16[j]     : s16[8 + j];
                v8[j] = keep + __shfl_xor_sync(0xffffffffu, send, 4);
            }
            float v4a[4];
            #pragma unroll
            for (int j = 0; j < 4; ++j) {
                float keep = bb1 ? v8[4 + j] : v8[j];
                float send = bb1 ? v8[j]     : v8[4 + j];
                v4a[j] = keep + __shfl_xor_sync(0xffffffffu, send, 8);
            }
            float v2a[2];
            #pragma unroll
            for (int j = 0; j < 2; ++j) {
                float keep = bb2 ? v4a[2 + j] : v4a[j];
                float send = bb2 ? v4a[j]     : v4a[2 + j];
                v2a[j] = keep + __shfl_xor_sync(0xffffffffu, send, 16);
            }
            const int nfv = bb0 * 4 + bb1 * 2 + bb2;
            *(float2*)(magg + jh * 2048 + node * HDIM + nfv * 8 + 2 * cq) =
                make_float2(v2a[0], v2a[1]);
        }
        __syncthreads();

        // ======== concat buffer: [zn | m_i | 0-pad] ========
        for (int idx = t; idx < 32 * HDIM; idx += 256) {
            int i = idx >> 6, c = idx & 63;
            float v = (i < NN) ? magg[idx] + magg[2048 + idx] : 0.f;
            catsh[i * CATW + DD + c] = v;
        }
        for (int idx = t; idx < 32 * DD; idx += 256) {
            int i = idx / DD, d = idx - i * DD;
            catsh[i * CATW + d] = (i < NN) ? znsh[i * ZROW + d] : 0.f;
        }
        if (t < 64) catsh[(t >> 1) * CATW + 86 + (t & 1)] = 0.f;
        __syncthreads();

        // ======== node MLP layer 1 via MMA: [32x88] @ [86x64] ========
        {
            const int mh  = w & 1;
            const int nh4 = w >> 1;
            const int row0 = mh * 16 + lq, row1 = row0 + 8;
            float c2[2][4];
            #pragma unroll
            for (int nfi = 0; nfi < 2; ++nfi)
                #pragma unroll
                for (int e = 0; e < 4; ++e) c2[nfi][e] = 0.f;

            #pragma unroll
            for (int kk = 0; kk < 11; ++kk) {
                const int k0 = kk * 8 + cq, k1 = k0 + 4;
                uint32_t a0 = tf32_rna(catsh[row0 * CATW + k0]);
                uint32_t a1 = tf32_rna(catsh[row1 * CATW + k0]);
                uint32_t a2 = tf32_rna(catsh[row0 * CATW + k1]);
                uint32_t a3 = tf32_rna(catsh[row1 * CATW + k1]);
                #pragma unroll
                for (int nfi = 0; nfi < 2; ++nfi) {
                    const int col = (nh4 * 2 + nfi) * 8 + lq;
                    uint32_t b0 = tf32_rna(nW1l[k0 * HDIM + col]);
                    uint32_t b1 = (k1 < DD + HDIM)
                                ? tf32_rna(nW1l[k1 * HDIM + col]) : 0u;
                    mma_tf32(c2[nfi], a0, a1, a2, a3, b0, b1);
                }
            }
            #pragma unroll
            for (int nfi = 0; nfi < 2; ++nfi) {
                const int colb = (nh4 * 2 + nfi) * 8 + 2 * cq;
                float2 nb = *(const float2*)(nb1l + colb);
                *(float2*)(hbuf + row0 * HROW + colb) = make_float2(
                    __uint_as_float(tf32_rna(silu_t(c2[nfi][0] + nb.x))),
                    __uint_as_float(tf32_rna(silu_t(c2[nfi][1] + nb.y))));
                *(float2*)(hbuf + row1 * HROW + colb) = make_float2(
                    __uint_as_float(tf32_rna(silu_t(c2[nfi][2] + nb.x))),
                    __uint_as_float(tf32_rna(silu_t(c2[nfi][3] + nb.y))));
            }
        }
        __syncthreads();

        // ======== node MLP layer 2 via MMA: [32x64] @ [64x24] + residual ========
        if (w < 6) {
            const int mf = w & 1;
            const int nf = w >> 1;          // 0..2
            float c4[4] = {0.f, 0.f, 0.f, 0.f};
            #pragma unroll
            for (int kk = 0; kk < 8; ++kk) {
                const int k0 = kk * 8 + cq, k1 = k0 + 4;
                uint32_t a0 = __float_as_uint(hbuf[(mf * 16 + lq) * HROW + k0]);
                uint32_t a1 = __float_as_uint(hbuf[(mf * 16 + lq + 8) * HROW + k0]);
                uint32_t a2 = __float_as_uint(hbuf[(mf * 16 + lq) * HROW + k1]);
                uint32_t a3 = __float_as_uint(hbuf[(mf * 16 + lq + 8) * HROW + k1]);
                uint32_t b0 = __float_as_uint(nw2s[k0 * NW2W + nf * 8 + lq]);
                uint32_t b1 = __float_as_uint(nw2s[k1 * NW2W + nf * 8 + lq]);
                mma_tf32(c4, a0, a1, a2, a3, b0, b1);
            }
            const int col = nf * 8 + 2 * cq;
            const int rr0 = mf * 16 + lq, rr1 = rr0 + 8;
            if (col < DD) {
                float nb = nb2l[col];
                if (rr0 < NN) zsh[rr0 * ZROW + col] += c4[0] + nb;
                if (rr1 < NN) zsh[rr1 * ZROW + col] += c4[2] + nb;
            }
            if (col + 1 < DD) {
                float nb = nb2l[col + 1];
                if (rr0 < NN) zsh[rr0 * ZROW + col + 1] += c4[1] + nb;
                if (rr1 < NN) zsh[rr1 * ZROW + col + 1] += c4[3] + nb;
            }
        }
        __syncthreads();
    }

    // ---- mean pool ----
    if (t < DD) {
        float s = 0.f;
        #pragma unroll
        for (int i = 0; i < NN; ++i) s += zsh[i * ZROW + t];
        znsh[t] = s * (1.0f / NN);
    }
    __syncthreads();

    // ---- head MLP ----
    if (t < HDIM) {
        float a = hb1[t];
        #pragma unroll
        for (int d = 0; d < DD; ++d) a += znsh[d] * hW1[d * HDIM + t];
        hbuf[t] = fmaxf(a, 0.f);
    }
    __syncthreads();

    float* ob = out + (size_t)b * (NN * OUTROW);
    for (int idx = t; idx < NN * OUTROW; idx += 256) {
        float v = 0.f;
        if (idx < NOUT) {
            v = hb2[idx];
            #pragma unroll
            for (int m2 = 0; m2 < HDIM; ++m2)
                v += hbuf[m2] * hW2[m2 * NOUT + idx];
        }
        ob[idx] = v;
    }
}

extern "C" void kernel_launch(void* const* d_in, const int* in_sizes, int n_in,
                              void* d_out, int out_size) {
    (void)in_sizes; (void)n_in; (void)out_size;
    const float* x    = (const float*)d_in[0];
    const float* ctx  = (const float*)d_in[1];
    const float* eW1  = (const float*)d_in[2];
    const float* eb1  = (const float*)d_in[3];
    const float* eW2  = (const float*)d_in[4];
    const float* eb2  = (const float*)d_in[5];
    const float* gW   = (const float*)d_in[6];
    const float* gb   = (const float*)d_in[7];
    const float* lng  = (const float*)d_in[8];
    const float* lnb  = (const float*)d_in[9];
    const float* nW1  = (const float*)d_in[10];
    const float* nb1  = (const float*)d_in[11];
    const float* nW2  = (const float*)d_in[12];
    const float* nb2  = (const float*)d_in[13];
    const float* hW1  = (const float*)d_in[14];
    const float* hb1  = (const float*)d_in[15];
    const float* hW2  = (const float*)d_in[16];
    const float* hb2  = (const float*)d_in[17];
    float* out = (float*)d_out;

    cudaFuncSetAttribute(gnn_kernel, cudaFuncAttributeMaxDynamicSharedMemorySize,
                         SMEM_FLOATS * sizeof(float));
    gnn_kernel<<<NB, 256, SMEM_FLOATS * sizeof(float)>>>(
        x, ctx, eW1, eb1, eW2, eb2, gW, gb, lng, lnb,
        nW1, nb1, nW2, nb2, hW1, hb1, hW2, hb2, out);
}

// round 8
// speedup vs baseline: 2.0596x; 1.3150x over previous
#include <cuda_runtime.h>
#include <cuda_fp16.h>
#include <cstdint>
#include <cstddef>

// Problem constants
#define NB   4096
#define NN   29
#define NC   6
#define CDIM 16
#define DD   22
#define HDIM 64
#define NL   2
#define NOUT 24
#define OUTROW 12
#define ZROW 25
#define PROW 72     // pi/pj row stride
#define CATW 100
#define W2HW 136    // fp16 W2 row stride (floats)
#define ZTW  28     // zt row stride: lq*28+cq mod 32 all-distinct -> conflict-free
#define HROW 68     // hbuf row stride

// Shared memory layout (float offsets)
#define OFF_Z    0        // 800
#define OFF_ZN   800      // 800
#define OFF_PI   1600     // 32*72 = 2304
#define OFF_PJ   3904     // 2304
#define OFF_W2H  6208     // 32*136 = 4352
#define OFF_ZT   10560    // 32*28 = 896
#define OFF_MAGG 11456    // 2*32*64 = 4096
#define OFF_H    15552    // 32*68 = 2176
#define OFF_EBG  17728    // 128 (eb2 | gW)
#define SMEM_FLOATS 17856 // 71424 bytes -> 3 CTAs/SM (214272 <= 228KB)
// catsh [32][100]=3200 aliases OFF_PI..OFF_PI+4608 (piR+pjR dead after tile loop)

__device__ __forceinline__ float tanhfast(float x) {
    float y;
    asm("tanh.approx.f32 %0, %1;" : "=f"(y) : "f"(x));
    return y;
}
__device__ __forceinline__ float silu_t(float v) {
    float h = 0.5f * v;
    return fmaf(h, tanhfast(h), h);
}
__device__ __forceinline__ float sigm_t(float v) {
    return fmaf(0.5f, tanhfast(0.5f * v), 0.5f);
}
__device__ __forceinline__ uint32_t tf32_rna(float x) {
    uint32_t u;
    asm("cvt.rna.tf32.f32 %0, %1;" : "=r"(u) : "f"(x));
    return u;
}
__device__ __forceinline__ uint32_t pack_h2(float lo, float hi) {
    __half2 h = __floats2half2_rn(lo, hi);
    return *(uint32_t*)&h;
}
__device__ __forceinline__ void mma_f16(float c[4], uint32_t a0, uint32_t a1,
                                        uint32_t a2, uint32_t a3,
                                        uint32_t b0, uint32_t b1) {
    asm volatile(
        "mma.sync.aligned.m16n8k16.row.col.f32.f16.f16.f32 "
        "{%0,%1,%2,%3}, {%4,%5,%6,%7}, {%8,%9}, {%0,%1,%2,%3};\n"
        : "+f"(c[0]), "+f"(c[1]), "+f"(c[2]), "+f"(c[3])
        : "r"(a0), "r"(a1), "r"(a2), "r"(a3), "r"(b0), "r"(b1));
}
__device__ __forceinline__ void mma_tf32(float c[4], uint32_t a0, uint32_t a1,
                                         uint32_t a2, uint32_t a3,
                                         uint32_t b0, uint32_t b1) {
    asm volatile(
        "mma.sync.aligned.m16n8k8.row.col.f32.tf32.tf32.f32 "
        "{%0,%1,%2,%3}, {%4,%5,%6,%7}, {%8,%9}, {%0,%1,%2,%3};\n"
        : "+f"(c[0]), "+f"(c[1]), "+f"(c[2]), "+f"(c[3])
        : "r"(a0), "r"(a1), "r"(a2), "r"(a3), "r"(b0), "r"(b1));
}

extern "C" __global__ void __launch_bounds__(256, 3)
gnn_kernel(const float* __restrict__ x,   const float* __restrict__ ctx,
           const float* __restrict__ eW1, const float* __restrict__ eb1,
           const float* __restrict__ eW2, const float* __restrict__ eb2,
           const float* __restrict__ gW,  const float* __restrict__ gb,
           const float* __restrict__ lng, const float* __restrict__ lnb,
           const float* __restrict__ nW1, const float* __restrict__ nb1,
           const float* __restrict__ nW2, const float* __restrict__ nb2,
           const float* __restrict__ hW1, const float* __restrict__ hb1,
           const float* __restrict__ hW2, const float* __restrict__ hb2,
           float* __restrict__ out)
{
    extern __shared__ float sh[];
    float* zsh   = sh + OFF_Z;
    float* znsh  = sh + OFF_ZN;
    float* piR   = sh + OFF_PI;    // [32][72]
    float* pjR   = sh + OFF_PJ;    // [32][72]
    float* w2h   = sh + OFF_W2H;   // [32][136] half2-packed fp16 W2
    float* zt    = sh + OFF_ZT;    // [32][28] tf32 z, zero-padded to 24 cols
    float* magg  = sh + OFF_MAGG;  // [2][32][64]
    float* hbuf  = sh + OFF_H;     // [32][68] tf32
    float* ebg   = sh + OFF_EBG;   // [eb2(64) | gW(64)]
    float* catsh = sh + OFF_PI;    // [32][100] aliases piR/pjR

    const int b = blockIdx.x;
    const int t = threadIdx.x;
    const int w = t >> 5;
    const int lane = t & 31;
    const int lq = lane >> 2;
    const int cq = lane & 3;
    const int i_sel = w >> 1;      // node within i-group
    const int jh = w & 1;          // jj half
    const int r0 = jh * 16 + lq;
    const int r1 = r0 + 8;

    // ---- load z = concat(x, context) ----
    for (int idx = t; idx < NN * DD; idx += 256) {
        int i = idx / DD, d = idx - i * DD;
        float v = (d < NC) ? x[(b * NN + i) * NC + d]
                           : ctx[(b * NN + i) * CDIM + (d - NC)];
        zsh[i * ZROW + d] = v;
    }
    __syncthreads();

    for (int l = 0; l < NL; ++l) {
        const float* eW1l = eW1 + l * 2 * DD * HDIM;
        const float* eb1l = eb1 + l * HDIM;
        const float* eW2l = eW2 + l * HDIM * HDIM;
        const float* eb2l = eb2 + l * HDIM;
        const float* gWl  = gW  + l * HDIM;
        const float  gbl  = gb[l];
        const float* lngl = lng + l * DD;
        const float* lnbl = lnb + l * DD;
        const float* nW1l = nW1 + l * (DD + HDIM) * HDIM;
        const float* nb1l = nb1 + l * HDIM;
        const float* nW2l = nW2 + l * HDIM * DD;
        const float* nb2l = nb2 + l * DD;

        // ======== staging: w2h, zt, ebg ========
        for (int e = t; e < 1024; e += 256) {
            int kp = e >> 5, c = e & 31;
            int kk = kp >> 2, cqv = kp & 3;
            int k0 = kk * 16 + 2 * cqv;
            float4 q;
            q.x = __uint_as_float(pack_h2(eW2l[k0 * 64 + c],        eW2l[(k0 + 1) * 64 + c]));
            q.y = __uint_as_float(pack_h2(eW2l[(k0 + 8) * 64 + c],  eW2l[(k0 + 9) * 64 + c]));
            q.z = __uint_as_float(pack_h2(eW2l[k0 * 64 + c + 32],   eW2l[(k0 + 1) * 64 + c + 32]));
            q.w = __uint_as_float(pack_h2(eW2l[(k0 + 8) * 64 + c + 32], eW2l[(k0 + 9) * 64 + c + 32]));
            *(float4*)(w2h + kp * W2HW + c * 4) = q;
        }
        for (int idx = t; idx < 32 * 24; idx += 256) {
            int i = idx / 24, k = idx - i * 24;
            float v = (i < NN && k < DD) ? zsh[i * ZROW + k] : 0.f;
            zt[i * ZTW + k] = __uint_as_float(tf32_rna(v));
        }
        if (t < 64) { ebg[t] = eb2l[t]; ebg[64 + t] = gWl[t]; }
        __syncthreads();

        // ======== projections via MMA: [32x24] @ [22x128] -> piR|pjR ========
        // B fragments direct from global (L2-hot), rows >= DD zero.
        {
            float pacc[2][2][4];
            #pragma unroll
            for (int mf = 0; mf < 2; ++mf)
                #pragma unroll
                for (int nfi = 0; nfi < 2; ++nfi)
                    #pragma unroll
                    for (int e = 0; e < 4; ++e) pacc[mf][nfi][e] = 0.f;

            const int halfoff = (w < 4) ? 0 : DD;   // pi rows vs pj rows of eW1
            #pragma unroll
            for (int kk = 0; kk < 3; ++kk) {
                const int k0 = kk * 8 + cq, k1 = k0 + 4;   // k0 <= 19 < DD; k1 may exceed
                uint32_t a00 = __float_as_uint(zt[lq * ZTW + k0]);
                uint32_t a01 = __float_as_uint(zt[(lq + 8) * ZTW + k0]);
                uint32_t a02 = __float_as_uint(zt[lq * ZTW + k1]);
                uint32_t a03 = __float_as_uint(zt[(lq + 8) * ZTW + k1]);
                uint32_t a10 = __float_as_uint(zt[(lq + 16) * ZTW + k0]);
                uint32_t a11 = __float_as_uint(zt[(lq + 24) * ZTW + k0]);
                uint32_t a12 = __float_as_uint(zt[(lq + 16) * ZTW + k1]);
                uint32_t a13 = __float_as_uint(zt[(lq + 24) * ZTW + k1]);
                #pragma unroll
                for (int nfi = 0; nfi < 2; ++nfi) {
                    const int col = (w & 3) * 16 + nfi * 8 + lq;
                    uint32_t b0 = tf32_rna(__ldg(eW1l + (halfoff + k0) * HDIM + col));
                    uint32_t b1 = (k1 < DD)
                                ? tf32_rna(__ldg(eW1l + (halfoff + k1) * HDIM + col)) : 0u;
                    mma_tf32(pacc[0][nfi], a00, a01, a02, a03, b0, b1);
                    mma_tf32(pacc[1][nfi], a10, a11, a12, a13, b0, b1);
                }
            }
            float* dst = (w < 4) ? piR : pjR;
            const int cb = (w & 3) * 16;
            #pragma unroll
            for (int nfi = 0; nfi < 2; ++nfi) {
                float ex = 0.f, ey = 0.f;
                if (w < 4) {
                    float2 e2 = *(const float2*)(eb1l + cb + nfi * 8 + 2 * cq);
                    ex = e2.x; ey = e2.y;
                }
                const int col = cb + nfi * 8 + 2 * cq;
                #pragma unroll
                for (int mf = 0; mf < 2; ++mf) {
                    int r = mf * 16 + lq;
                    *(float2*)(dst + r * PROW + col) =
                        make_float2(pacc[mf][nfi][0] + ex, pacc[mf][nfi][1] + ey);
                    *(float2*)(dst + (r + 8) * PROW + col) =
                        make_float2(pacc[mf][nfi][2] + ex, pacc[mf][nfi][3] + ey);
                }
            }
        }
        // ---- layernorm ----
        if (t < NN) {
            float mu = 0.f, sq = 0.f;
            #pragma unroll
            for (int d = 0; d < DD; ++d) {
                float v = zsh[t * ZROW + d];
                mu += v; sq += v * v;
            }
            mu *= (1.0f / DD);
            float var = sq * (1.0f / DD) - mu * mu;
            float rs = rsqrtf(var + 1e-5f);
            #pragma unroll
            for (int d = 0; d < DD; ++d)
                znsh[t * ZROW + d] = (zsh[t * ZROW + d] - mu) * rs * lngl[d] + lnbl[d];
        }
        __syncthreads();

        const float* pj0b = pjR + r0 * PROW;
        const float* pj1b = pjR + r1 * PROW;

        // ======== 8 edge tiles (fp16 MMA), zero intra-tile syncs ========
        for (int ig = 0; ig < 8; ++ig) {
            const int node = ig * 4 + i_sel;
            const float* pib = piR + node * PROW;

            float acc[8][4];
            #pragma unroll
            for (int nf = 0; nf < 8; ++nf)
                #pragma unroll
                for (int e = 0; e < 4; ++e) acc[nf][e] = 0.f;

            #pragma unroll
            for (int kk = 0; kk < 4; ++kk) {
                const int ka = kk * 16 + 2 * cq;
                float2 pi0  = *(const float2*)(pib + ka);
                float2 pi1  = *(const float2*)(pib + ka + 8);
                float2 pj00 = *(const float2*)(pj0b + ka);
                float2 pj01 = *(const float2*)(pj0b + ka + 8);
                float2 pj10 = *(const float2*)(pj1b + ka);
                float2 pj11 = *(const float2*)(pj1b + ka + 8);
                uint32_t a0 = pack_h2(silu_t(pi0.x + pj00.x), silu_t(pi0.y + pj00.y));
                uint32_t a1 = pack_h2(silu_t(pi0.x + pj10.x), silu_t(pi0.y + pj10.y));
                uint32_t a2 = pack_h2(silu_t(pi1.x + pj01.x), silu_t(pi1.y + pj01.y));
                uint32_t a3 = pack_h2(silu_t(pi1.x + pj11.x), silu_t(pi1.y + pj11.y));
                const float* wb = w2h + (kk * 4 + cq) * W2HW + lq * 4;
                #pragma unroll
                for (int nf = 0; nf < 4; ++nf) {
                    float4 q = *(const float4*)(wb + nf * 32);
                    mma_f16(acc[nf],     a0, a1, a2, a3,
                            __float_as_uint(q.x), __float_as_uint(q.y));
                    mma_f16(acc[nf + 4], a0, a1, a2, a3,
                            __float_as_uint(q.z), __float_as_uint(q.w));
                }
            }

            // epilogue: silu+bias, in-warp gate (constants from SMEM broadcast)
            float gp0 = 0.f, gp1 = 0.f;
            #pragma unroll
            for (int nf = 0; nf < 8; ++nf) {
                float2 e2 = *(const float2*)(ebg + nf * 8 + 2 * cq);
                float2 g2 = *(const float2*)(ebg + 64 + nf * 8 + 2 * cq);
                float v0 = silu_t(acc[nf][0] + e2.x);
                float v1 = silu_t(acc[nf][1] + e2.y);
                float v2 = silu_t(acc[nf][2] + e2.x);
                float v3 = silu_t(acc[nf][3] + e2.y);
                acc[nf][0] = v0; acc[nf][1] = v1; acc[nf][2] = v2; acc[nf][3] = v3;
                gp0 = fmaf(v0, g2.x, fmaf(v1, g2.y, gp0));
                gp1 = fmaf(v2, g2.x, fmaf(v3, g2.y, gp1));
            }
            gp0 += __shfl_xor_sync(0xffffffffu, gp0, 1);
            gp0 += __shfl_xor_sync(0xffffffffu, gp0, 2);
            gp1 += __shfl_xor_sync(0xffffffffu, gp1, 1);
            gp1 += __shfl_xor_sync(0xffffffffu, gp1, 2);
            float g0 = sigm_t(gp0 + gbl);
            float g1 = (r1 < NN) ? sigm_t(gp1 + gbl) : 0.f;

            float s16[16];
            #pragma unroll
            for (int nf = 0; nf < 8; ++nf) {
                s16[nf * 2]     = fmaf(acc[nf][0], g0, acc[nf][2] * g1);
                s16[nf * 2 + 1] = fmaf(acc[nf][1], g0, acc[nf][3] * g1);
            }
            const int bb0 = lq & 1, bb1 = (lq >> 1) & 1, bb2 = (lq >> 2) & 1;
            float v8[8];
            #pragma unroll
            for (int j = 0; j < 8; ++j) {
                float keep = bb0 ? s16[8 + j] : s16[j];
                float send = bb0 ? s16[j]     : s16[8 + j];
                v8[j] = keep + __shfl_xor_sync(0xffffffffu, send, 4);
            }
            float v4a[4];
            #pragma unroll
            for (int j = 0; j < 4; ++j) {
                float keep = bb1 ? v8[4 + j] : v8[j];
                float send = bb1 ? v8[j]     : v8[4 + j];
                v4a[j] = keep + __shfl_xor_sync(0xffffffffu, send, 8);
            }
            float v2a[2];
            #pragma unroll
            for (int j = 0; j < 2; ++j) {
                float keep = bb2 ? v4a[2 + j] : v4a[j];
                float send = bb2 ? v4a[j]     : v4a[2 + j];
                v2a[j] = keep + __shfl_xor_sync(0xffffffffu, send, 16);
            }
            const int nfv = bb0 * 4 + bb1 * 2 + bb2;
            *(float2*)(magg + jh * 2048 + node * HDIM + nfv * 8 + 2 * cq) =
                make_float2(v2a[0], v2a[1]);
        }
        __syncthreads();

        // ======== concat buffer: [zn | m_i | 0-pad] ========
        for (int idx = t; idx < 32 * HDIM; idx += 256) {
            int i = idx >> 6, c = idx & 63;
            float v = (i < NN) ? magg[idx] + magg[2048 + idx] : 0.f;
            catsh[i * CATW + DD + c] = v;
        }
        for (int idx = t; idx < 32 * DD; idx += 256) {
            int i = idx / DD, d = idx - i * DD;
            catsh[i * CATW + d] = (i < NN) ? znsh[i * ZROW + d] : 0.f;
        }
        if (t < 64) catsh[(t >> 1) * CATW + 86 + (t & 1)] = 0.f;
        __syncthreads();

        // ======== node MLP layer 1 via MMA: [32x88] @ [86x64] ========
        {
            const int mh  = w & 1;
            const int nh4 = w >> 1;
            const int row0 = mh * 16 + lq, row1 = row0 + 8;
            float c2[2][4];
            #pragma unroll
            for (int nfi = 0; nfi < 2; ++nfi)
                #pragma unroll
                for (int e = 0; e < 4; ++e) c2[nfi][e] = 0.f;

            #pragma unroll
            for (int kk = 0; kk < 11; ++kk) {
                const int k0 = kk * 8 + cq, k1 = k0 + 4;
                uint32_t a0 = tf32_rna(catsh[row0 * CATW + k0]);
                uint32_t a1 = tf32_rna(catsh[row1 * CATW + k0]);
                uint32_t a2 = tf32_rna(catsh[row0 * CATW + k1]);
                uint32_t a3 = tf32_rna(catsh[row1 * CATW + k1]);
                #pragma unroll
                for (int nfi = 0; nfi < 2; ++nfi) {
                    const int col = (nh4 * 2 + nfi) * 8 + lq;
                    uint32_t b0 = tf32_rna(__ldg(nW1l + k0 * HDIM + col));
                    uint32_t b1 = (k1 < DD + HDIM)
                                ? tf32_rna(__ldg(nW1l + k1 * HDIM + col)) : 0u;
                    mma_tf32(c2[nfi], a0, a1, a2, a3, b0, b1);
                }
            }
            #pragma unroll
            for (int nfi = 0; nfi < 2; ++nfi) {
                const int colb = (nh4 * 2 + nfi) * 8 + 2 * cq;
                float2 nb = *(const float2*)(nb1l + colb);
                *(float2*)(hbuf + row0 * HROW + colb) = make_float2(
                    __uint_as_float(tf32_rna(silu_t(c2[nfi][0] + nb.x))),
                    __uint_as_float(tf32_rna(silu_t(c2[nfi][1] + nb.y))));
                *(float2*)(hbuf + row1 * HROW + colb) = make_float2(
                    __uint_as_float(tf32_rna(silu_t(c2[nfi][2] + nb.x))),
                    __uint_as_float(tf32_rna(silu_t(c2[nfi][3] + nb.y))));
            }
        }
        __syncthreads();

        // ======== node MLP layer 2 via MMA: [32x64] @ [64x24] + residual ========
        if (w < 6) {
            const int mf = w & 1;
            const int nf = w >> 1;          // 0..2
            const int d0 = nf * 8 + lq;     // B col (0..23)
            float c4[4] = {0.f, 0.f, 0.f, 0.f};
            #pragma unroll
            for (int kk = 0; kk < 8; ++kk) {
                const int k0 = kk * 8 + cq, k1 = k0 + 4;
                uint32_t a0 = __float_as_uint(hbuf[(mf * 16 + lq) * HROW + k0]);
                uint32_t a1 = __float_as_uint(hbuf[(mf * 16 + lq + 8) * HROW + k0]);
                uint32_t a2 = __float_as_uint(hbuf[(mf * 16 + lq) * HROW + k1]);
                uint32_t a3 = __float_as_uint(hbuf[(mf * 16 + lq + 8) * HROW + k1]);
                uint32_t b0 = (d0 < DD) ? tf32_rna(__ldg(nW2l + k0 * DD + d0)) : 0u;
                uint32_t b1 = (d0 < DD) ? tf32_rna(__ldg(nW2l + k1 * DD + d0)) : 0u;
                mma_tf32(c4, a0, a1, a2, a3, b0, b1);
            }
            const int col = nf * 8 + 2 * cq;
            const int rr0 = mf * 16 + lq, rr1 = rr0 + 8;
            if (col < DD) {
                float nb = nb2l[col];
                if (rr0 < NN) zsh[rr0 * ZROW + col] += c4[0] + nb;
                if (rr1 < NN) zsh[rr1 * ZROW + col] += c4[2] + nb;
            }
            if (col + 1 < DD) {
                float nb = nb2l[col + 1];
                if (rr0 < NN) zsh[rr0 * ZROW + col + 1] += c4[1] + nb;
                if (rr1 < NN) zsh[rr1 * ZROW + col + 1] += c4[3] + nb;
            }
        }
        __syncthreads();
    }

    // ---- mean pool ----
    if (t < DD) {
        float s = 0.f;
        #pragma unroll
        for (int i = 0; i < NN; ++i) s += zsh[i * ZROW + t];
        znsh[t] = s * (1.0f / NN);
    }
    __syncthreads();

    // ---- head MLP ----
    if (t < HDIM) {
        float a = hb1[t];
        #pragma unroll
        for (int d = 0; d < DD; ++d) a += znsh[d] * hW1[d * HDIM + t];
        hbuf[t] = fmaxf(a, 0.f);
    }
    __syncthreads();

    float* ob = out + (size_t)b * (NN * OUTROW);
    for (int idx = t; idx < NN * OUTROW; idx += 256) {
        float v = 0.f;
        if (idx < NOUT) {
            v = hb2[idx];
            #pragma unroll
            for (int m2 = 0; m2 < HDIM; ++m2)
                v += hbuf[m2] * hW2[m2 * NOUT + idx];
        }
        ob[idx] = v;
    }
}

extern "C" void kernel_launch(void* const* d_in, const int* in_sizes, int n_in,
                              void* d_out, int out_size) {
    (void)in_sizes; (void)n_in; (void)out_size;
    const float* x    = (const float*)d_in[0];
    const float* ctx  = (const float*)d_in[1];
    const float* eW1  = (const float*)d_in[2];
    const float* eb1  = (const float*)d_in[3];
    const float* eW2  = (const float*)d_in[4];
    const float* eb2  = (const float*)d_in[5];
    const float* gW   = (const float*)d_in[6];
    const float* gb   = (const float*)d_in[7];
    const float* lng  = (const float*)d_in[8];
    const float* lnb  = (const float*)d_in[9];
    const float* nW1  = (const float*)d_in[10];
    const float* nb1  = (const float*)d_in[11];
    const float* nW2  = (const float*)d_in[12];
    const float* nb2  = (const float*)d_in[13];
    const float* hW1  = (const float*)d_in[14];
    const float* hb1  = (const float*)d_in[15];
    const float* hW2  = (const float*)d_in[16];
    const float* hb2  = (const float*)d_in[17];
    float* out = (float*)d_out;

    cudaFuncSetAttribute(gnn_kernel, cudaFuncAttributeMaxDynamicSharedMemorySize,
                         SMEM_FLOATS * sizeof(float));
    gnn_kernel<<<NB, 256, SMEM_FLOATS * sizeof(float)>>>(
        x, ctx, eW1, eb1, eW2, eb2, gW, gb, lng, lnb,
        nW1, nb1, nW2, nb2, hW1, hb1, hW2, hb2, out);
}

// round 9
// speedup vs baseline: 2.2503x; 1.0926x over previous
#include <cuda_runtime.h>
#include <cuda_fp16.h>
#include <cstdint>
#include <cstddef>

// Problem constants
#define NB   4096
#define NN   29
#define NC   6
#define CDIM 16
#define DD   22
#define HDIM 64
#define NL   2
#define NOUT 24
#define OUTROW 12
#define ZROW 25
#define PRU  36     // pi/pj row stride in uint32 (half2 pairs): (4lq+cq)%32 distinct
#define CATW 100
#define W2HW 136    // fp16 W2 row stride (floats)
#define ZTW  28     // zt row stride
#define HROW 68     // hbuf row stride

// Shared memory layout (float offsets)
#define OFF_Z    0        // 800
#define OFF_ZN   800      // 800
#define OFF_PI   1600     // 32*36 = 1152 (uint32 half2)
#define OFF_PJ   2752     // 1152
#define OFF_W2H  3904     // 32*136 = 4352
#define OFF_ZT   8256     // 32*28 = 896
#define OFF_MAGG 9152     // 2*32*64 = 4096
#define OFF_H    13248    // 32*68 = 2176
#define OFF_EBG  15424    // 128 (eb2 | gW)
#define SMEM_FLOATS 15552 // 62208 bytes -> 3 CTAs/SM (186624 <= 228KB)
// catsh [32][100]=3200 aliases OFF_PI..4800 (piR/pjR/w2h-head dead there)

__device__ __forceinline__ float tanhfast(float x) {
    float y;
    asm("tanh.approx.f32 %0, %1;" : "=f"(y) : "f"(x));
    return y;
}
__device__ __forceinline__ float silu_t(float v) {
    float h = 0.5f * v;
    return fmaf(h, tanhfast(h), h);
}
__device__ __forceinline__ float sigm_t(float v) {
    return fmaf(0.5f, tanhfast(0.5f * v), 0.5f);
}
__device__ __forceinline__ uint32_t tf32_rna(float x) {
    uint32_t u;
    asm("cvt.rna.tf32.f32 %0, %1;" : "=r"(u) : "f"(x));
    return u;
}
__device__ __forceinline__ uint32_t pack_h2(float lo, float hi) {
    __half2 h = __floats2half2_rn(lo, hi);
    return *(uint32_t*)&h;
}
__device__ __forceinline__ uint32_t hadd2u(uint32_t a, uint32_t b) {
    __half2 r = __hadd2(*(__half2*)&a, *(__half2*)&b);
    return *(uint32_t*)&r;
}
// silu(v) = h + h*tanh(h), h = v/2, all in f16x2 (one MUFU for two lanes)
__device__ __forceinline__ uint32_t silu_h2(uint32_t v) {
    __half2 h = __hmul2(*(__half2*)&v, __float2half2_rn(0.5f));
    uint32_t hu = *(uint32_t*)&h, tu;
    asm("tanh.approx.f16x2 %0, %1;" : "=r"(tu) : "r"(hu));
    __half2 r = __hfma2(h, *(__half2*)&tu, h);
    return *(uint32_t*)&r;
}
__device__ __forceinline__ float2 h22f2(uint32_t u) {
    return __half22float2(*(__half2*)&u);
}
__device__ __forceinline__ void mma_f16(float c[4], uint32_t a0, uint32_t a1,
                                        uint32_t a2, uint32_t a3,
                                        uint32_t b0, uint32_t b1) {
    asm volatile(
        "mma.sync.aligned.m16n8k16.row.col.f32.f16.f16.f32 "
        "{%0,%1,%2,%3}, {%4,%5,%6,%7}, {%8,%9}, {%0,%1,%2,%3};\n"
        : "+f"(c[0]), "+f"(c[1]), "+f"(c[2]), "+f"(c[3])
        : "r"(a0), "r"(a1), "r"(a2), "r"(a3), "r"(b0), "r"(b1));
}
__device__ __forceinline__ void mma_tf32(float c[4], uint32_t a0, uint32_t a1,
                                         uint32_t a2, uint32_t a3,
                                         uint32_t b0, uint32_t b1) {
    asm volatile(
        "mma.sync.aligned.m16n8k8.row.col.f32.tf32.tf32.f32 "
        "{%0,%1,%2,%3}, {%4,%5,%6,%7}, {%8,%9}, {%0,%1,%2,%3};\n"
        : "+f"(c[0]), "+f"(c[1]), "+f"(c[2]), "+f"(c[3])
        : "r"(a0), "r"(a1), "r"(a2), "r"(a3), "r"(b0), "r"(b1));
}

extern "C" __global__ void __launch_bounds__(256, 3)
gnn_kernel(const float* __restrict__ x,   const float* __restrict__ ctx,
           const float* __restrict__ eW1, const float* __restrict__ eb1,
           const float* __restrict__ eW2, const float* __restrict__ eb2,
           const float* __restrict__ gW,  const float* __restrict__ gb,
           const float* __restrict__ lng, const float* __restrict__ lnb,
           const float* __restrict__ nW1, const float* __restrict__ nb1,
           const float* __restrict__ nW2, const float* __restrict__ nb2,
           const float* __restrict__ hW1, const float* __restrict__ hb1,
           const float* __restrict__ hW2, const float* __restrict__ hb2,
           float* __restrict__ out)
{
    extern __shared__ float sh[];
    float*    zsh  = sh + OFF_Z;
    float*    znsh = sh + OFF_ZN;
    uint32_t* piU  = (uint32_t*)(sh + OFF_PI);  // [32][36] half2
    uint32_t* pjU  = (uint32_t*)(sh + OFF_PJ);  // [32][36] half2
    float*    w2h  = sh + OFF_W2H;              // [32][136] half2-packed fp16 W2
    float*    zt   = sh + OFF_ZT;               // [32][28] tf32
    float*    magg = sh + OFF_MAGG;             // [2][32][64]
    float*    hbuf = sh + OFF_H;                // [32][68] tf32
    float*    ebg  = sh + OFF_EBG;              // [eb2(64) | gW(64)]
    float*    catsh = sh + OFF_PI;              // [32][100] aliases pi/pj/w2h-head

    const int b = blockIdx.x;
    const int t = threadIdx.x;
    const int w = t >> 5;
    const int lane = t & 31;
    const int lq = lane >> 2;
    const int cq = lane & 3;
    const int i_sel = w >> 1;
    const int jh = w & 1;
    const int r0 = jh * 16 + lq;
    const int r1 = r0 + 8;

    // ---- load z = concat(x, context) ----
    for (int idx = t; idx < NN * DD; idx += 256) {
        int i = idx / DD, d = idx - i * DD;
        float v = (d < NC) ? x[(b * NN + i) * NC + d]
                           : ctx[(b * NN + i) * CDIM + (d - NC)];
        zsh[i * ZROW + d] = v;
    }
    __syncthreads();

    for (int l = 0; l < NL; ++l) {
        const float* eW1l = eW1 + l * 2 * DD * HDIM;
        const float* eb1l = eb1 + l * HDIM;
        const float* eW2l = eW2 + l * HDIM * HDIM;
        const float* eb2l = eb2 + l * HDIM;
        const float* gWl  = gW  + l * HDIM;
        const float  gbl  = gb[l];
        const float* lngl = lng + l * DD;
        const float* lnbl = lnb + l * DD;
        const float* nW1l = nW1 + l * (DD + HDIM) * HDIM;
        const float* nb1l = nb1 + l * HDIM;
        const float* nW2l = nW2 + l * HDIM * DD;
        const float* nb2l = nb2 + l * DD;

        // ======== staging: w2h, zt, ebg ========
        for (int e = t; e < 1024; e += 256) {
            int kp = e >> 5, c = e & 31;
            int kk = kp >> 2, cqv = kp & 3;
            int k0 = kk * 16 + 2 * cqv;
            float4 q;
            q.x = __uint_as_float(pack_h2(eW2l[k0 * 64 + c],        eW2l[(k0 + 1) * 64 + c]));
            q.y = __uint_as_float(pack_h2(eW2l[(k0 + 8) * 64 + c],  eW2l[(k0 + 9) * 64 + c]));
            q.z = __uint_as_float(pack_h2(eW2l[k0 * 64 + c + 32],   eW2l[(k0 + 1) * 64 + c + 32]));
            q.w = __uint_as_float(pack_h2(eW2l[(k0 + 8) * 64 + c + 32], eW2l[(k0 + 9) * 64 + c + 32]));
            *(float4*)(w2h + kp * W2HW + c * 4) = q;
        }
        for (int idx = t; idx < 32 * 24; idx += 256) {
            int i = idx / 24, k = idx - i * 24;
            float v = (i < NN && k < DD) ? zsh[i * ZROW + k] : 0.f;
            zt[i * ZTW + k] = __uint_as_float(tf32_rna(v));
        }
        if (t < 64) { ebg[t] = eb2l[t]; ebg[64 + t] = gWl[t]; }
        __syncthreads();

        // ======== projections via MMA: [32x24] @ [22x128] -> piU|pjU (half2) ========
        {
            float pacc[2][2][4];
            #pragma unroll
            for (int mf = 0; mf < 2; ++mf)
                #pragma unroll
                for (int nfi = 0; nfi < 2; ++nfi)
                    #pragma unroll
                    for (int e = 0; e < 4; ++e) pacc[mf][nfi][e] = 0.f;

            const int halfoff = (w < 4) ? 0 : DD;
            #pragma unroll
            for (int kk = 0; kk < 3; ++kk) {
                const int k0 = kk * 8 + cq, k1 = k0 + 4;
                uint32_t a00 = __float_as_uint(zt[lq * ZTW + k0]);
                uint32_t a01 = __float_as_uint(zt[(lq + 8) * ZTW + k0]);
                uint32_t a02 = __float_as_uint(zt[lq * ZTW + k1]);
                uint32_t a03 = __float_as_uint(zt[(lq + 8) * ZTW + k1]);
                uint32_t a10 = __float_as_uint(zt[(lq + 16) * ZTW + k0]);
                uint32_t a11 = __float_as_uint(zt[(lq + 24) * ZTW + k0]);
                uint32_t a12 = __float_as_uint(zt[(lq + 16) * ZTW + k1]);
                uint32_t a13 = __float_as_uint(zt[(lq + 24) * ZTW + k1]);
                #pragma unroll
                for (int nfi = 0; nfi < 2; ++nfi) {
                    const int col = (w & 3) * 16 + nfi * 8 + lq;
                    uint32_t b0 = tf32_rna(__ldg(eW1l + (halfoff + k0) * HDIM + col));
                    uint32_t b1 = (k1 < DD)
                                ? tf32_rna(__ldg(eW1l + (halfoff + k1) * HDIM + col)) : 0u;
                    mma_tf32(pacc[0][nfi], a00, a01, a02, a03, b0, b1);
                    mma_tf32(pacc[1][nfi], a10, a11, a12, a13, b0, b1);
                }
            }
            uint32_t* dstU = (w < 4) ? piU : pjU;
            const int cb = (w & 3) * 16;
            #pragma unroll
            for (int nfi = 0; nfi < 2; ++nfi) {
                float ex = 0.f, ey = 0.f;
                if (w < 4) {
                    float2 e2 = *(const float2*)(eb1l + cb + nfi * 8 + 2 * cq);
                    ex = e2.x; ey = e2.y;
                }
                const int cp = cb / 2 + nfi * 4 + cq;  // half2 pair index
                #pragma unroll
                for (int mf = 0; mf < 2; ++mf) {
                    int r = mf * 16 + lq;
                    dstU[r * PRU + cp] =
                        pack_h2(pacc[mf][nfi][0] + ex, pacc[mf][nfi][1] + ey);
                    dstU[(r + 8) * PRU + cp] =
                        pack_h2(pacc[mf][nfi][2] + ex, pacc[mf][nfi][3] + ey);
                }
            }
        }
        // ---- layernorm ----
        if (t < NN) {
            float mu = 0.f, sq = 0.f;
            #pragma unroll
            for (int d = 0; d < DD; ++d) {
                float v = zsh[t * ZROW + d];
                mu += v; sq += v * v;
            }
            mu *= (1.0f / DD);
            float var = sq * (1.0f / DD) - mu * mu;
            float rs = rsqrtf(var + 1e-5f);
            #pragma unroll
            for (int d = 0; d < DD; ++d)
                znsh[t * ZROW + d] = (zsh[t * ZROW + d] - mu) * rs * lngl[d] + lnbl[d];
        }
        __syncthreads();

        const uint32_t* pj0b = pjU + r0 * PRU;
        const uint32_t* pj1b = pjU + r1 * PRU;

        // ======== 8 edge tiles (fp16 MMA + f16x2 silu), zero intra-tile syncs ========
        for (int ig = 0; ig < 8; ++ig) {
            const int node = ig * 4 + i_sel;
            if (node >= NN) continue;            // dead-node skip (no barriers in loop)
            const uint32_t* pib = piU + node * PRU;

            float acc[8][4];
            #pragma unroll
            for (int nf = 0; nf < 8; ++nf)
                #pragma unroll
                for (int e = 0; e < 4; ++e) acc[nf][e] = 0.f;

            #pragma unroll
            for (int kk = 0; kk < 4; ++kk) {
                const int kp = kk * 8 + cq;
                uint32_t pi0 = pib[kp], pi1 = pib[kp + 4];
                uint32_t a0 = silu_h2(hadd2u(pi0, pj0b[kp]));
                uint32_t a1 = silu_h2(hadd2u(pi0, pj1b[kp]));
                uint32_t a2 = silu_h2(hadd2u(pi1, pj0b[kp + 4]));
                uint32_t a3 = silu_h2(hadd2u(pi1, pj1b[kp + 4]));
                const float* wb = w2h + (kk * 4 + cq) * W2HW + lq * 4;
                #pragma unroll
                for (int nf = 0; nf < 4; ++nf) {
                    float4 q = *(const float4*)(wb + nf * 32);
                    mma_f16(acc[nf],     a0, a1, a2, a3,
                            __float_as_uint(q.x), __float_as_uint(q.y));
                    mma_f16(acc[nf + 4], a0, a1, a2, a3,
                            __float_as_uint(q.z), __float_as_uint(q.w));
                }
            }

            // epilogue: f16x2 silu, fp32 gating
            float gp0 = 0.f, gp1 = 0.f;
            #pragma unroll
            for (int nf = 0; nf < 8; ++nf) {
                float2 e2 = *(const float2*)(ebg + nf * 8 + 2 * cq);
                float2 g2 = *(const float2*)(ebg + 64 + nf * 8 + 2 * cq);
                uint32_t u01 = silu_h2(pack_h2(acc[nf][0] + e2.x, acc[nf][1] + e2.y));
                uint32_t u23 = silu_h2(pack_h2(acc[nf][2] + e2.x, acc[nf][3] + e2.y));
                float2 v01 = h22f2(u01), v23 = h22f2(u23);
                acc[nf][0] = v01.x; acc[nf][1] = v01.y;
                acc[nf][2] = v23.x; acc[nf][3] = v23.y;
                gp0 = fmaf(v01.x, g2.x, fmaf(v01.y, g2.y, gp0));
                gp1 = fmaf(v23.x, g2.x, fmaf(v23.y, g2.y, gp1));
            }
            gp0 += __shfl_xor_sync(0xffffffffu, gp0, 1);
            gp0 += __shfl_xor_sync(0xffffffffu, gp0, 2);
            gp1 += __shfl_xor_sync(0xffffffffu, gp1, 1);
            gp1 += __shfl_xor_sync(0xffffffffu, gp1, 2);
            float g0 = sigm_t(gp0 + gbl);
            float g1 = (r1 < NN) ? sigm_t(gp1 + gbl) : 0.f;

            float s16[16];
            #pragma unroll
            for (int nf = 0; nf < 8; ++nf) {
                s16[nf * 2]     = fmaf(acc[nf][0], g0, acc[nf][2] * g1);
                s16[nf * 2 + 1] = fmaf(acc[nf][1], g0, acc[nf][3] * g1);
            }
            const int bb0 = lq & 1, bb1 = (lq >> 1) & 1, bb2 = (lq >> 2) & 1;
            float v8[8];
            #pragma unroll
            for (int j = 0; j < 8; ++j) {
                float keep = bb0 ? s16[8 + j] : s16[j];
                float send = bb0 ? s16[j]     : s16[8 + j];
                v8[j] = keep + __shfl_xor_sync(0xffffffffu, send, 4);
            }
            float v4a[4];
            #pragma unroll
            for (int j = 0; j < 4; ++j) {
                float keep = bb1 ? v8[4 + j] : v8[j];
                float send = bb1 ? v8[j]     : v8[4 + j];
                v4a[j] = keep + __shfl_xor_sync(0xffffffffu, send, 8);
            }
            float v2a[2];
            #pragma unroll
            for (int j = 0; j < 2; ++j) {
                float keep = bb2 ? v4a[2 + j] : v4a[j];
                float send = bb2 ? v4a[j]     : v4a[2 + j];
                v2a[j] = keep + __shfl_xor_sync(0xffffffffu, send, 16);
            }
            const int nfv = bb0 * 4 + bb1 * 2 + bb2;
            *(float2*)(magg + jh * 2048 + node * HDIM + nfv * 8 + 2 * cq) =
                make_float2(v2a[0], v2a[1]);
        }
        __syncthreads();

        // ======== concat buffer: [zn | m_i | 0-pad] ========
        for (int idx = t; idx < 32 * HDIM; idx += 256) {
            int i = idx >> 6, c = idx & 63;
            float v = (i < NN) ? magg[idx] + magg[2048 + idx] : 0.f;
            catsh[i * CATW + DD + c] = v;
        }
        for (int idx = t; idx < 32 * DD; idx += 256) {
            int i = idx / DD, d = idx - i * DD;
            catsh[i * CATW + d] = (i < NN) ? znsh[i * ZROW + d] : 0.f;
        }
        if (t < 64) catsh[(t >> 1) * CATW + 86 + (t & 1)] = 0.f;
        __syncthreads();

        // ======== node MLP layer 1 via MMA: [32x88] @ [86x64] ========
        {
            const int mh  = w & 1;
            const int nh4 = w >> 1;
            const int row0 = mh * 16 + lq, row1 = row0 + 8;
            float c2[2][4];
            #pragma unroll
            for (int nfi = 0; nfi < 2; ++nfi)
                #pragma unroll
                for (int e = 0; e < 4; ++e) c2[nfi][e] = 0.f;

            #pragma unroll
            for (int kk = 0; kk < 11; ++kk) {
                const int k0 = kk * 8 + cq, k1 = k0 + 4;
                uint32_t a0 = tf32_rna(catsh[row0 * CATW + k0]);
                uint32_t a1 = tf32_rna(catsh[row1 * CATW + k0]);
                uint32_t a2 = tf32_rna(catsh[row0 * CATW + k1]);
                uint32_t a3 = tf32_rna(catsh[row1 * CATW + k1]);
                #pragma unroll
                for (int nfi = 0; nfi < 2; ++nfi) {
                    const int col = (nh4 * 2 + nfi) * 8 + lq;
                    uint32_t b0 = tf32_rna(__ldg(nW1l + k0 * HDIM + col));
                    uint32_t b1 = (k1 < DD + HDIM)
                                ? tf32_rna(__ldg(nW1l + k1 * HDIM + col)) : 0u;
                    mma_tf32(c2[nfi], a0, a1, a2, a3, b0, b1);
                }
            }
            #pragma unroll
            for (int nfi = 0; nfi < 2; ++nfi) {
                const int colb = (nh4 * 2 + nfi) * 8 + 2 * cq;
                float2 nb = *(const float2*)(nb1l + colb);
                *(float2*)(hbuf + row0 * HROW + colb) = make_float2(
                    __uint_as_float(tf32_rna(silu_t(c2[nfi][0] + nb.x))),
                    __uint_as_float(tf32_rna(silu_t(c2[nfi][1] + nb.y))));
                *(float2*)(hbuf + row1 * HROW + colb) = make_float2(
                    __uint_as_float(tf32_rna(silu_t(c2[nfi][2] + nb.x))),
                    __uint_as_float(tf32_rna(silu_t(c2[nfi][3] + nb.y))));
            }
        }
        __syncthreads();

        // ======== node MLP layer 2 via MMA: [32x64] @ [64x24] + residual ========
        if (w < 6) {
            const int mf = w & 1;
            const int nf = w >> 1;
            const int d0 = nf * 8 + lq;
            float c4[4] = {0.f, 0.f, 0.f, 0.f};
            #pragma unroll
            for (int kk = 0; kk < 8; ++kk) {
                const int k0 = kk * 8 + cq, k1 = k0 + 4;
                uint32_t a0 = __float_as_uint(hbuf[(mf * 16 + lq) * HROW + k0]);
                uint32_t a1 = __float_as_uint(hbuf[(mf * 16 + lq + 8) * HROW + k0]);
                uint32_t a2 = __float_as_uint(hbuf[(mf * 16 + lq) * HROW + k1]);
                uint32_t a3 = __float_as_uint(hbuf[(mf * 16 + lq + 8) * HROW + k1]);
                uint32_t b0 = (d0 < DD) ? tf32_rna(__ldg(nW2l + k0 * DD + d0)) : 0u;
                uint32_t b1 = (d0 < DD) ? tf32_rna(__ldg(nW2l + k1 * DD + d0)) : 0u;
                mma_tf32(c4, a0, a1, a2, a3, b0, b1);
            }
            const int col = nf * 8 + 2 * cq;
            const int rr0 = mf * 16 + lq, rr1 = rr0 + 8;
            if (col < DD) {
                float nb = nb2l[col];
                if (rr0 < NN) zsh[rr0 * ZROW + col] += c4[0] + nb;
                if (rr1 < NN) zsh[rr1 * ZROW + col] += c4[2] + nb;
            }
            if (col + 1 < DD) {
                float nb = nb2l[col + 1];
                if (rr0 < NN) zsh[rr0 * ZROW + col + 1] += c4[1] + nb;
                if (rr1 < NN) zsh[rr1 * ZROW + col + 1] += c4[3] + nb;
            }
        }
        __syncthreads();
    }

    // ---- mean pool ----
    if (t < DD) {
        float s = 0.f;
        #pragma unroll
        for (int i = 0; i < NN; ++i) s += zsh[i * ZROW + t];
        znsh[t] = s * (1.0f / NN);
    }
    __syncthreads();

    // ---- head MLP ----
    if (t < HDIM) {
        float a = hb1[t];
        #pragma unroll
        for (int d = 0; d < DD; ++d) a += znsh[d] * hW1[d * HDIM + t];
        hbuf[t] = fmaxf(a, 0.f);
    }
    __syncthreads();

    float* ob = out + (size_t)b * (NN * OUTROW);
    for (int idx = t; idx < NN * OUTROW; idx += 256) {
        float v = 0.f;
        if (idx < NOUT) {
            v = hb2[idx];
            #pragma unroll
            for (int m2 = 0; m2 < HDIM; ++m2)
                v += hbuf[m2] * hW2[m2 * NOUT + idx];
        }
        ob[idx] = v;
    }
}

extern "C" void kernel_launch(void* const* d_in, const int* in_sizes, int n_in,
                              void* d_out, int out_size) {
    (void)in_sizes; (void)n_in; (void)out_size;
    const float* x    = (const float*)d_in[0];
    const float* ctx  = (const float*)d_in[1];
    const float* eW1  = (const float*)d_in[2];
    const float* eb1  = (const float*)d_in[3];
    const float* eW2  = (const float*)d_in[4];
    const float* eb2  = (const float*)d_in[5];
    const float* gW   = (const float*)d_in[6];
    const float* gb   = (const float*)d_in[7];
    const float* lng  = (const float*)d_in[8];
    const float* lnb  = (const float*)d_in[9];
    const float* nW1  = (const float*)d_in[10];
    const float* nb1  = (const float*)d_in[11];
    const float* nW2  = (const float*)d_in[12];
    const float* nb2  = (const float*)d_in[13];
    const float* hW1  = (const float*)d_in[14];
    const float* hb1  = (const float*)d_in[15];
    const float* hW2  = (const float*)d_in[16];
    const float* hb2  = (const float*)d_in[17];
    float* out = (float*)d_out;

    cudaFuncSetAttribute(gnn_kernel, cudaFuncAttributeMaxDynamicSharedMemorySize,
                         SMEM_FLOATS * sizeof(float));
    gnn_kernel<<<NB, 256, SMEM_FLOATS * sizeof(float)>>>(
        x, ctx, eW1, eb1, eW2, eb2, gW, gb, lng, lnb,
        nW1, nb1, nW2, nb2, hW1, hb1, hW2, hb2, out);
}

// round 10
// speedup vs baseline: 2.2752x; 1.0111x over previous
#include <cuda_runtime.h>
#include <cuda_fp16.h>
#include <cstdint>
#include <cstddef>

// Problem constants
#define NB   4096
#define NN   29
#define NC   6
#define CDIM 16
#define DD   22
#define HDIM 64
#define NL   2
#define NOUT 24
#define OUTROW 12
#define ZROW 25
#define PRU  40     // pi/pj row stride (uint32): 40 % 32 == 8 -> LDS.64 conflict-free
#define CATW 100
#define W2HW 136    // fp16 W2 row stride (floats)
#define ZTW  28     // zt row stride
#define HROW 68     // hbuf row stride

// Shared memory layout (float offsets)
#define OFF_Z    0        // 800
#define OFF_ZN   800      // 800
#define OFF_PI   1600     // 32*40 = 1280 (uint32 half2, paired (k,k+4))
#define OFF_PJ   2880     // 1280
#define OFF_W2H  4160     // 32*136 = 4352
#define OFF_ZT   8512     // 32*28 = 896
#define OFF_MAGG 9408     // 2*32*64 = 4096
#define OFF_H    13504    // 32*68 = 2176
#define OFF_EBH  15680    // 32 (eb2 half2, per-cq contiguous)
#define OFF_GWP  15712    // 64 (gW fp32, per-cq contiguous)
#define SMEM_FLOATS 15776 // 63104 bytes -> 3 CTAs/SM (189312 <= 228KB)
// catsh [32][100]=3200 aliases 1600..4800 (pi/pj/w2h-head dead by concat phase)

__device__ __forceinline__ float tanhfast(float x) {
    float y;
    asm("tanh.approx.f32 %0, %1;" : "=f"(y) : "f"(x));
    return y;
}
__device__ __forceinline__ float silu_t(float v) {
    float h = 0.5f * v;
    return fmaf(h, tanhfast(h), h);
}
__device__ __forceinline__ float sigm_t(float v) {
    return fmaf(0.5f, tanhfast(0.5f * v), 0.5f);
}
__device__ __forceinline__ uint32_t tf32_rna(float x) {
    uint32_t u;
    asm("cvt.rna.tf32.f32 %0, %1;" : "=r"(u) : "f"(x));
    return u;
}
__device__ __forceinline__ uint32_t pack_h2(float lo, float hi) {
    __half2 h = __floats2half2_rn(lo, hi);
    return *(uint32_t*)&h;
}
__device__ __forceinline__ uint32_t hadd2u(uint32_t a, uint32_t b) {
    __half2 r = __hadd2(*(__half2*)&a, *(__half2*)&b);
    return *(uint32_t*)&r;
}
// silu(v) = h + h*tanh(h), h = v/2, in f16x2 (one MUFU per two lanes)
__device__ __forceinline__ uint32_t silu_h2(uint32_t v) {
    __half2 h = __hmul2(*(__half2*)&v, __float2half2_rn(0.5f));
    uint32_t hu = *(uint32_t*)&h, tu;
    asm("tanh.approx.f16x2 %0, %1;" : "=r"(tu) : "r"(hu));
    __half2 r = __hfma2(h, *(__half2*)&tu, h);
    return *(uint32_t*)&r;
}
__device__ __forceinline__ float2 h22f2(uint32_t u) {
    return __half22float2(*(__half2*)&u);
}
__device__ __forceinline__ void mma_f16(float c[4], uint32_t a0, uint32_t a1,
                                        uint32_t a2, uint32_t a3,
                                        uint32_t b0, uint32_t b1) {
    asm volatile(
        "mma.sync.aligned.m16n8k16.row.col.f32.f16.f16.f32 "
        "{%0,%1,%2,%3}, {%4,%5,%6,%7}, {%8,%9}, {%0,%1,%2,%3};\n"
        : "+f"(c[0]), "+f"(c[1]), "+f"(c[2]), "+f"(c[3])
        : "r"(a0), "r"(a1), "r"(a2), "r"(a3), "r"(b0), "r"(b1));
}
__device__ __forceinline__ void mma_tf32(float c[4], uint32_t a0, uint32_t a1,
                                         uint32_t a2, uint32_t a3,
                                         uint32_t b0, uint32_t b1) {
    asm volatile(
        "mma.sync.aligned.m16n8k8.row.col.f32.tf32.tf32.f32 "
        "{%0,%1,%2,%3}, {%4,%5,%6,%7}, {%8,%9}, {%0,%1,%2,%3};\n"
        : "+f"(c[0]), "+f"(c[1]), "+f"(c[2]), "+f"(c[3])
        : "r"(a0), "r"(a1), "r"(a2), "r"(a3), "r"(b0), "r"(b1));
}

extern "C" __global__ void __launch_bounds__(256, 3)
gnn_kernel(const float* __restrict__ x,   const float* __restrict__ ctx,
           const float* __restrict__ eW1, const float* __restrict__ eb1,
           const float* __restrict__ eW2, const float* __restrict__ eb2,
           const float* __restrict__ gW,  const float* __restrict__ gb,
           const float* __restrict__ lng, const float* __restrict__ lnb,
           const float* __restrict__ nW1, const float* __restrict__ nb1,
           const float* __restrict__ nW2, const float* __restrict__ nb2,
           const float* __restrict__ hW1, const float* __restrict__ hb1,
           const float* __restrict__ hW2, const float* __restrict__ hb2,
           float* __restrict__ out)
{
    extern __shared__ float sh[];
    float*    zsh  = sh + OFF_Z;
    float*    znsh = sh + OFF_ZN;
    uint32_t* piU  = (uint32_t*)(sh + OFF_PI);  // [32][40] half2 pairs (k,k+4)
    uint32_t* pjU  = (uint32_t*)(sh + OFF_PJ);  // [32][40]
    float*    w2h  = sh + OFF_W2H;              // [32][136] half2-packed fp16 W2
    float*    zt   = sh + OFF_ZT;               // [32][28] tf32
    float*    magg = sh + OFF_MAGG;             // [2][32][64]
    float*    hbuf = sh + OFF_H;                // [32][68] tf32
    uint32_t* ebhU = (uint32_t*)(sh + OFF_EBH); // [4 cq][8 nf] eb2 half2
    float*    gwp  = sh + OFF_GWP;              // [4 cq][16] gW fp32 permuted
    float*    catsh = sh + OFF_PI;              // [32][100] aliases pi/pj/w2h-head

    const int b = blockIdx.x;
    const int t = threadIdx.x;
    const int w = t >> 5;
    const int lane = t & 31;
    const int lq = lane >> 2;
    const int cq = lane & 3;
    const int i_sel = w >> 1;
    const int jh = w & 1;
    const int r0 = jh * 16 + lq;
    const int r1 = r0 + 8;

    // ---- load z = concat(x, context) ----
    for (int idx = t; idx < NN * DD; idx += 256) {
        int i = idx / DD, d = idx - i * DD;
        float v = (d < NC) ? x[(b * NN + i) * NC + d]
                           : ctx[(b * NN + i) * CDIM + (d - NC)];
        zsh[i * ZROW + d] = v;
    }
    __syncthreads();

    for (int l = 0; l < NL; ++l) {
        const float* eW1l = eW1 + l * 2 * DD * HDIM;
        const float* eb1l = eb1 + l * HDIM;
        const float* eW2l = eW2 + l * HDIM * HDIM;
        const float* eb2l = eb2 + l * HDIM;
        const float* gWl  = gW  + l * HDIM;
        const float  gbl  = gb[l];
        const float* lngl = lng + l * DD;
        const float* lnbl = lnb + l * DD;
        const float* nW1l = nW1 + l * (DD + HDIM) * HDIM;
        const float* nb1l = nb1 + l * HDIM;
        const float* nW2l = nW2 + l * HDIM * DD;
        const float* nb2l = nb2 + l * DD;

        // ======== staging: w2h, zt, ebh, gwp ========
        for (int e = t; e < 1024; e += 256) {
            int kp = e >> 5, c = e & 31;
            int kk = kp >> 2, cqv = kp & 3;
            int k0 = kk * 16 + 2 * cqv;
            float4 q;
            q.x = __uint_as_float(pack_h2(eW2l[k0 * 64 + c],        eW2l[(k0 + 1) * 64 + c]));
            q.y = __uint_as_float(pack_h2(eW2l[(k0 + 8) * 64 + c],  eW2l[(k0 + 9) * 64 + c]));
            q.z = __uint_as_float(pack_h2(eW2l[k0 * 64 + c + 32],   eW2l[(k0 + 1) * 64 + c + 32]));
            q.w = __uint_as_float(pack_h2(eW2l[(k0 + 8) * 64 + c + 32], eW2l[(k0 + 9) * 64 + c + 32]));
            *(float4*)(w2h + kp * W2HW + c * 4) = q;
        }
        for (int idx = t; idx < 32 * 24; idx += 256) {
            int i = idx / 24, k = idx - i * 24;
            float v = (i < NN && k < DD) ? zsh[i * ZROW + k] : 0.f;
            zt[i * ZTW + k] = __uint_as_float(tf32_rna(v));
        }
        if (t < 32) {
            int cqv = t >> 3, nf = t & 7;
            ebhU[cqv * 8 + nf] = pack_h2(eb2l[nf * 8 + 2 * cqv],
                                         eb2l[nf * 8 + 2 * cqv + 1]);
        }
        if (t >= 64 && t < 128) {
            int i = t - 64;
            int cqv = i >> 4, e2 = i & 15;
            gwp[cqv * 16 + e2] = gWl[(e2 >> 1) * 8 + 2 * cqv + (e2 & 1)];
        }
        __syncthreads();

        // ======== projections via MMA: [32x24] @ [22x128] -> piU|pjU (half2 paired) ========
        {
            float pacc[2][2][4];
            #pragma unroll
            for (int mf = 0; mf < 2; ++mf)
                #pragma unroll
                for (int nfi = 0; nfi < 2; ++nfi)
                    #pragma unroll
                    for (int e = 0; e < 4; ++e) pacc[mf][nfi][e] = 0.f;

            const int halfoff = (w < 4) ? 0 : DD;
            #pragma unroll
            for (int kk = 0; kk < 3; ++kk) {
                const int k0 = kk * 8 + cq, k1 = k0 + 4;
                uint32_t a00 = __float_as_uint(zt[lq * ZTW + k0]);
                uint32_t a01 = __float_as_uint(zt[(lq + 8) * ZTW + k0]);
                uint32_t a02 = __float_as_uint(zt[lq * ZTW + k1]);
                uint32_t a03 = __float_as_uint(zt[(lq + 8) * ZTW + k1]);
                uint32_t a10 = __float_as_uint(zt[(lq + 16) * ZTW + k0]);
                uint32_t a11 = __float_as_uint(zt[(lq + 24) * ZTW + k0]);
                uint32_t a12 = __float_as_uint(zt[(lq + 16) * ZTW + k1]);
                uint32_t a13 = __float_as_uint(zt[(lq + 24) * ZTW + k1]);
                #pragma unroll
                for (int nfi = 0; nfi < 2; ++nfi) {
                    const int col = (w & 3) * 16 + nfi * 8 + lq;
                    uint32_t b0 = tf32_rna(__ldg(eW1l + (halfoff + k0) * HDIM + col));
                    uint32_t b1 = (k1 < DD)
                                ? tf32_rna(__ldg(eW1l + (halfoff + k1) * HDIM + col)) : 0u;
                    mma_tf32(pacc[0][nfi], a00, a01, a02, a03, b0, b1);
                    mma_tf32(pacc[1][nfi], a10, a11, a12, a13, b0, b1);
                }
            }
            uint32_t* dstU = (w < 4) ? piU : pjU;
            const int cb = (w & 3) * 16;
            #pragma unroll
            for (int nfi = 0; nfi < 2; ++nfi) {
                float ex = 0.f, ey = 0.f;
                if (w < 4) {
                    float2 e2 = *(const float2*)(eb1l + cb + nfi * 8 + 2 * cq);
                    ex = e2.x; ey = e2.y;
                }
                // paired layout: old pair-idx (w&3)*8 + nfi*4 + cq  ->  (w&3)*8 + cq*2 + nfi
                const int cp = (w & 3) * 8 + cq * 2 + nfi;
                #pragma unroll
                for (int mf = 0; mf < 2; ++mf) {
                    int r = mf * 16 + lq;
                    dstU[r * PRU + cp] =
                        pack_h2(pacc[mf][nfi][0] + ex, pacc[mf][nfi][1] + ey);
                    dstU[(r + 8) * PRU + cp] =
                        pack_h2(pacc[mf][nfi][2] + ex, pacc[mf][nfi][3] + ey);
                }
            }
        }
        // ---- layernorm ----
        if (t < NN) {
            float mu = 0.f, sq = 0.f;
            #pragma unroll
            for (int d = 0; d < DD; ++d) {
                float v = zsh[t * ZROW + d];
                mu += v; sq += v * v;
            }
            mu *= (1.0f / DD);
            float var = sq * (1.0f / DD) - mu * mu;
            float rs = rsqrtf(var + 1e-5f);
            #pragma unroll
            for (int d = 0; d < DD; ++d)
                znsh[t * ZROW + d] = (zsh[t * ZROW + d] - mu) * rs * lngl[d] + lnbl[d];
        }
        __syncthreads();

        // ---- hoist pj pairs (tile-invariant) into registers ----
        uint2 pj0q[4], pj1q[4];
        {
            const uint2* pj0p = (const uint2*)(pjU + r0 * PRU);
            const uint2* pj1p = (const uint2*)(pjU + r1 * PRU);
            #pragma unroll
            for (int kk = 0; kk < 4; ++kk) {
                pj0q[kk] = pj0p[kk * 4 + cq];
                pj1q[kk] = pj1p[kk * 4 + cq];
            }
        }

        // ======== 8 edge tiles (fp16 MMA + f16x2 silu), zero intra-tile syncs ========
        for (int ig = 0; ig < 8; ++ig) {
            const int node = ig * 4 + i_sel;
            if (node >= NN) continue;            // dead-node skip
            const uint2* pi2 = (const uint2*)(piU + node * PRU);

            float acc[8][4];
            #pragma unroll
            for (int nf = 0; nf < 8; ++nf)
                #pragma unroll
                for (int e = 0; e < 4; ++e) acc[nf][e] = 0.f;

            #pragma unroll
            for (int kk = 0; kk < 4; ++kk) {
                uint2 piq = pi2[kk * 4 + cq];    // broadcast across lq
                uint32_t a0 = silu_h2(hadd2u(piq.x, pj0q[kk].x));
                uint32_t a1 = silu_h2(hadd2u(piq.x, pj1q[kk].x));
                uint32_t a2 = silu_h2(hadd2u(piq.y, pj0q[kk].y));
                uint32_t a3 = silu_h2(hadd2u(piq.y, pj1q[kk].y));
                const float* wb = w2h + (kk * 4 + cq) * W2HW + lq * 4;
                #pragma unroll
                for (int nf = 0; nf < 4; ++nf) {
                    float4 q = *(const float4*)(wb + nf * 32);
                    mma_f16(acc[nf],     a0, a1, a2, a3,
                            __float_as_uint(q.x), __float_as_uint(q.y));
                    mma_f16(acc[nf + 4], a0, a1, a2, a3,
                            __float_as_uint(q.z), __float_as_uint(q.w));
                }
            }

            // epilogue constants (broadcast, per-cq contiguous)
            uint32_t ebr[8];
            *(uint4*)(ebr)     = *(const uint4*)(ebhU + cq * 8);
            *(uint4*)(ebr + 4) = *(const uint4*)(ebhU + cq * 8 + 4);
            float gwr[16];
            #pragma unroll
            for (int qi = 0; qi < 4; ++qi)
                *(float4*)(gwr + qi * 4) = *(const float4*)(gwp + cq * 16 + qi * 4);

            // epilogue: f16x2 bias+silu, fp32 gating
            float gp0 = 0.f, gp1 = 0.f;
            #pragma unroll
            for (int nf = 0; nf < 8; ++nf) {
                uint32_t u01 = silu_h2(hadd2u(pack_h2(acc[nf][0], acc[nf][1]), ebr[nf]));
                uint32_t u23 = silu_h2(hadd2u(pack_h2(acc[nf][2], acc[nf][3]), ebr[nf]));
                float2 v01 = h22f2(u01), v23 = h22f2(u23);
                acc[nf][0] = v01.x; acc[nf][1] = v01.y;
                acc[nf][2] = v23.x; acc[nf][3] = v23.y;
                gp0 = fmaf(v01.x, gwr[nf * 2], fmaf(v01.y, gwr[nf * 2 + 1], gp0));
                gp1 = fmaf(v23.x, gwr[nf * 2], fmaf(v23.y, gwr[nf * 2 + 1], gp1));
            }
            gp0 += __shfl_xor_sync(0xffffffffu, gp0, 1);
            gp0 += __shfl_xor_sync(0xffffffffu, gp0, 2);
            gp1 += __shfl_xor_sync(0xffffffffu, gp1, 1);
            gp1 += __shfl_xor_sync(0xffffffffu, gp1, 2);
            float g0 = sigm_t(gp0 + gbl);
            float g1 = (r1 < NN) ? sigm_t(gp1 + gbl) : 0.f;

            float s16[16];
            #pragma unroll
            for (int nf = 0; nf < 8; ++nf) {
                s16[nf * 2]     = fmaf(acc[nf][0], g0, acc[nf][2] * g1);
                s16[nf * 2 + 1] = fmaf(acc[nf][1], g0, acc[nf][3] * g1);
            }
            const int bb0 = lq & 1, bb1 = (lq >> 1) & 1, bb2 = (lq >> 2) & 1;
            float v8[8];
            #pragma unroll
            for (int j = 0; j < 8; ++j) {
                float keep = bb0 ? s16[8 + j] : s16[j];
                float send = bb0 ? s16[j]     : s16[8 + j];
                v8[j] = keep + __shfl_xor_sync(0xffffffffu, send, 4);
            }
            float v4a[4];
            #pragma unroll
            for (int j = 0; j < 4; ++j) {
                float keep = bb1 ? v8[4 + j] : v8[j];
                float send = bb1 ? v8[j]     : v8[4 + j];
                v4a[j] = keep + __shfl_xor_sync(0xffffffffu, send, 8);
            }
            float v2a[2];
            #pragma unroll
            for (int j = 0; j < 2; ++j) {
                float keep = bb2 ? v4a[2 + j] : v4a[j];
                float send = bb2 ? v4a[j]     : v4a[2 + j];
                v2a[j] = keep + __shfl_xor_sync(0xffffffffu, send, 16);
            }
            const int nfv = bb0 * 4 + bb1 * 2 + bb2;
            *(float2*)(magg + jh * 2048 + node * HDIM + nfv * 8 + 2 * cq) =
                make_float2(v2a[0], v2a[1]);
        }
        __syncthreads();

        // ======== concat buffer: [zn | m_i | 0-pad] ========
        for (int idx = t; idx < 32 * HDIM; idx += 256) {
            int i = idx >> 6, c = idx & 63;
            float v = (i < NN) ? magg[idx] + magg[2048 + idx] : 0.f;
            catsh[i * CATW + DD + c] = v;
        }
        for (int idx = t; idx < 32 * DD; idx += 256) {
            int i = idx / DD, d = idx - i * DD;
            catsh[i * CATW + d] = (i < NN) ? znsh[i * ZROW + d] : 0.f;
        }
        if (t < 64) catsh[(t >> 1) * CATW + 86 + (t & 1)] = 0.f;
        __syncthreads();

        // ======== node MLP layer 1 via MMA: [32x88] @ [86x64] ========
        {
            const int mh  = w & 1;
            const int nh4 = w >> 1;
            const int row0 = mh * 16 + lq, row1 = row0 + 8;
            float c2[2][4];
            #pragma unroll
            for (int nfi = 0; nfi < 2; ++nfi)
                #pragma unroll
                for (int e = 0; e < 4; ++e) c2[nfi][e] = 0.f;

            #pragma unroll
            for (int kk = 0; kk < 11; ++kk) {
                const int k0 = kk * 8 + cq, k1 = k0 + 4;
                uint32_t a0 = tf32_rna(catsh[row0 * CATW + k0]);
                uint32_t a1 = tf32_rna(catsh[row1 * CATW + k0]);
                uint32_t a2 = tf32_rna(catsh[row0 * CATW + k1]);
                uint32_t a3 = tf32_rna(catsh[row1 * CATW + k1]);
                #pragma unroll
                for (int nfi = 0; nfi < 2; ++nfi) {
                    const int col = (nh4 * 2 + nfi) * 8 + lq;
                    uint32_t b0 = tf32_rna(__ldg(nW1l + k0 * HDIM + col));
                    uint32_t b1 = (k1 < DD + HDIM)
                                ? tf32_rna(__ldg(nW1l + k1 * HDIM + col)) : 0u;
                    mma_tf32(c2[nfi], a0, a1, a2, a3, b0, b1);
                }
            }
            #pragma unroll
            for (int nfi = 0; nfi < 2; ++nfi) {
                const int colb = (nh4 * 2 + nfi) * 8 + 2 * cq;
                float2 nb = *(const float2*)(nb1l + colb);
                *(float2*)(hbuf + row0 * HROW + colb) = make_float2(
                    __uint_as_float(tf32_rna(silu_t(c2[nfi][0] + nb.x))),
                    __uint_as_float(tf32_rna(silu_t(c2[nfi][1] + nb.y))));
                *(float2*)(hbuf + row1 * HROW + colb) = make_float2(
                    __uint_as_float(tf32_rna(silu_t(c2[nfi][2] + nb.x))),
                    __uint_as_float(tf32_rna(silu_t(c2[nfi][3] + nb.y))));
            }
        }
        __syncthreads();

        // ======== node MLP layer 2 via MMA: [32x64] @ [64x24] + residual ========
        if (w < 6) {
            const int mf = w & 1;
            const int nf = w >> 1;
            const int d0 = nf * 8 + lq;
            float c4[4] = {0.f, 0.f, 0.f, 0.f};
            #pragma unroll
            for (int kk = 0; kk < 8; ++kk) {
                const int k0 = kk * 8 + cq, k1 = k0 + 4;
                uint32_t a0 = __float_as_uint(hbuf[(mf * 16 + lq) * HROW + k0]);
                uint32_t a1 = __float_as_uint(hbuf[(mf * 16 + lq + 8) * HROW + k0]);
                uint32_t a2 = __float_as_uint(hbuf[(mf * 16 + lq) * HROW + k1]);
                uint32_t a3 = __float_as_uint(hbuf[(mf * 16 + lq + 8) * HROW + k1]);
                uint32_t b0 = (d0 < DD) ? tf32_rna(__ldg(nW2l + k0 * DD + d0)) : 0u;
                uint32_t b1 = (d0 < DD) ? tf32_rna(__ldg(nW2l + k1 * DD + d0)) : 0u;
                mma_tf32(c4, a0, a1, a2, a3, b0, b1);
            }
            const int col = nf * 8 + 2 * cq;
            const int rr0 = mf * 16 + lq, rr1 = rr0 + 8;
            if (col < DD) {
                float nb = nb2l[col];
                if (rr0 < NN) zsh[rr0 * ZROW + col] += c4[0] + nb;
                if (rr1 < NN) zsh[rr1 * ZROW + col] += c4[2] + nb;
            }
            if (col + 1 < DD) {
                float nb = nb2l[col + 1];
                if (rr0 < NN) zsh[rr0 * ZROW + col + 1] += c4[1] + nb;
                if (rr1 < NN) zsh[rr1 * ZROW + col + 1] += c4[3] + nb;
            }
        }
        __syncthreads();
    }

    // ---- mean pool ----
    if (t < DD) {
        float s = 0.f;
        #pragma unroll
        for (int i = 0; i < NN; ++i) s += zsh[i * ZROW + t];
        znsh[t] = s * (1.0f / NN);
    }
    __syncthreads();

    // ---- head MLP ----
    if (t < HDIM) {
        float a = hb1[t];
        #pragma unroll
        for (int d = 0; d < DD; ++d) a += znsh[d] * hW1[d * HDIM + t];
        hbuf[t] = fmaxf(a, 0.f);
    }
    __syncthreads();

    float* ob = out + (size_t)b * (NN * OUTROW);
    for (int idx = t; idx < NN * OUTROW; idx += 256) {
        float v = 0.f;
        if (idx < NOUT) {
            v = hb2[idx];
            #pragma unroll
            for (int m2 = 0; m2 < HDIM; ++m2)
                v += hbuf[m2] * hW2[m2 * NOUT + idx];
        }
        ob[idx] = v;
    }
}

extern "C" void kernel_launch(void* const* d_in, const int* in_sizes, int n_in,
                              void* d_out, int out_size) {
    (void)in_sizes; (void)n_in; (void)out_size;
    const float* x    = (const float*)d_in[0];
    const float* ctx  = (const float*)d_in[1];
    const float* eW1  = (const float*)d_in[2];
    const float* eb1  = (const float*)d_in[3];
    const float* eW2  = (const float*)d_in[4];
    const float* eb2  = (const float*)d_in[5];
    const float* gW   = (const float*)d_in[6];
    const float* gb   = (const float*)d_in[7];
    const float* lng  = (const float*)d_in[8];
    const float* lnb  = (const float*)d_in[9];
    const float* nW1  = (const float*)d_in[10];
    const float* nb1  = (const float*)d_in[11];
    const float* nW2  = (const float*)d_in[12];
    const float* nb2  = (const float*)d_in[13];
    const float* hW1  = (const float*)d_in[14];
    const float* hb1  = (const float*)d_in[15];
    const float* hW2  = (const float*)d_in[16];
    const float* hb2  = (const float*)d_in[17];
    float* out = (float*)d_out;

    cudaFuncSetAttribute(gnn_kernel, cudaFuncAttributeMaxDynamicSharedMemorySize,
                         SMEM_FLOATS * sizeof(float));
    gnn_kernel<<<NB, 256, SMEM_FLOATS * sizeof(float)>>>(
        x, ctx, eW1, eb1, eW2, eb2, gW, gb, lng, lnb,
        nW1, nb1, nW2, nb2, hW1, hb1, hW2, hb2, out);
}

// round 11
// speedup vs baseline: 2.3020x; 1.0118x over previous
#include <cuda_runtime.h>
#include <cuda_fp16.h>
#include <cstdint>
#include <cstddef>

// Problem constants
#define NB   4096
#define NN   29
#define NC   6
#define CDIM 16
#define DD   22
#define HDIM 64
#define NL   2
#define NOUT 24
#define OUTROW 12
#define ZROW 25
#define PRU  40     // pi/pj row stride (uint32)
#define CATW 100
#define W2HW 136    // fp16 W2 row stride (floats)
#define ZTW  28     // zt row stride
#define HROW 68     // hbuf row stride

// Shared memory layout (float offsets)
#define OFF_Z    0        // 800
#define OFF_ZN   800      // 800
#define OFF_PI   1600     // 32*40 = 1280 (uint32 half2, paired (k,k+4))
#define OFF_PJ   2880     // 1280
#define OFF_W2H  4160     // 32*136 = 4352
#define OFF_ZT   8512     // 32*28 = 896
#define OFF_MAGG 9408     // 2*32*64 = 4096
#define OFF_H    13504    // 32*68 = 2176
#define OFF_EBH  15680    // 32 (eb2 half2, per-cq contiguous)
#define OFF_GWH  15712    // 32 (gW half2, per-cq contiguous)
#define SMEM_FLOATS 15744 // 62976 bytes -> 3 CTAs/SM
// catsh [32][100]=3200 aliases 1600..4800

__device__ __forceinline__ float tanhfast(float x) {
    float y;
    asm("tanh.approx.f32 %0, %1;" : "=f"(y) : "f"(x));
    return y;
}
__device__ __forceinline__ float silu_t(float v) {
    float h = 0.5f * v;
    return fmaf(h, tanhfast(h), h);
}
__device__ __forceinline__ float sigm_t(float v) {
    return fmaf(0.5f, tanhfast(0.5f * v), 0.5f);
}
__device__ __forceinline__ uint32_t tf32_rna(float x) {
    uint32_t u;
    asm("cvt.rna.tf32.f32 %0, %1;" : "=r"(u) : "f"(x));
    return u;
}
__device__ __forceinline__ uint32_t pack_h2(float lo, float hi) {
    __half2 h = __floats2half2_rn(lo, hi);
    return *(uint32_t*)&h;
}
__device__ __forceinline__ uint32_t hadd2u(uint32_t a, uint32_t b) {
    __half2 r = __hadd2(*(__half2*)&a, *(__half2*)&b);
    return *(uint32_t*)&r;
}
__device__ __forceinline__ uint32_t hfma2u(uint32_t a, uint32_t b, uint32_t c) {
    __half2 r = __hfma2(*(__half2*)&a, *(__half2*)&b, *(__half2*)&c);
    return *(uint32_t*)&r;
}
__device__ __forceinline__ uint32_t hmul2u(uint32_t a, uint32_t b) {
    __half2 r = __hmul2(*(__half2*)&a, *(__half2*)&b);
    return *(uint32_t*)&r;
}
// silu in f16x2
__device__ __forceinline__ uint32_t silu_h2(uint32_t v) {
    __half2 h = __hmul2(*(__half2*)&v, __float2half2_rn(0.5f));
    uint32_t hu = *(uint32_t*)&h, tu;
    asm("tanh.approx.f16x2 %0, %1;" : "=r"(tu) : "r"(hu));
    __half2 r = __hfma2(h, *(__half2*)&tu, h);
    return *(uint32_t*)&r;
}
__device__ __forceinline__ float2 h22f2(uint32_t u) {
    return __half22float2(*(__half2*)&u);
}
__device__ __forceinline__ uint32_t bcast_h2(float v) {
    __half2 h = __float2half2_rn(v);
    return *(uint32_t*)&h;
}
__device__ __forceinline__ void mma_f16(float c[4], uint32_t a0, uint32_t a1,
                                        uint32_t a2, uint32_t a3,
                                        uint32_t b0, uint32_t b1) {
    asm volatile(
        "mma.sync.aligned.m16n8k16.row.col.f32.f16.f16.f32 "
        "{%0,%1,%2,%3}, {%4,%5,%6,%7}, {%8,%9}, {%0,%1,%2,%3};\n"
        : "+f"(c[0]), "+f"(c[1]), "+f"(c[2]), "+f"(c[3])
        : "r"(a0), "r"(a1), "r"(a2), "r"(a3), "r"(b0), "r"(b1));
}
__device__ __forceinline__ void mma_tf32(float c[4], uint32_t a0, uint32_t a1,
                                         uint32_t a2, uint32_t a3,
                                         uint32_t b0, uint32_t b1) {
    asm volatile(
        "mma.sync.aligned.m16n8k8.row.col.f32.tf32.tf32.f32 "
        "{%0,%1,%2,%3}, {%4,%5,%6,%7}, {%8,%9}, {%0,%1,%2,%3};\n"
        : "+f"(c[0]), "+f"(c[1]), "+f"(c[2]), "+f"(c[3])
        : "r"(a0), "r"(a1), "r"(a2), "r"(a3), "r"(b0), "r"(b1));
}

extern "C" __global__ void __launch_bounds__(256, 3)
gnn_kernel(const float* __restrict__ x,   const float* __restrict__ ctx,
           const float* __restrict__ eW1, const float* __restrict__ eb1,
           const float* __restrict__ eW2, const float* __restrict__ eb2,
           const float* __restrict__ gW,  const float* __restrict__ gb,
           const float* __restrict__ lng, const float* __restrict__ lnb,
           const float* __restrict__ nW1, const float* __restrict__ nb1,
           const float* __restrict__ nW2, const float* __restrict__ nb2,
           const float* __restrict__ hW1, const float* __restrict__ hb1,
           const float* __restrict__ hW2, const float* __restrict__ hb2,
           float* __restrict__ out)
{
    extern __shared__ float sh[];
    float*    zsh  = sh + OFF_Z;
    float*    znsh = sh + OFF_ZN;
    uint32_t* piU  = (uint32_t*)(sh + OFF_PI);
    uint32_t* pjU  = (uint32_t*)(sh + OFF_PJ);
    float*    w2h  = sh + OFF_W2H;
    float*    zt   = sh + OFF_ZT;
    float*    magg = sh + OFF_MAGG;
    float*    hbuf = sh + OFF_H;
    uint32_t* ebhU = (uint32_t*)(sh + OFF_EBH);
    uint32_t* gwhU = (uint32_t*)(sh + OFF_GWH);
    float*    catsh = sh + OFF_PI;

    const int b = blockIdx.x;
    const int t = threadIdx.x;
    const int w = t >> 5;
    const int lane = t & 31;
    const int lq = lane >> 2;
    const int cq = lane & 3;
    const int i_sel = w >> 1;
    const int jh = w & 1;
    const int r0 = jh * 16 + lq;
    const int r1 = r0 + 8;

    // ---- load z = concat(x, context) ----
    for (int idx = t; idx < NN * DD; idx += 256) {
        int i = idx / DD, d = idx - i * DD;
        float v = (d < NC) ? x[(b * NN + i) * NC + d]
                           : ctx[(b * NN + i) * CDIM + (d - NC)];
        zsh[i * ZROW + d] = v;
    }
    __syncthreads();

    for (int l = 0; l < NL; ++l) {
        const float* eW1l = eW1 + l * 2 * DD * HDIM;
        const float* eb1l = eb1 + l * HDIM;
        const float* eW2l = eW2 + l * HDIM * HDIM;
        const float* eb2l = eb2 + l * HDIM;
        const float* gWl  = gW  + l * HDIM;
        const float  gbl  = gb[l];
        const float* lngl = lng + l * DD;
        const float* lnbl = lnb + l * DD;
        const float* nW1l = nW1 + l * (DD + HDIM) * HDIM;
        const float* nb1l = nb1 + l * HDIM;
        const float* nW2l = nW2 + l * HDIM * DD;
        const float* nb2l = nb2 + l * DD;

        // ======== staging: w2h, zt, ebh, gwh ========
        for (int e = t; e < 1024; e += 256) {
            int kp = e >> 5, c = e & 31;
            int kk = kp >> 2, cqv = kp & 3;
            int k0 = kk * 16 + 2 * cqv;
            float4 q;
            q.x = __uint_as_float(pack_h2(eW2l[k0 * 64 + c],        eW2l[(k0 + 1) * 64 + c]));
            q.y = __uint_as_float(pack_h2(eW2l[(k0 + 8) * 64 + c],  eW2l[(k0 + 9) * 64 + c]));
            q.z = __uint_as_float(pack_h2(eW2l[k0 * 64 + c + 32],   eW2l[(k0 + 1) * 64 + c + 32]));
            q.w = __uint_as_float(pack_h2(eW2l[(k0 + 8) * 64 + c + 32], eW2l[(k0 + 9) * 64 + c + 32]));
            *(float4*)(w2h + kp * W2HW + c * 4) = q;
        }
        for (int idx = t; idx < 32 * 24; idx += 256) {
            int i = idx / 24, k = idx - i * 24;
            float v = (i < NN && k < DD) ? zsh[i * ZROW + k] : 0.f;
            zt[i * ZTW + k] = __uint_as_float(tf32_rna(v));
        }
        if (t < 32) {
            int cqv = t >> 3, nf = t & 7;
            ebhU[cqv * 8 + nf] = pack_h2(eb2l[nf * 8 + 2 * cqv],
                                         eb2l[nf * 8 + 2 * cqv + 1]);
        }
        if (t >= 32 && t < 64) {
            int i = t - 32;
            int cqv = i >> 3, nf = i & 7;
            gwhU[cqv * 8 + nf] = pack_h2(gWl[nf * 8 + 2 * cqv],
                                         gWl[nf * 8 + 2 * cqv + 1]);
        }
        __syncthreads();

        // ======== projections via MMA: [32x24] @ [22x128] -> piU|pjU ========
        {
            float pacc[2][2][4];
            #pragma unroll
            for (int mf = 0; mf < 2; ++mf)
                #pragma unroll
                for (int nfi = 0; nfi < 2; ++nfi)
                    #pragma unroll
                    for (int e = 0; e < 4; ++e) pacc[mf][nfi][e] = 0.f;

            const int halfoff = (w < 4) ? 0 : DD;
            #pragma unroll
            for (int kk = 0; kk < 3; ++kk) {
                const int k0 = kk * 8 + cq, k1 = k0 + 4;
                uint32_t a00 = __float_as_uint(zt[lq * ZTW + k0]);
                uint32_t a01 = __float_as_uint(zt[(lq + 8) * ZTW + k0]);
                uint32_t a02 = __float_as_uint(zt[lq * ZTW + k1]);
                uint32_t a03 = __float_as_uint(zt[(lq + 8) * ZTW + k1]);
                uint32_t a10 = __float_as_uint(zt[(lq + 16) * ZTW + k0]);
                uint32_t a11 = __float_as_uint(zt[(lq + 24) * ZTW + k0]);
                uint32_t a12 = __float_as_uint(zt[(lq + 16) * ZTW + k1]);
                uint32_t a13 = __float_as_uint(zt[(lq + 24) * ZTW + k1]);
                #pragma unroll
                for (int nfi = 0; nfi < 2; ++nfi) {
                    const int col = (w & 3) * 16 + nfi * 8 + lq;
                    uint32_t b0 = tf32_rna(__ldg(eW1l + (halfoff + k0) * HDIM + col));
                    uint32_t b1 = (k1 < DD)
                                ? tf32_rna(__ldg(eW1l + (halfoff + k1) * HDIM + col)) : 0u;
                    mma_tf32(pacc[0][nfi], a00, a01, a02, a03, b0, b1);
                    mma_tf32(pacc[1][nfi], a10, a11, a12, a13, b0, b1);
                }
            }
            uint32_t* dstU = (w < 4) ? piU : pjU;
            #pragma unroll
            for (int nfi = 0; nfi < 2; ++nfi) {
                float ex = 0.f, ey = 0.f;
                if (w < 4) {
                    float2 e2 = *(const float2*)(eb1l + (w & 3) * 16 + nfi * 8 + 2 * cq);
                    ex = e2.x; ey = e2.y;
                }
                const int cp = (w & 3) * 8 + cq * 2 + nfi;
                #pragma unroll
                for (int mf = 0; mf < 2; ++mf) {
                    int r = mf * 16 + lq;
                    dstU[r * PRU + cp] =
                        pack_h2(pacc[mf][nfi][0] + ex, pacc[mf][nfi][1] + ey);
                    dstU[(r + 8) * PRU + cp] =
                        pack_h2(pacc[mf][nfi][2] + ex, pacc[mf][nfi][3] + ey);
                }
            }
        }
        // ---- layernorm ----
        if (t < NN) {
            float mu = 0.f, sq = 0.f;
            #pragma unroll
            for (int d = 0; d < DD; ++d) {
                float v = zsh[t * ZROW + d];
                mu += v; sq += v * v;
            }
            mu *= (1.0f / DD);
            float var = sq * (1.0f / DD) - mu * mu;
            float rs = rsqrtf(var + 1e-5f);
            #pragma unroll
            for (int d = 0; d < DD; ++d)
                znsh[t * ZROW + d] = (zsh[t * ZROW + d] - mu) * rs * lngl[d] + lnbl[d];
        }
        __syncthreads();

        // ---- per-layer hoists: pj pairs + epilogue constants ----
        uint2 pj0q[4], pj1q[4];
        {
            const uint2* pj0p = (const uint2*)(pjU + r0 * PRU);
            const uint2* pj1p = (const uint2*)(pjU + r1 * PRU);
            #pragma unroll
            for (int kk = 0; kk < 4; ++kk) {
                pj0q[kk] = pj0p[kk * 4 + cq];
                pj1q[kk] = pj1p[kk * 4 + cq];
            }
        }
        uint32_t ebr[8], gwh[8];
        *(uint4*)(ebr)     = *(const uint4*)(ebhU + cq * 8);
        *(uint4*)(ebr + 4) = *(const uint4*)(ebhU + cq * 8 + 4);
        *(uint4*)(gwh)     = *(const uint4*)(gwhU + cq * 8);
        *(uint4*)(gwh + 4) = *(const uint4*)(gwhU + cq * 8 + 4);

        // ======== 8 edge tiles (fp16 MMA + f16x2 epilogue) ========
        for (int ig = 0; ig < 8; ++ig) {
            const int node = ig * 4 + i_sel;
            if (node >= NN) continue;
            const uint2* pi2 = (const uint2*)(piU + node * PRU);

            float acc[8][4];
            #pragma unroll
            for (int nf = 0; nf < 8; ++nf)
                #pragma unroll
                for (int e = 0; e < 4; ++e) acc[nf][e] = 0.f;

            #pragma unroll
            for (int kk = 0; kk < 4; ++kk) {
                uint2 piq = pi2[kk * 4 + cq];
                uint32_t a0 = silu_h2(hadd2u(piq.x, pj0q[kk].x));
                uint32_t a1 = silu_h2(hadd2u(piq.x, pj1q[kk].x));
                uint32_t a2 = silu_h2(hadd2u(piq.y, pj0q[kk].y));
                uint32_t a3 = silu_h2(hadd2u(piq.y, pj1q[kk].y));
                const float* wb = w2h + (kk * 4 + cq) * W2HW + lq * 4;
                #pragma unroll
                for (int nf = 0; nf < 4; ++nf) {
                    float4 q = *(const float4*)(wb + nf * 32);
                    mma_f16(acc[nf],     a0, a1, a2, a3,
                            __float_as_uint(q.x), __float_as_uint(q.y));
                    mma_f16(acc[nf + 4], a0, a1, a2, a3,
                            __float_as_uint(q.z), __float_as_uint(q.w));
                }
            }

            // epilogue: f16x2 bias+silu, f16x2 gate dot
            uint32_t m01[8], m23[8];
            uint32_t gph0 = 0, gph1 = 0;     // half2(0,0)
            #pragma unroll
            for (int nf = 0; nf < 8; ++nf) {
                uint32_t u01 = silu_h2(hadd2u(pack_h2(acc[nf][0], acc[nf][1]), ebr[nf]));
                uint32_t u23 = silu_h2(hadd2u(pack_h2(acc[nf][2], acc[nf][3]), ebr[nf]));
                m01[nf] = u01; m23[nf] = u23;
                gph0 = hfma2u(u01, gwh[nf], gph0);
                gph1 = hfma2u(u23, gwh[nf], gph1);
            }
            float2 gpf0 = h22f2(gph0), gpf1 = h22f2(gph1);
            float gp0 = gpf0.x + gpf0.y;
            float gp1 = gpf1.x + gpf1.y;
            gp0 += __shfl_xor_sync(0xffffffffu, gp0, 1);
            gp0 += __shfl_xor_sync(0xffffffffu, gp0, 2);
            gp1 += __shfl_xor_sync(0xffffffffu, gp1, 1);
            gp1 += __shfl_xor_sync(0xffffffffu, gp1, 2);
            float g0 = sigm_t(gp0 + gbl);
            float g1 = (r1 < NN) ? sigm_t(gp1 + gbl) : 0.f;
            uint32_t g0h = bcast_h2(g0), g1h = bcast_h2(g1);

            // gated 2-term j-combine in f16x2, unpack, fp32 reduction
            float s16[16];
            #pragma unroll
            for (int nf = 0; nf < 8; ++nf) {
                uint32_t sv = hfma2u(m23[nf], g1h, hmul2u(m01[nf], g0h));
                float2 s2 = h22f2(sv);
                s16[nf * 2] = s2.x; s16[nf * 2 + 1] = s2.y;
            }
            const int bb0 = lq & 1, bb1 = (lq >> 1) & 1, bb2 = (lq >> 2) & 1;
            float v8[8];
            #pragma unroll
            for (int j = 0; j < 8; ++j) {
                float keep = bb0 ? s16[8 + j] : s16[j];
                float send = bb0 ? s16[j]     : s16[8 + j];
                v8[j] = keep + __shfl_xor_sync(0xffffffffu, send, 4);
            }
            float v4a[4];
            #pragma unroll
            for (int j = 0; j < 4; ++j) {
                float keep = bb1 ? v8[4 + j] : v8[j];
                float send = bb1 ? v8[j]     : v8[4 + j];
                v4a[j] = keep + __shfl_xor_sync(0xffffffffu, send, 8);
            }
            float v2a[2];
            #pragma unroll
            for (int j = 0; j < 2; ++j) {
                float keep = bb2 ? v4a[2 + j] : v4a[j];
                float send = bb2 ? v4a[j]     : v4a[2 + j];
                v2a[j] = keep + __shfl_xor_sync(0xffffffffu, send, 16);
            }
            const int nfv = bb0 * 4 + bb1 * 2 + bb2;
            *(float2*)(magg + jh * 2048 + node * HDIM + nfv * 8 + 2 * cq) =
                make_float2(v2a[0], v2a[1]);
        }
        __syncthreads();

        // ======== concat buffer: [zn | m_i | 0-pad], pre-rounded tf32 ========
        for (int idx = t; idx < 32 * HDIM; idx += 256) {
            int i = idx >> 6, c = idx & 63;
            float v = (i < NN) ? magg[idx] + magg[2048 + idx] : 0.f;
            catsh[i * CATW + DD + c] = __uint_as_float(tf32_rna(v));
        }
        for (int idx = t; idx < 32 * DD; idx += 256) {
            int i = idx / DD, d = idx - i * DD;
            float v = (i < NN) ? znsh[i * ZROW + d] : 0.f;
            catsh[i * CATW + d] = __uint_as_float(tf32_rna(v));
        }
        if (t < 64) catsh[(t >> 1) * CATW + 86 + (t & 1)] = 0.f;
        __syncthreads();

        // ======== node MLP layer 1 via MMA: [32x88] @ [86x64] ========
        {
            const int mh  = w & 1;
            const int nh4 = w >> 1;
            const int row0 = mh * 16 + lq, row1 = row0 + 8;
            float c2[2][4];
            #pragma unroll
            for (int nfi = 0; nfi < 2; ++nfi)
                #pragma unroll
                for (int e = 0; e < 4; ++e) c2[nfi][e] = 0.f;

            #pragma unroll
            for (int kk = 0; kk < 11; ++kk) {
                const int k0 = kk * 8 + cq, k1 = k0 + 4;
                uint32_t a0 = __float_as_uint(catsh[row0 * CATW + k0]);
                uint32_t a1 = __float_as_uint(catsh[row1 * CATW + k0]);
                uint32_t a2 = __float_as_uint(catsh[row0 * CATW + k1]);
                uint32_t a3 = __float_as_uint(catsh[row1 * CATW + k1]);
                #pragma unroll
                for (int nfi = 0; nfi < 2; ++nfi) {
                    const int col = (nh4 * 2 + nfi) * 8 + lq;
                    uint32_t b0 = tf32_rna(__ldg(nW1l + k0 * HDIM + col));
                    uint32_t b1 = (k1 < DD + HDIM)
                                ? tf32_rna(__ldg(nW1l + k1 * HDIM + col)) : 0u;
                    mma_tf32(c2[nfi], a0, a1, a2, a3, b0, b1);
                }
            }
            #pragma unroll
            for (int nfi = 0; nfi < 2; ++nfi) {
                const int colb = (nh4 * 2 + nfi) * 8 + 2 * cq;
                float2 nb = *(const float2*)(nb1l + colb);
                *(float2*)(hbuf + row0 * HROW + colb) = make_float2(
                    __uint_as_float(tf32_rna(silu_t(c2[nfi][0] + nb.x))),
                    __uint_as_float(tf32_rna(silu_t(c2[nfi][1] + nb.y))));
                *(float2*)(hbuf + row1 * HROW + colb) = make_float2(
                    __uint_as_float(tf32_rna(silu_t(c2[nfi][2] + nb.x))),
                    __uint_as_float(tf32_rna(silu_t(c2[nfi][3] + nb.y))));
            }
        }
        __syncthreads();

        // ======== node MLP layer 2 via MMA: [32x64] @ [64x24] + residual ========
        if (w < 6) {
            const int mf = w & 1;
            const int nf = w >> 1;
            const int d0 = nf * 8 + lq;
            float c4[4] = {0.f, 0.f, 0.f, 0.f};
            #pragma unroll
            for (int kk = 0; kk < 8; ++kk) {
                const int k0 = kk * 8 + cq, k1 = k0 + 4;
                uint32_t a0 = __float_as_uint(hbuf[(mf * 16 + lq) * HROW + k0]);
                uint32_t a1 = __float_as_uint(hbuf[(mf * 16 + lq + 8) * HROW + k0]);
                uint32_t a2 = __float_as_uint(hbuf[(mf * 16 + lq) * HROW + k1]);
                uint32_t a3 = __float_as_uint(hbuf[(mf * 16 + lq + 8) * HROW + k1]);
                uint32_t b0 = (d0 < DD) ? tf32_rna(__ldg(nW2l + k0 * DD + d0)) : 0u;
                uint32_t b1 = (d0 < DD) ? tf32_rna(__ldg(nW2l + k1 * DD + d0)) : 0u;
                mma_tf32(c4, a0, a1, a2, a3, b0, b1);
            }
            const int col = nf * 8 + 2 * cq;
            const int rr0 = mf * 16 + lq, rr1 = rr0 + 8;
            if (col < DD) {
                float nb = nb2l[col];
                if (rr0 < NN) zsh[rr0 * ZROW + col] += c4[0] + nb;
                if (rr1 < NN) zsh[rr1 * ZROW + col] += c4[2] + nb;
            }
            if (col + 1 < DD) {
                float nb = nb2l[col + 1];
                if (rr0 < NN) zsh[rr0 * ZROW + col + 1] += c4[1] + nb;
                if (rr1 < NN) zsh[rr1 * ZROW + col + 1] += c4[3] + nb;
            }
        }
        __syncthreads();
    }

    // ---- mean pool ----
    if (t < DD) {
        float s = 0.f;
        #pragma unroll
        for (int i = 0; i < NN; ++i) s += zsh[i * ZROW + t];
        znsh[t] = s * (1.0f / NN);
    }
    __syncthreads();

    // ---- head MLP ----
    if (t < HDIM) {
        float a = hb1[t];
        #pragma unroll
        for (int d = 0; d < DD; ++d) a += znsh[d] * hW1[d * HDIM + t];
        hbuf[t] = fmaxf(a, 0.f);
    }
    __syncthreads();

    float* ob = out + (size_t)b * (NN * OUTROW);
    for (int idx = t; idx < NN * OUTROW; idx += 256) {
        float v = 0.f;
        if (idx < NOUT) {
            v = hb2[idx];
            #pragma unroll
            for (int m2 = 0; m2 < HDIM; ++m2)
                v += hbuf[m2] * hW2[m2 * NOUT + idx];
        }
        ob[idx] = v;
    }
}

extern "C" void kernel_launch(void* const* d_in, const int* in_sizes, int n_in,
                              void* d_out, int out_size) {
    (void)in_sizes; (void)n_in; (void)out_size;
    const float* x    = (const float*)d_in[0];
    const float* ctx  = (const float*)d_in[1];
    const float* eW1  = (const float*)d_in[2];
    const float* eb1  = (const float*)d_in[3];
    const float* eW2  = (const float*)d_in[4];
    const float* eb2  = (const float*)d_in[5];
    const float* gW   = (const float*)d_in[6];
    const float* gb   = (const float*)d_in[7];
    const float* lng  = (const float*)d_in[8];
    const float* lnb  = (const float*)d_in[9];
    const float* nW1  = (const float*)d_in[10];
    const float* nb1  = (const float*)d_in[11];
    const float* nW2  = (const float*)d_in[12];
    const float* nb2  = (const float*)d_in[13];
    const float* hW1  = (const float*)d_in[14];
    const float* hb1  = (const float*)d_in[15];
    const float* hW2  = (const float*)d_in[16];
    const float* hb2  = (const float*)d_in[17];
    float* out = (float*)d_out;

    cudaFuncSetAttribute(gnn_kernel, cudaFuncAttributeMaxDynamicSharedMemorySize,
                         SMEM_FLOATS * sizeof(float));
    gnn_kernel<<<NB, 256, SMEM_FLOATS * sizeof(float)>>>(
        x, ctx, eW1, eb1, eW2, eb2, gW, gb, lng, lnb,
        nW1, nb1, nW2, nb2, hW1, hb1, hW2, hb2, out);
}

// round 12
// speedup vs baseline: 2.5305x; 1.0993x over previous
#include <cuda_runtime.h>
#include <cuda_fp16.h>
#include <cstdint>
#include <cstddef>

// Problem constants
#define NB   4096
#define NN   29
#define NC   6
#define CDIM 16
#define DD   22
#define HDIM 64
#define NL   2
#define NOUT 24
#define OUTROW 12
#define ZROW 25
#define PRU  40     // pi/pj row stride (uint32)
#define W2HW 136    // fp16 W2 row stride (floats)
#define ZTU  20     // ztU row stride (uint32 pairs): 20lq+cq distinct mod 32
#define CATU 52     // catshU row stride: 52%32=20 -> distinct
#define HBU  36     // hbufU row stride: 36%32=4 -> distinct
#define MAGU 32     // maggU row stride

// Shared memory layout (float offsets)
#define OFF_Z    0        // 800
#define OFF_ZN   800      // 800
#define OFF_PI   1600     // 1280 (piU)
#define OFF_PJ   2880     // 1280 (pjU)
#define OFF_W2H  4160     // 4352
#define OFF_ZT   8512     // 32*20 = 640 (ztU)
#define OFF_MAGG 9152     // 2*32*32 = 2048 (maggU)
#define OFF_H    11200    // 32*36 = 1152 (hbufU)
#define OFF_EBH  12352    // 32
#define OFF_GWH  12384    // 32
#define SMEM_FLOATS 12416 // 49664 bytes -> 3 CTAs/SM
// catshU [32][52]=1664 uint aliases OFF_PI..(piU/pjU dead after tile loop)

__device__ __forceinline__ float tanhfast(float x) {
    float y;
    asm("tanh.approx.f32 %0, %1;" : "=f"(y) : "f"(x));
    return y;
}
__device__ __forceinline__ float silu_t(float v) {
    float h = 0.5f * v;
    return fmaf(h, tanhfast(h), h);
}
__device__ __forceinline__ float sigm_t(float v) {
    return fmaf(0.5f, tanhfast(0.5f * v), 0.5f);
}
__device__ __forceinline__ uint32_t pack_h2(float lo, float hi) {
    __half2 h = __floats2half2_rn(lo, hi);
    return *(uint32_t*)&h;
}
__device__ __forceinline__ uint32_t hadd2u(uint32_t a, uint32_t b) {
    __half2 r = __hadd2(*(__half2*)&a, *(__half2*)&b);
    return *(uint32_t*)&r;
}
__device__ __forceinline__ uint32_t hfma2u(uint32_t a, uint32_t b, uint32_t c) {
    __half2 r = __hfma2(*(__half2*)&a, *(__half2*)&b, *(__half2*)&c);
    return *(uint32_t*)&r;
}
__device__ __forceinline__ uint32_t hmul2u(uint32_t a, uint32_t b) {
    __half2 r = __hmul2(*(__half2*)&a, *(__half2*)&b);
    return *(uint32_t*)&r;
}
__device__ __forceinline__ uint32_t silu_h2(uint32_t v) {
    __half2 h = __hmul2(*(__half2*)&v, __float2half2_rn(0.5f));
    uint32_t hu = *(uint32_t*)&h, tu;
    asm("tanh.approx.f16x2 %0, %1;" : "=r"(tu) : "r"(hu));
    __half2 r = __hfma2(h, *(__half2*)&tu, h);
    return *(uint32_t*)&r;
}
__device__ __forceinline__ float2 h22f2(uint32_t u) {
    return __half22float2(*(__half2*)&u);
}
__device__ __forceinline__ uint32_t bcast_h2(float v) {
    __half2 h = __float2half2_rn(v);
    return *(uint32_t*)&h;
}
__device__ __forceinline__ void mma_f16(float c[4], uint32_t a0, uint32_t a1,
                                        uint32_t a2, uint32_t a3,
                                        uint32_t b0, uint32_t b1) {
    asm volatile(
        "mma.sync.aligned.m16n8k16.row.col.f32.f16.f16.f32 "
        "{%0,%1,%2,%3}, {%4,%5,%6,%7}, {%8,%9}, {%0,%1,%2,%3};\n"
        : "+f"(c[0]), "+f"(c[1]), "+f"(c[2]), "+f"(c[3])
        : "r"(a0), "r"(a1), "r"(a2), "r"(a3), "r"(b0), "r"(b1));
}
__device__ __forceinline__ void mma_f16_k8(float c[4], uint32_t a0, uint32_t a1,
                                           uint32_t b0) {
    asm volatile(
        "mma.sync.aligned.m16n8k8.row.col.f32.f16.f16.f32 "
        "{%0,%1,%2,%3}, {%4,%5}, {%6}, {%0,%1,%2,%3};\n"
        : "+f"(c[0]), "+f"(c[1]), "+f"(c[2]), "+f"(c[3])
        : "r"(a0), "r"(a1), "r"(b0));
}

extern "C" __global__ void __launch_bounds__(256, 3)
gnn_kernel(const float* __restrict__ x,   const float* __restrict__ ctx,
           const float* __restrict__ eW1, const float* __restrict__ eb1,
           const float* __restrict__ eW2, const float* __restrict__ eb2,
           const float* __restrict__ gW,  const float* __restrict__ gb,
           const float* __restrict__ lng, const float* __restrict__ lnb,
           const float* __restrict__ nW1, const float* __restrict__ nb1,
           const float* __restrict__ nW2, const float* __restrict__ nb2,
           const float* __restrict__ hW1, const float* __restrict__ hb1,
           const float* __restrict__ hW2, const float* __restrict__ hb2,
           float* __restrict__ out)
{
    extern __shared__ float sh[];
    float*    zsh  = sh + OFF_Z;
    float*    znsh = sh + OFF_ZN;
    uint32_t* piU  = (uint32_t*)(sh + OFF_PI);
    uint32_t* pjU  = (uint32_t*)(sh + OFF_PJ);
    float*    w2h  = sh + OFF_W2H;
    uint32_t* ztU  = (uint32_t*)(sh + OFF_ZT);    // [32][20] half2 pairs
    uint32_t* maggU = (uint32_t*)(sh + OFF_MAGG); // [2][32][32] half2
    uint32_t* hbufU = (uint32_t*)(sh + OFF_H);    // [32][36] half2 pairs
    uint32_t* ebhU = (uint32_t*)(sh + OFF_EBH);
    uint32_t* gwhU = (uint32_t*)(sh + OFF_GWH);
    uint32_t* catshU = (uint32_t*)(sh + OFF_PI);  // [32][52] aliases pi/pj

    const int b = blockIdx.x;
    const int t = threadIdx.x;
    const int w = t >> 5;
    const int lane = t & 31;
    const int lq = lane >> 2;
    const int cq = lane & 3;
    const int i_sel = w >> 1;
    const int jh = w & 1;
    const int r0 = jh * 16 + lq;
    const int r1 = r0 + 8;

    // ---- load z = concat(x, context) ----
    for (int idx = t; idx < NN * DD; idx += 256) {
        int i = idx / DD, d = idx - i * DD;
        float v = (d < NC) ? x[(b * NN + i) * NC + d]
                           : ctx[(b * NN + i) * CDIM + (d - NC)];
        zsh[i * ZROW + d] = v;
    }
    __syncthreads();

    for (int l = 0; l < NL; ++l) {
        const float* eW1l = eW1 + l * 2 * DD * HDIM;
        const float* eb1l = eb1 + l * HDIM;
        const float* eW2l = eW2 + l * HDIM * HDIM;
        const float* eb2l = eb2 + l * HDIM;
        const float* gWl  = gW  + l * HDIM;
        const float  gbl  = gb[l];
        const float* lngl = lng + l * DD;
        const float* lnbl = lnb + l * DD;
        const float* nW1l = nW1 + l * (DD + HDIM) * HDIM;
        const float* nb1l = nb1 + l * HDIM;
        const float* nW2l = nW2 + l * HDIM * DD;
        const float* nb2l = nb2 + l * DD;

        // ======== staging: w2h, ztU, ebh, gwh ========
        for (int e = t; e < 1024; e += 256) {
            int kp = e >> 5, c = e & 31;
            int kk = kp >> 2, cqv = kp & 3;
            int k0 = kk * 16 + 2 * cqv;
            float4 q;
            q.x = __uint_as_float(pack_h2(eW2l[k0 * 64 + c],        eW2l[(k0 + 1) * 64 + c]));
            q.y = __uint_as_float(pack_h2(eW2l[(k0 + 8) * 64 + c],  eW2l[(k0 + 9) * 64 + c]));
            q.z = __uint_as_float(pack_h2(eW2l[k0 * 64 + c + 32],   eW2l[(k0 + 1) * 64 + c + 32]));
            q.w = __uint_as_float(pack_h2(eW2l[(k0 + 8) * 64 + c + 32], eW2l[(k0 + 9) * 64 + c + 32]));
            *(float4*)(w2h + kp * W2HW + c * 4) = q;
        }
        for (int idx = t; idx < 32 * 16; idx += 256) {
            int i = idx >> 4, p = idx & 15;
            uint32_t v = 0;
            if (i < NN && p < 11)
                v = pack_h2(zsh[i * ZROW + 2 * p], zsh[i * ZROW + 2 * p + 1]);
            ztU[i * ZTU + p] = v;
        }
        if (t < 32) {
            int cqv = t >> 3, nf = t & 7;
            ebhU[cqv * 8 + nf] = pack_h2(eb2l[nf * 8 + 2 * cqv],
                                         eb2l[nf * 8 + 2 * cqv + 1]);
        }
        if (t >= 32 && t < 64) {
            int i = t - 32;
            int cqv = i >> 3, nf = i & 7;
            gwhU[cqv * 8 + nf] = pack_h2(gWl[nf * 8 + 2 * cqv],
                                         gWl[nf * 8 + 2 * cqv + 1]);
        }
        __syncthreads();

        // ======== projections via f16 MMA: [32x24] @ [22x128] -> piU|pjU ========
        {
            float pacc[2][2][4];
            #pragma unroll
            for (int mf = 0; mf < 2; ++mf)
                #pragma unroll
                for (int nfi = 0; nfi < 2; ++nfi)
                    #pragma unroll
                    for (int e = 0; e < 4; ++e) pacc[mf][nfi][e] = 0.f;

            const float* Wb = eW1l + ((w < 4) ? 0 : DD) * HDIM;
            // K block 0-15 (m16n8k16)
            {
                uint32_t aA[2][4];
                #pragma unroll
                for (int mf = 0; mf < 2; ++mf) {
                    int rb = mf * 16;
                    aA[mf][0] = ztU[(rb + lq) * ZTU + cq];
                    aA[mf][1] = ztU[(rb + lq + 8) * ZTU + cq];
                    aA[mf][2] = ztU[(rb + lq) * ZTU + cq + 4];
                    aA[mf][3] = ztU[(rb + lq + 8) * ZTU + cq + 4];
                }
                #pragma unroll
                for (int nfi = 0; nfi < 2; ++nfi) {
                    const int col = (w & 3) * 16 + nfi * 8 + lq;
                    uint32_t b0 = pack_h2(__ldg(Wb + (2 * cq) * HDIM + col),
                                          __ldg(Wb + (2 * cq + 1) * HDIM + col));
                    uint32_t b1 = pack_h2(__ldg(Wb + (2 * cq + 8) * HDIM + col),
                                          __ldg(Wb + (2 * cq + 9) * HDIM + col));
                    #pragma unroll
                    for (int mf = 0; mf < 2; ++mf)
                        mma_f16(pacc[mf][nfi], aA[mf][0], aA[mf][1],
                                aA[mf][2], aA[mf][3], b0, b1);
                }
            }
            // K block 16-23 (m16n8k8, cq==3 -> zero pair k=22,23)
            {
                uint32_t aA[2][2];
                #pragma unroll
                for (int mf = 0; mf < 2; ++mf) {
                    int rb = mf * 16;
                    aA[mf][0] = ztU[(rb + lq) * ZTU + 8 + cq];
                    aA[mf][1] = ztU[(rb + lq + 8) * ZTU + 8 + cq];
                }
                #pragma unroll
                for (int nfi = 0; nfi < 2; ++nfi) {
                    const int col = (w & 3) * 16 + nfi * 8 + lq;
                    uint32_t b0 = (cq < 3)
                        ? pack_h2(__ldg(Wb + (16 + 2 * cq) * HDIM + col),
                                  __ldg(Wb + (17 + 2 * cq) * HDIM + col)) : 0u;
                    #pragma unroll
                    for (int mf = 0; mf < 2; ++mf)
                        mma_f16_k8(pacc[mf][nfi], aA[mf][0], aA[mf][1], b0);
                }
            }
            uint32_t* dstU = (w < 4) ? piU : pjU;
            #pragma unroll
            for (int nfi = 0; nfi < 2; ++nfi) {
                float ex = 0.f, ey = 0.f;
                if (w < 4) {
                    float2 e2 = *(const float2*)(eb1l + (w & 3) * 16 + nfi * 8 + 2 * cq);
                    ex = e2.x; ey = e2.y;
                }
                const int cp = (w & 3) * 8 + cq * 2 + nfi;
                #pragma unroll
                for (int mf = 0; mf < 2; ++mf) {
                    int r = mf * 16 + lq;
                    dstU[r * PRU + cp] =
                        pack_h2(pacc[mf][nfi][0] + ex, pacc[mf][nfi][1] + ey);
                    dstU[(r + 8) * PRU + cp] =
                        pack_h2(pacc[mf][nfi][2] + ex, pacc[mf][nfi][3] + ey);
                }
            }
        }
        // ---- layernorm, parallel: 32 rows x 8 lanes ----
        {
            const int i = t >> 3, j = t & 7;
            float mu = 0.f, sq = 0.f;
            if (i < NN) {
                #pragma unroll
                for (int c = j; c < DD; c += 8) {
                    float v = zsh[i * ZROW + c];
                    mu += v; sq += v * v;
                }
            }
            mu += __shfl_xor_sync(0xffffffffu, mu, 1);
            mu += __shfl_xor_sync(0xffffffffu, mu, 2);
            mu += __shfl_xor_sync(0xffffffffu, mu, 4);
            sq += __shfl_xor_sync(0xffffffffu, sq, 1);
            sq += __shfl_xor_sync(0xffffffffu, sq, 2);
            sq += __shfl_xor_sync(0xffffffffu, sq, 4);
            mu *= (1.0f / DD);
            float var = sq * (1.0f / DD) - mu * mu;
            float rs = rsqrtf(var + 1e-5f);
            if (i < NN) {
                #pragma unroll
                for (int c = j; c < DD; c += 8)
                    znsh[i * ZROW + c] = (zsh[i * ZROW + c] - mu) * rs * lngl[c] + lnbl[c];
            }
        }
        __syncthreads();

        // ---- per-layer hoists: pj pairs + epilogue constants ----
        uint2 pj0q[4], pj1q[4];
        {
            const uint2* pj0p = (const uint2*)(pjU + r0 * PRU);
            const uint2* pj1p = (const uint2*)(pjU + r1 * PRU);
            #pragma unroll
            for (int kk = 0; kk < 4; ++kk) {
                pj0q[kk] = pj0p[kk * 4 + cq];
                pj1q[kk] = pj1p[kk * 4 + cq];
            }
        }
        uint32_t ebr[8], gwh[8];
        *(uint4*)(ebr)     = *(const uint4*)(ebhU + cq * 8);
        *(uint4*)(ebr + 4) = *(const uint4*)(ebhU + cq * 8 + 4);
        *(uint4*)(gwh)     = *(const uint4*)(gwhU + cq * 8);
        *(uint4*)(gwh + 4) = *(const uint4*)(gwhU + cq * 8 + 4);

        // ======== 7-8 edge tiles (fp16 MMA + packed epilogue) ========
        for (int ig = 0; ig < 8; ++ig) {
            const int node = ig * 4 + i_sel;
            if (node >= NN) continue;
            const uint2* pi2 = (const uint2*)(piU + node * PRU);

            float acc[8][4];
            #pragma unroll
            for (int nf = 0; nf < 8; ++nf)
                #pragma unroll
                for (int e = 0; e < 4; ++e) acc[nf][e] = 0.f;

            #pragma unroll
            for (int kk = 0; kk < 4; ++kk) {
                uint2 piq = pi2[kk * 4 + cq];
                uint32_t a0 = silu_h2(hadd2u(piq.x, pj0q[kk].x));
                uint32_t a1 = silu_h2(hadd2u(piq.x, pj1q[kk].x));
                uint32_t a2 = silu_h2(hadd2u(piq.y, pj0q[kk].y));
                uint32_t a3 = silu_h2(hadd2u(piq.y, pj1q[kk].y));
                const float* wb = w2h + (kk * 4 + cq) * W2HW + lq * 4;
                #pragma unroll
                for (int nf = 0; nf < 4; ++nf) {
                    float4 q = *(const float4*)(wb + nf * 32);
                    mma_f16(acc[nf],     a0, a1, a2, a3,
                            __float_as_uint(q.x), __float_as_uint(q.y));
                    mma_f16(acc[nf + 4], a0, a1, a2, a3,
                            __float_as_uint(q.z), __float_as_uint(q.w));
                }
            }

            // epilogue: f16x2 bias+silu, f16x2 gate dot
            uint32_t m01[8], m23[8];
            uint32_t gph0 = 0, gph1 = 0;
            #pragma unroll
            for (int nf = 0; nf < 8; ++nf) {
                uint32_t u01 = silu_h2(hadd2u(pack_h2(acc[nf][0], acc[nf][1]), ebr[nf]));
                uint32_t u23 = silu_h2(hadd2u(pack_h2(acc[nf][2], acc[nf][3]), ebr[nf]));
                m01[nf] = u01; m23[nf] = u23;
                gph0 = hfma2u(u01, gwh[nf], gph0);
                gph1 = hfma2u(u23, gwh[nf], gph1);
            }
            float2 gpf0 = h22f2(gph0), gpf1 = h22f2(gph1);
            float gp0 = gpf0.x + gpf0.y;
            float gp1 = gpf1.x + gpf1.y;
            gp0 += __shfl_xor_sync(0xffffffffu, gp0, 1);
            gp0 += __shfl_xor_sync(0xffffffffu, gp0, 2);
            gp1 += __shfl_xor_sync(0xffffffffu, gp1, 1);
            gp1 += __shfl_xor_sync(0xffffffffu, gp1, 2);
            float g0 = sigm_t(gp0 + gbl);
            float g1 = (r1 < NN) ? sigm_t(gp1 + gbl) : 0.f;
            uint32_t g0h = bcast_h2(g0), g1h = bcast_h2(g1);

            // gated 2-term combine + packed value-splitting reduction over lq
            uint32_t s8h[8];
            #pragma unroll
            for (int nf = 0; nf < 8; ++nf)
                s8h[nf] = hfma2u(m23[nf], g1h, hmul2u(m01[nf], g0h));

            const int bb0 = lq & 1, bb1 = (lq >> 1) & 1, bb2 = (lq >> 2) & 1;
            uint32_t v4h[4];
            #pragma unroll
            for (int j = 0; j < 4; ++j) {
                uint32_t keep = bb0 ? s8h[4 + j] : s8h[j];
                uint32_t send = bb0 ? s8h[j]     : s8h[4 + j];
                v4h[j] = hadd2u(keep, __shfl_xor_sync(0xffffffffu, send, 4));
            }
            uint32_t v2h[2];
            #pragma unroll
            for (int j = 0; j < 2; ++j) {
                uint32_t keep = bb1 ? v4h[2 + j] : v4h[j];
                uint32_t send = bb1 ? v4h[j]     : v4h[2 + j];
                v2h[j] = hadd2u(keep, __shfl_xor_sync(0xffffffffu, send, 8));
            }
            uint32_t v1h;
            {
                uint32_t keep = bb2 ? v2h[1] : v2h[0];
                uint32_t send = bb2 ? v2h[0] : v2h[1];
                v1h = hadd2u(keep, __shfl_xor_sync(0xffffffffu, send, 16));
            }
            const int nfv = bb0 * 4 + bb1 * 2 + bb2;
            maggU[jh * 1024 + node * MAGU + nfv * 4 + cq] = v1h;
        }
        __syncthreads();

        // ======== concat buffer (packed half2): [zn | m_i | 0-pad] ========
        for (int idx = t; idx < 32 * 32; idx += 256) {   // m_i pairs 11..42
            int i = idx >> 5, p = idx & 31;
            uint32_t v = 0;
            if (i < NN) v = hadd2u(maggU[i * MAGU + p], maggU[1024 + i * MAGU + p]);
            catshU[i * CATU + 11 + p] = v;
        }
        for (int idx = t; idx < 32 * 16; idx += 256) {   // zn pairs 0..10 + zero 43..47
            int i = idx >> 4, p = idx & 15;
            if (p < 11) {
                uint32_t v = 0;
                if (i < NN) v = pack_h2(znsh[i * ZROW + 2 * p], znsh[i * ZROW + 2 * p + 1]);
                catshU[i * CATU + p] = v;
            } else {
                catshU[i * CATU + 32 + p] = 0;           // pairs 43..47
            }
        }
        __syncthreads();

        // ======== node MLP layer 1 via f16 MMA: [32x88] @ [86x64] ========
        {
            const int mh  = w & 1;
            const int nh4 = w >> 1;
            const int row0 = mh * 16 + lq, row1 = row0 + 8;
            float c2[2][4];
            #pragma unroll
            for (int nfi = 0; nfi < 2; ++nfi)
                #pragma unroll
                for (int e = 0; e < 4; ++e) c2[nfi][e] = 0.f;

            #pragma unroll
            for (int kk = 0; kk < 5; ++kk) {
                uint32_t a0 = catshU[row0 * CATU + kk * 8 + cq];
                uint32_t a1 = catshU[row1 * CATU + kk * 8 + cq];
                uint32_t a2 = catshU[row0 * CATU + kk * 8 + cq + 4];
                uint32_t a3 = catshU[row1 * CATU + kk * 8 + cq + 4];
                const int k0 = kk * 16 + 2 * cq;
                #pragma unroll
                for (int nfi = 0; nfi < 2; ++nfi) {
                    const int col = (nh4 * 2 + nfi) * 8 + lq;
                    uint32_t b0 = pack_h2(__ldg(nW1l + k0 * HDIM + col),
                                          __ldg(nW1l + (k0 + 1) * HDIM + col));
                    uint32_t b1 = pack_h2(__ldg(nW1l + (k0 + 8) * HDIM + col),
                                          __ldg(nW1l + (k0 + 9) * HDIM + col));
                    mma_f16(c2[nfi], a0, a1, a2, a3, b0, b1);
                }
            }
            {   // K block 80-87 (k8); pair 43 = (k86,k87) staged 0; guard cq==3
                uint32_t a0 = catshU[row0 * CATU + 40 + cq];
                uint32_t a1 = catshU[row1 * CATU + 40 + cq];
                const int k0 = 80 + 2 * cq;
                #pragma unroll
                for (int nfi = 0; nfi < 2; ++nfi) {
                    const int col = (nh4 * 2 + nfi) * 8 + lq;
                    uint32_t b0 = (cq < 3)
                        ? pack_h2(__ldg(nW1l + k0 * HDIM + col),
                                  __ldg(nW1l + (k0 + 1) * HDIM + col)) : 0u;
                    mma_f16_k8(c2[nfi], a0, a1, b0);
                }
            }
            #pragma unroll
            for (int nfi = 0; nfi < 2; ++nfi) {
                const int colb = (nh4 * 2 + nfi) * 8 + 2 * cq;
                float2 nb = *(const float2*)(nb1l + colb);
                const int pid = colb >> 1;
                hbufU[row0 * HBU + pid] =
                    pack_h2(silu_t(c2[nfi][0] + nb.x), silu_t(c2[nfi][1] + nb.y));
                hbufU[row1 * HBU + pid] =
                    pack_h2(silu_t(c2[nfi][2] + nb.x), silu_t(c2[nfi][3] + nb.y));
            }
        }
        __syncthreads();

        // ======== node MLP layer 2 via f16 MMA: [32x64] @ [64x24] + residual ========
        if (w < 6) {
            const int mf = w & 1;
            const int nf = w >> 1;
            const int d0 = nf * 8 + lq;
            const int rr0 = mf * 16 + lq, rr1 = rr0 + 8;
            float c4[4] = {0.f, 0.f, 0.f, 0.f};
            #pragma unroll
            for (int kk = 0; kk < 4; ++kk) {
                uint32_t a0 = hbufU[rr0 * HBU + kk * 8 + cq];
                uint32_t a1 = hbufU[rr1 * HBU + kk * 8 + cq];
                uint32_t a2 = hbufU[rr0 * HBU + kk * 8 + cq + 4];
                uint32_t a3 = hbufU[rr1 * HBU + kk * 8 + cq + 4];
                const int k0 = kk * 16 + 2 * cq;
                uint32_t b0 = 0, b1 = 0;
                if (d0 < DD) {
                    b0 = pack_h2(__ldg(nW2l + k0 * DD + d0),
                                 __ldg(nW2l + (k0 + 1) * DD + d0));
                    b1 = pack_h2(__ldg(nW2l + (k0 + 8) * DD + d0),
                                 __ldg(nW2l + (k0 + 9) * DD + d0));
                }
                mma_f16(c4, a0, a1, a2, a3, b0, b1);
            }
            const int col = nf * 8 + 2 * cq;
            if (col < DD) {
                float nb = nb2l[col];
                if (rr0 < NN) zsh[rr0 * ZROW + col] += c4[0] + nb;
                if (rr1 < NN) zsh[rr1 * ZROW + col] += c4[2] + nb;
            }
            if (col + 1 < DD) {
                float nb = nb2l[col + 1];
                if (rr0 < NN) zsh[rr0 * ZROW + col + 1] += c4[1] + nb;
                if (rr1 < NN) zsh[rr1 * ZROW + col + 1] += c4[3] + nb;
            }
        }
        __syncthreads();
    }

    // ---- mean pool ----
    if (t < DD) {
        float s = 0.f;
        #pragma unroll
        for (int i = 0; i < NN; ++i) s += zsh[i * ZROW + t];
        znsh[t] = s * (1.0f / NN);
    }
    __syncthreads();

    // ---- head MLP (fp32 scratch in znsh+64) ----
    float* hscr = znsh + 64;
    if (t < HDIM) {
        float a = hb1[t];
        #pragma unroll
        for (int d = 0; d < DD; ++d) a += znsh[d] * hW1[d * HDIM + t];
        hscr[t] = fmaxf(a, 0.f);
    }
    __syncthreads();

    float* ob = out + (size_t)b * (NN * OUTROW);
    for (int idx = t; idx < NN * OUTROW; idx += 256) {
        float v = 0.f;
        if (idx < NOUT) {
            v = hb2[idx];
            #pragma unroll
            for (int m2 = 0; m2 < HDIM; ++m2)
                v += hscr[m2] * hW2[m2 * NOUT + idx];
        }
        ob[idx] = v;
    }
}

extern "C" void kernel_launch(void* const* d_in, const int* in_sizes, int n_in,
                              void* d_out, int out_size) {
    (void)in_sizes; (void)n_in; (void)out_size;
    const float* x    = (const float*)d_in[0];
    const float* ctx  = (const float*)d_in[1];
    const float* eW1  = (const float*)d_in[2];
    const float* eb1  = (const float*)d_in[3];
    const float* eW2  = (const float*)d_in[4];
    const float* eb2  = (const float*)d_in[5];
    const float* gW   = (const float*)d_in[6];
    const float* gb   = (const float*)d_in[7];
    const float* lng  = (const float*)d_in[8];
    const float* lnb  = (const float*)d_in[9];
    const float* nW1  = (const float*)d_in[10];
    const float* nb1  = (const float*)d_in[11];
    const float* nW2  = (const float*)d_in[12];
    const float* nb2  = (const float*)d_in[13];
    const float* hW1  = (const float*)d_in[14];
    const float* hb1  = (const float*)d_in[15];
    const float* hW2  = (const float*)d_in[16];
    const float* hb2  = (const float*)d_in[17];
    float* out = (float*)d_out;

    cudaFuncSetAttribute(gnn_kernel, cudaFuncAttributeMaxDynamicSharedMemorySize,
                         SMEM_FLOATS * sizeof(float));
    gnn_kernel<<<NB, 256, SMEM_FLOATS * sizeof(float)>>>(
        x, ctx, eW1, eb1, eW2, eb2, gW, gb, lng, lnb,
        nW1, nb1, nW2, nb2, hW1, hb1, hW2, hb2, out);
}

// round 13
// speedup vs baseline: 2.6291x; 1.0390x over previous
#include <cuda_runtime.h>
#include <cuda_fp16.h>
#include <cstdint>
#include <cstddef>

// Problem constants
#define NB   4096
#define NN   29
#define NC   6
#define CDIM 16
#define DD   22
#define HDIM 64
#define NL   2
#define NOUT 24
#define OUTROW 12
#define ZROW 25
#define PRU  40     // pi/pj row stride (uint32)
#define W2HW 136    // fp16 W2 row stride (floats)
#define ZTU  20     // ztU row stride (uint32 pairs)
#define CATU 52     // catshU row stride
#define HBU  36     // hbufU row stride
#define MAGU 32     // maggU row stride

// Shared memory layout (float offsets)
#define OFF_Z    0        // 800
#define OFF_ZN   800      // 800
#define OFF_PI   1600     // 1280 (piU)
#define OFF_PJ   2880     // 1280 (pjU)
#define OFF_W2H  4160     // 4352
#define OFF_ZT   8512     // 640 (ztU)
#define OFF_MAGG 9152     // 2048 (maggU)
#define OFF_H    11200    // 1152 (hbufU)
#define OFF_EBH  12352    // 32
#define OFF_GWH  12384    // 32
#define SMEM_FLOATS 12416 // 49664 bytes -> 4 CTAs/SM (198656 <= 227KB)
// catshU [32][52]=1664 uint aliases OFF_PI..

__device__ __forceinline__ float tanhfast(float x) {
    float y;
    asm("tanh.approx.f32 %0, %1;" : "=f"(y) : "f"(x));
    return y;
}
__device__ __forceinline__ float silu_t(float v) {
    float h = 0.5f * v;
    return fmaf(h, tanhfast(h), h);
}
__device__ __forceinline__ float sigm_t(float v) {
    return fmaf(0.5f, tanhfast(0.5f * v), 0.5f);
}
__device__ __forceinline__ uint32_t pack_h2(float lo, float hi) {
    __half2 h = __floats2half2_rn(lo, hi);
    return *(uint32_t*)&h;
}
__device__ __forceinline__ uint32_t hadd2u(uint32_t a, uint32_t b) {
    __half2 r = __hadd2(*(__half2*)&a, *(__half2*)&b);
    return *(uint32_t*)&r;
}
__device__ __forceinline__ uint32_t hfma2u(uint32_t a, uint32_t b, uint32_t c) {
    __half2 r = __hfma2(*(__half2*)&a, *(__half2*)&b, *(__half2*)&c);
    return *(uint32_t*)&r;
}
__device__ __forceinline__ uint32_t hmul2u(uint32_t a, uint32_t b) {
    __half2 r = __hmul2(*(__half2*)&a, *(__half2*)&b);
    return *(uint32_t*)&r;
}
__device__ __forceinline__ uint32_t silu_h2(uint32_t v) {
    __half2 h = __hmul2(*(__half2*)&v, __float2half2_rn(0.5f));
    uint32_t hu = *(uint32_t*)&h, tu;
    asm("tanh.approx.f16x2 %0, %1;" : "=r"(tu) : "r"(hu));
    __half2 r = __hfma2(h, *(__half2*)&tu, h);
    return *(uint32_t*)&r;
}
__device__ __forceinline__ float2 h22f2(uint32_t u) {
    return __half22float2(*(__half2*)&u);
}
__device__ __forceinline__ uint32_t bcast_h2(float v) {
    __half2 h = __float2half2_rn(v);
    return *(uint32_t*)&h;
}
__device__ __forceinline__ void mma_f16(float c[4], uint32_t a0, uint32_t a1,
                                        uint32_t a2, uint32_t a3,
                                        uint32_t b0, uint32_t b1) {
    asm volatile(
        "mma.sync.aligned.m16n8k16.row.col.f32.f16.f16.f32 "
        "{%0,%1,%2,%3}, {%4,%5,%6,%7}, {%8,%9}, {%0,%1,%2,%3};\n"
        : "+f"(c[0]), "+f"(c[1]), "+f"(c[2]), "+f"(c[3])
        : "r"(a0), "r"(a1), "r"(a2), "r"(a3), "r"(b0), "r"(b1));
}
__device__ __forceinline__ void mma_f16_k8(float c[4], uint32_t a0, uint32_t a1,
                                           uint32_t b0) {
    asm volatile(
        "mma.sync.aligned.m16n8k8.row.col.f32.f16.f16.f32 "
        "{%0,%1,%2,%3}, {%4,%5}, {%6}, {%0,%1,%2,%3};\n"
        : "+f"(c[0]), "+f"(c[1]), "+f"(c[2]), "+f"(c[3])
        : "r"(a0), "r"(a1), "r"(b0));
}

extern "C" __global__ void __launch_bounds__(256, 4)
gnn_kernel(const float* __restrict__ x,   const float* __restrict__ ctx,
           const float* __restrict__ eW1, const float* __restrict__ eb1,
           const float* __restrict__ eW2, const float* __restrict__ eb2,
           const float* __restrict__ gW,  const float* __restrict__ gb,
           const float* __restrict__ lng, const float* __restrict__ lnb,
           const float* __restrict__ nW1, const float* __restrict__ nb1,
           const float* __restrict__ nW2, const float* __restrict__ nb2,
           const float* __restrict__ hW1, const float* __restrict__ hb1,
           const float* __restrict__ hW2, const float* __restrict__ hb2,
           float* __restrict__ out)
{
    extern __shared__ float sh[];
    float*    zsh  = sh + OFF_Z;
    float*    znsh = sh + OFF_ZN;
    uint32_t* piU  = (uint32_t*)(sh + OFF_PI);
    uint32_t* pjU  = (uint32_t*)(sh + OFF_PJ);
    float*    w2h  = sh + OFF_W2H;
    uint32_t* ztU  = (uint32_t*)(sh + OFF_ZT);
    uint32_t* maggU = (uint32_t*)(sh + OFF_MAGG);
    uint32_t* hbufU = (uint32_t*)(sh + OFF_H);
    uint32_t* ebhU = (uint32_t*)(sh + OFF_EBH);
    uint32_t* gwhU = (uint32_t*)(sh + OFF_GWH);
    uint32_t* catshU = (uint32_t*)(sh + OFF_PI);

    const int b = blockIdx.x;
    const int t = threadIdx.x;
    const int w = t >> 5;
    const int lane = t & 31;
    const int lq = lane >> 2;
    const int cq = lane & 3;
    const int i_sel = w >> 1;
    const int jh = w & 1;
    const int r0 = jh * 16 + lq;
    const int r1 = r0 + 8;

    // ---- load z = concat(x, context) ----
    for (int idx = t; idx < NN * DD; idx += 256) {
        int i = idx / DD, d = idx - i * DD;
        float v = (d < NC) ? x[(b * NN + i) * NC + d]
                           : ctx[(b * NN + i) * CDIM + (d - NC)];
        zsh[i * ZROW + d] = v;
    }
    __syncthreads();

    for (int l = 0; l < NL; ++l) {
        const float* eW1l = eW1 + l * 2 * DD * HDIM;
        const float* eb1l = eb1 + l * HDIM;
        const float* eW2l = eW2 + l * HDIM * HDIM;
        const float* eb2l = eb2 + l * HDIM;
        const float* gWl  = gW  + l * HDIM;
        const float  gbl  = gb[l];
        const float* lngl = lng + l * DD;
        const float* lnbl = lnb + l * DD;
        const float* nW1l = nW1 + l * (DD + HDIM) * HDIM;
        const float* nb1l = nb1 + l * HDIM;
        const float* nW2l = nW2 + l * HDIM * DD;
        const float* nb2l = nb2 + l * DD;

        // ======== staging: w2h, ztU, ebh, gwh ========
        for (int e = t; e < 1024; e += 256) {
            int kp = e >> 5, c = e & 31;
            int kk = kp >> 2, cqv = kp & 3;
            int k0 = kk * 16 + 2 * cqv;
            float4 q;
            q.x = __uint_as_float(pack_h2(eW2l[k0 * 64 + c],        eW2l[(k0 + 1) * 64 + c]));
            q.y = __uint_as_float(pack_h2(eW2l[(k0 + 8) * 64 + c],  eW2l[(k0 + 9) * 64 + c]));
            q.z = __uint_as_float(pack_h2(eW2l[k0 * 64 + c + 32],   eW2l[(k0 + 1) * 64 + c + 32]));
            q.w = __uint_as_float(pack_h2(eW2l[(k0 + 8) * 64 + c + 32], eW2l[(k0 + 9) * 64 + c + 32]));
            *(float4*)(w2h + kp * W2HW + c * 4) = q;
        }
        for (int idx = t; idx < 32 * 16; idx += 256) {
            int i = idx >> 4, p = idx & 15;
            uint32_t v = 0;
            if (i < NN && p < 11)
                v = pack_h2(zsh[i * ZROW + 2 * p], zsh[i * ZROW + 2 * p + 1]);
            ztU[i * ZTU + p] = v;
        }
        if (t < 32) {
            int cqv = t >> 3, nf = t & 7;
            ebhU[cqv * 8 + nf] = pack_h2(eb2l[nf * 8 + 2 * cqv],
                                         eb2l[nf * 8 + 2 * cqv + 1]);
        }
        if (t >= 32 && t < 64) {
            int i = t - 32;
            int cqv = i >> 3, nf = i & 7;
            gwhU[cqv * 8 + nf] = pack_h2(gWl[nf * 8 + 2 * cqv],
                                         gWl[nf * 8 + 2 * cqv + 1]);
        }
        __syncthreads();

        // ======== projections via f16 MMA: [32x24] @ [22x128] -> piU|pjU ========
        {
            float pacc[2][2][4];
            #pragma unroll
            for (int mf = 0; mf < 2; ++mf)
                #pragma unroll
                for (int nfi = 0; nfi < 2; ++nfi)
                    #pragma unroll
                    for (int e = 0; e < 4; ++e) pacc[mf][nfi][e] = 0.f;

            const float* Wb = eW1l + ((w < 4) ? 0 : DD) * HDIM;
            {
                uint32_t aA[2][4];
                #pragma unroll
                for (int mf = 0; mf < 2; ++mf) {
                    int rb = mf * 16;
                    aA[mf][0] = ztU[(rb + lq) * ZTU + cq];
                    aA[mf][1] = ztU[(rb + lq + 8) * ZTU + cq];
                    aA[mf][2] = ztU[(rb + lq) * ZTU + cq + 4];
                    aA[mf][3] = ztU[(rb + lq + 8) * ZTU + cq + 4];
                }
                #pragma unroll
                for (int nfi = 0; nfi < 2; ++nfi) {
                    const int col = (w & 3) * 16 + nfi * 8 + lq;
                    uint32_t b0 = pack_h2(__ldg(Wb + (2 * cq) * HDIM + col),
                                          __ldg(Wb + (2 * cq + 1) * HDIM + col));
                    uint32_t b1 = pack_h2(__ldg(Wb + (2 * cq + 8) * HDIM + col),
                                          __ldg(Wb + (2 * cq + 9) * HDIM + col));
                    #pragma unroll
                    for (int mf = 0; mf < 2; ++mf)
                        mma_f16(pacc[mf][nfi], aA[mf][0], aA[mf][1],
                                aA[mf][2], aA[mf][3], b0, b1);
                }
            }
            {
                uint32_t aA[2][2];
                #pragma unroll
                for (int mf = 0; mf < 2; ++mf) {
                    int rb = mf * 16;
                    aA[mf][0] = ztU[(rb + lq) * ZTU + 8 + cq];
                    aA[mf][1] = ztU[(rb + lq + 8) * ZTU + 8 + cq];
                }
                #pragma unroll
                for (int nfi = 0; nfi < 2; ++nfi) {
                    const int col = (w & 3) * 16 + nfi * 8 + lq;
                    uint32_t b0 = (cq < 3)
                        ? pack_h2(__ldg(Wb + (16 + 2 * cq) * HDIM + col),
                                  __ldg(Wb + (17 + 2 * cq) * HDIM + col)) : 0u;
                    #pragma unroll
                    for (int mf = 0; mf < 2; ++mf)
                        mma_f16_k8(pacc[mf][nfi], aA[mf][0], aA[mf][1], b0);
                }
            }
            uint32_t* dstU = (w < 4) ? piU : pjU;
            #pragma unroll
            for (int nfi = 0; nfi < 2; ++nfi) {
                float ex = 0.f, ey = 0.f;
                if (w < 4) {
                    float2 e2 = *(const float2*)(eb1l + (w & 3) * 16 + nfi * 8 + 2 * cq);
                    ex = e2.x; ey = e2.y;
                }
                const int cp = (w & 3) * 8 + cq * 2 + nfi;
                #pragma unroll
                for (int mf = 0; mf < 2; ++mf) {
                    int r = mf * 16 + lq;
                    dstU[r * PRU + cp] =
                        pack_h2(pacc[mf][nfi][0] + ex, pacc[mf][nfi][1] + ey);
                    dstU[(r + 8) * PRU + cp] =
                        pack_h2(pacc[mf][nfi][2] + ex, pacc[mf][nfi][3] + ey);
                }
            }
        }
        // ---- layernorm, parallel: 32 rows x 8 lanes ----
        {
            const int i = t >> 3, j = t & 7;
            float mu = 0.f, sq = 0.f;
            if (i < NN) {
                #pragma unroll
                for (int c = j; c < DD; c += 8) {
                    float v = zsh[i * ZROW + c];
                    mu += v; sq += v * v;
                }
            }
            mu += __shfl_xor_sync(0xffffffffu, mu, 1);
            mu += __shfl_xor_sync(0xffffffffu, mu, 2);
            mu += __shfl_xor_sync(0xffffffffu, mu, 4);
            sq += __shfl_xor_sync(0xffffffffu, sq, 1);
            sq += __shfl_xor_sync(0xffffffffu, sq, 2);
            sq += __shfl_xor_sync(0xffffffffu, sq, 4);
            mu *= (1.0f / DD);
            float var = sq * (1.0f / DD) - mu * mu;
            float rs = rsqrtf(var + 1e-5f);
            if (i < NN) {
                #pragma unroll
                for (int c = j; c < DD; c += 8)
                    znsh[i * ZROW + c] = (zsh[i * ZROW + c] - mu) * rs * lngl[c] + lnbl[c];
            }
        }
        __syncthreads();

        // ---- per-layer hoist: pj pairs only (fit 64-reg budget) ----
        uint2 pj0q[4], pj1q[4];
        {
            const uint2* pj0p = (const uint2*)(pjU + r0 * PRU);
            const uint2* pj1p = (const uint2*)(pjU + r1 * PRU);
            #pragma unroll
            for (int kk = 0; kk < 4; ++kk) {
                pj0q[kk] = pj0p[kk * 4 + cq];
                pj1q[kk] = pj1p[kk * 4 + cq];
            }
        }

        // ======== edge tiles (fp16 MMA + packed epilogue) ========
        for (int ig = 0; ig < 8; ++ig) {
            const int node = ig * 4 + i_sel;
            if (node >= NN) continue;
            const uint2* pi2 = (const uint2*)(piU + node * PRU);

            float acc[8][4];
            #pragma unroll
            for (int nf = 0; nf < 8; ++nf)
                #pragma unroll
                for (int e = 0; e < 4; ++e) acc[nf][e] = 0.f;

            #pragma unroll
            for (int kk = 0; kk < 4; ++kk) {
                uint2 piq = pi2[kk * 4 + cq];
                uint32_t a0 = silu_h2(hadd2u(piq.x, pj0q[kk].x));
                uint32_t a1 = silu_h2(hadd2u(piq.x, pj1q[kk].x));
                uint32_t a2 = silu_h2(hadd2u(piq.y, pj0q[kk].y));
                uint32_t a3 = silu_h2(hadd2u(piq.y, pj1q[kk].y));
                const float* wb = w2h + (kk * 4 + cq) * W2HW + lq * 4;
                #pragma unroll
                for (int nf = 0; nf < 4; ++nf) {
                    float4 q = *(const float4*)(wb + nf * 32);
                    mma_f16(acc[nf],     a0, a1, a2, a3,
                            __float_as_uint(q.x), __float_as_uint(q.y));
                    mma_f16(acc[nf + 4], a0, a1, a2, a3,
                            __float_as_uint(q.z), __float_as_uint(q.w));
                }
            }

            // epilogue constants from SMEM (broadcast; trades regs for occupancy)
            uint32_t ebr[8], gwh[8];
            *(uint4*)(ebr)     = *(const uint4*)(ebhU + cq * 8);
            *(uint4*)(ebr + 4) = *(const uint4*)(ebhU + cq * 8 + 4);
            *(uint4*)(gwh)     = *(const uint4*)(gwhU + cq * 8);
            *(uint4*)(gwh + 4) = *(const uint4*)(gwhU + cq * 8 + 4);

            uint32_t m01[8], m23[8];
            uint32_t gph0 = 0, gph1 = 0;
            #pragma unroll
            for (int nf = 0; nf < 8; ++nf) {
                uint32_t u01 = silu_h2(hadd2u(pack_h2(acc[nf][0], acc[nf][1]), ebr[nf]));
                uint32_t u23 = silu_h2(hadd2u(pack_h2(acc[nf][2], acc[nf][3]), ebr[nf]));
                m01[nf] = u01; m23[nf] = u23;
                gph0 = hfma2u(u01, gwh[nf], gph0);
                gph1 = hfma2u(u23, gwh[nf], gph1);
            }
            float2 gpf0 = h22f2(gph0), gpf1 = h22f2(gph1);
            float gp0 = gpf0.x + gpf0.y;
            float gp1 = gpf1.x + gpf1.y;
            gp0 += __shfl_xor_sync(0xffffffffu, gp0, 1);
            gp0 += __shfl_xor_sync(0xffffffffu, gp0, 2);
            gp1 += __shfl_xor_sync(0xffffffffu, gp1, 1);
            gp1 += __shfl_xor_sync(0xffffffffu, gp1, 2);
            float g0 = sigm_t(gp0 + gbl);
            float g1 = (r1 < NN) ? sigm_t(gp1 + gbl) : 0.f;
            uint32_t g0h = bcast_h2(g0), g1h = bcast_h2(g1);

            uint32_t s8h[8];
            #pragma unroll
            for (int nf = 0; nf < 8; ++nf)
                s8h[nf] = hfma2u(m23[nf], g1h, hmul2u(m01[nf], g0h));

            const int bb0 = lq & 1, bb1 = (lq >> 1) & 1, bb2 = (lq >> 2) & 1;
            uint32_t v4h[4];
            #pragma unroll
            for (int j = 0; j < 4; ++j) {
                uint32_t keep = bb0 ? s8h[4 + j] : s8h[j];
                uint32_t send = bb0 ? s8h[j]     : s8h[4 + j];
                v4h[j] = hadd2u(keep, __shfl_xor_sync(0xffffffffu, send, 4));
            }
            uint32_t v2h[2];
            #pragma unroll
            for (int j = 0; j < 2; ++j) {
                uint32_t keep = bb1 ? v4h[2 + j] : v4h[j];
                uint32_t send = bb1 ? v4h[j]     : v4h[2 + j];
                v2h[j] = hadd2u(keep, __shfl_xor_sync(0xffffffffu, send, 8));
            }
            uint32_t v1h;
            {
                uint32_t keep = bb2 ? v2h[1] : v2h[0];
                uint32_t send = bb2 ? v2h[0] : v2h[1];
                v1h = hadd2u(keep, __shfl_xor_sync(0xffffffffu, send, 16));
            }
            const int nfv = bb0 * 4 + bb1 * 2 + bb2;
            maggU[jh * 1024 + node * MAGU + nfv * 4 + cq] = v1h;
        }
        __syncthreads();

        // ======== concat buffer (packed half2): [zn | m_i | 0-pad] ========
        for (int idx = t; idx < 32 * 32; idx += 256) {
            int i = idx >> 5, p = idx & 31;
            uint32_t v = 0;
            if (i < NN) v = hadd2u(maggU[i * MAGU + p], maggU[1024 + i * MAGU + p]);
            catshU[i * CATU + 11 + p] = v;
        }
        for (int idx = t; idx < 32 * 16; idx += 256) {
            int i = idx >> 4, p = idx & 15;
            if (p < 11) {
                uint32_t v = 0;
                if (i < NN) v = pack_h2(znsh[i * ZROW + 2 * p], znsh[i * ZROW + 2 * p + 1]);
                catshU[i * CATU + p] = v;
            } else {
                catshU[i * CATU + 32 + p] = 0;
            }
        }
        __syncthreads();

        // ======== node MLP layer 1 via f16 MMA: [32x88] @ [86x64] ========
        {
            const int mh  = w & 1;
            const int nh4 = w >> 1;
            const int row0 = mh * 16 + lq, row1 = row0 + 8;
            float c2[2][4];
            #pragma unroll
            for (int nfi = 0; nfi < 2; ++nfi)
                #pragma unroll
                for (int e = 0; e < 4; ++e) c2[nfi][e] = 0.f;

            #pragma unroll
            for (int kk = 0; kk < 5; ++kk) {
                uint32_t a0 = catshU[row0 * CATU + kk * 8 + cq];
                uint32_t a1 = catshU[row1 * CATU + kk * 8 + cq];
                uint32_t a2 = catshU[row0 * CATU + kk * 8 + cq + 4];
                uint32_t a3 = catshU[row1 * CATU + kk * 8 + cq + 4];
                const int k0 = kk * 16 + 2 * cq;
                #pragma unroll
                for (int nfi = 0; nfi < 2; ++nfi) {
                    const int col = (nh4 * 2 + nfi) * 8 + lq;
                    uint32_t b0 = pack_h2(__ldg(nW1l + k0 * HDIM + col),
                                          __ldg(nW1l + (k0 + 1) * HDIM + col));
                    uint32_t b1 = pack_h2(__ldg(nW1l + (k0 + 8) * HDIM + col),
                                          __ldg(nW1l + (k0 + 9) * HDIM + col));
                    mma_f16(c2[nfi], a0, a1, a2, a3, b0, b1);
                }
            }
            {
                uint32_t a0 = catshU[row0 * CATU + 40 + cq];
                uint32_t a1 = catshU[row1 * CATU + 40 + cq];
                const int k0 = 80 + 2 * cq;
                #pragma unroll
                for (int nfi = 0; nfi < 2; ++nfi) {
                    const int col = (nh4 * 2 + nfi) * 8 + lq;
                    uint32_t b0 = (cq < 3)
                        ? pack_h2(__ldg(nW1l + k0 * HDIM + col),
                                  __ldg(nW1l + (k0 + 1) * HDIM + col)) : 0u;
                    mma_f16_k8(c2[nfi], a0, a1, b0);
                }
            }
            #pragma unroll
            for (int nfi = 0; nfi < 2; ++nfi) {
                const int colb = (nh4 * 2 + nfi) * 8 + 2 * cq;
                float2 nb = *(const float2*)(nb1l + colb);
                const int pid = colb >> 1;
                hbufU[row0 * HBU + pid] =
                    pack_h2(silu_t(c2[nfi][0] + nb.x), silu_t(c2[nfi][1] + nb.y));
                hbufU[row1 * HBU + pid] =
                    pack_h2(silu_t(c2[nfi][2] + nb.x), silu_t(c2[nfi][3] + nb.y));
            }
        }
        __syncthreads();

        // ======== node MLP layer 2 via f16 MMA: [32x64] @ [64x24] + residual ========
        if (w < 6) {
            const int mf = w & 1;
            const int nf = w >> 1;
            const int d0 = nf * 8 + lq;
            const int rr0 = mf * 16 + lq, rr1 = rr0 + 8;
            float c4[4] = {0.f, 0.f, 0.f, 0.f};
            #pragma unroll
            for (int kk = 0; kk < 4; ++kk) {
                uint32_t a0 = hbufU[rr0 * HBU + kk * 8 + cq];
                uint32_t a1 = hbufU[rr1 * HBU + kk * 8 + cq];
                uint32_t a2 = hbufU[rr0 * HBU + kk * 8 + cq + 4];
                uint32_t a3 = hbufU[rr1 * HBU + kk * 8 + cq + 4];
                const int k0 = kk * 16 + 2 * cq;
                uint32_t b0 = 0, b1 = 0;
                if (d0 < DD) {
                    b0 = pack_h2(__ldg(nW2l + k0 * DD + d0),
                                 __ldg(nW2l + (k0 + 1) * DD + d0));
                    b1 = pack_h2(__ldg(nW2l + (k0 + 8) * DD + d0),
                                 __ldg(nW2l + (k0 + 9) * DD + d0));
                }
                mma_f16(c4, a0, a1, a2, a3, b0, b1);
            }
            const int col = nf * 8 + 2 * cq;
            if (col < DD) {
                float nb = nb2l[col];
                if (rr0 < NN) zsh[rr0 * ZROW + col] += c4[0] + nb;
                if (rr1 < NN) zsh[rr1 * ZROW + col] += c4[2] + nb;
            }
            if (col + 1 < DD) {
                float nb = nb2l[col + 1];
                if (rr0 < NN) zsh[rr0 * ZROW + col + 1] += c4[1] + nb;
                if (rr1 < NN) zsh[rr1 * ZROW + col + 1] += c4[3] + nb;
            }
        }
        __syncthreads();
    }

    // ---- mean pool ----
    if (t < DD) {
        float s = 0.f;
        #pragma unroll
        for (int i = 0; i < NN; ++i) s += zsh[i * ZROW + t];
        znsh[t] = s * (1.0f / NN);
    }
    __syncthreads();

    // ---- head MLP ----
    float* hscr = znsh + 64;
    if (t < HDIM) {
        float a = hb1[t];
        #pragma unroll
        for (int d = 0; d < DD; ++d) a += znsh[d] * hW1[d * HDIM + t];
        hscr[t] = fmaxf(a, 0.f);
    }
    __syncthreads();

    float* ob = out + (size_t)b * (NN * OUTROW);
    for (int idx = t; idx < NN * OUTROW; idx += 256) {
        float v = 0.f;
        if (idx < NOUT) {
            v = hb2[idx];
            #pragma unroll
            for (int m2 = 0; m2 < HDIM; ++m2)
                v += hscr[m2] * hW2[m2 * NOUT + idx];
        }
        ob[idx] = v;
    }
}

extern "C" void kernel_launch(void* const* d_in, const int* in_sizes, int n_in,
                              void* d_out, int out_size) {
    (void)in_sizes; (void)n_in; (void)out_size;
    const float* x    = (const float*)d_in[0];
    const float* ctx  = (const float*)d_in[1];
    const float* eW1  = (const float*)d_in[2];
    const float* eb1  = (const float*)d_in[3];
    const float* eW2  = (const float*)d_in[4];
    const float* eb2  = (const float*)d_in[5];
    const float* gW   = (const float*)d_in[6];
    const float* gb   = (const float*)d_in[7];
    const float* lng  = (const float*)d_in[8];
    const float* lnb  = (const float*)d_in[9];
    const float* nW1  = (const float*)d_in[10];
    const float* nb1  = (const float*)d_in[11];
    const float* nW2  = (const float*)d_in[12];
    const float* nb2  = (const float*)d_in[13];
    const float* hW1  = (const float*)d_in[14];
    const float* hb1  = (const float*)d_in[15];
    const float* hW2  = (const float*)d_in[16];
    const float* hb2  = (const float*)d_in[17];
    float* out = (float*)d_out;

    cudaFuncSetAttribute(gnn_kernel, cudaFuncAttributeMaxDynamicSharedMemorySize,
                         SMEM_FLOATS * sizeof(float));
    gnn_kernel<<<NB, 256, SMEM_FLOATS * sizeof(float)>>>(
        x, ctx, eW1, eb1, eW2, eb2, gW, gb, lng, lnb,
        nW1, nb1, nW2, nb2, hW1, hb1, hW2, hb2, out);
}

// round 14
// speedup vs baseline: 2.8005x; 1.0652x over previous
#include <cuda_runtime.h>
#include <cuda_fp16.h>
#include <cstdint>
#include <cstddef>

// Problem constants
#define NB   4096
#define NN   29
#define NC   6
#define CDIM 16
#define DD   22
#define HDIM 64
#define NL   2
#define NOUT 24
#define OUTROW 12
#define ZROW 25
#define PRU  40     // pi/pj row stride (uint32)
#define W2HW 136    // W2 smem row stride (uint32)
#define ZTU  20     // ztU row stride
#define CATU 52     // catshU row stride
#define HBU  36     // hbufU row stride
#define MAGU 32     // maggU row stride

// Shared memory layout (float offsets)
#define OFF_Z    0        // 800
#define OFF_ZN   800      // 800
#define OFF_PI   1600     // 1280
#define OFF_PJ   2880     // 1280
#define OFF_W2H  4160     // 4352
#define OFF_ZT   8512     // 640
#define OFF_MAGG 9152     // 2048
#define OFF_H    11200    // 1152
#define OFF_EBH  12352    // 32
#define OFF_GWH  12384    // 32
#define SMEM_FLOATS 12416 // 49664 bytes -> 4 CTAs/SM

// Prepacked fp16 weights (device scratch; filled by prep_pack each launch)
__device__ uint32_t g_eW1p[NL * 2 * 12 * 64];  // [l][half][kpair 12][c64], zero-padded
__device__ uint32_t g_eW2p[NL * 32 * 64];      // [l][kpair 32][c64]
__device__ uint32_t g_nW1p[NL * 44 * 64];      // [l][kpair 44][c64], zero-padded
__device__ uint32_t g_nW2p[NL * 32 * 24];      // [l][kpair 32][d24], zero-padded

__device__ __forceinline__ float tanhfast(float x) {
    float y;
    asm("tanh.approx.f32 %0, %1;" : "=f"(y) : "f"(x));
    return y;
}
__device__ __forceinline__ float silu_t(float v) {
    float h = 0.5f * v;
    return fmaf(h, tanhfast(h), h);
}
__device__ __forceinline__ float sigm_t(float v) {
    return fmaf(0.5f, tanhfast(0.5f * v), 0.5f);
}
__device__ __forceinline__ uint32_t pack_h2(float lo, float hi) {
    __half2 h = __floats2half2_rn(lo, hi);
    return *(uint32_t*)&h;
}
__device__ __forceinline__ uint32_t hadd2u(uint32_t a, uint32_t b) {
    __half2 r = __hadd2(*(__half2*)&a, *(__half2*)&b);
    return *(uint32_t*)&r;
}
__device__ __forceinline__ uint32_t hfma2u(uint32_t a, uint32_t b, uint32_t c) {
    __half2 r = __hfma2(*(__half2*)&a, *(__half2*)&b, *(__half2*)&c);
    return *(uint32_t*)&r;
}
__device__ __forceinline__ uint32_t hmul2u(uint32_t a, uint32_t b) {
    __half2 r = __hmul2(*(__half2*)&a, *(__half2*)&b);
    return *(uint32_t*)&r;
}
// silu(2h) given h: h + h*tanh(h)
__device__ __forceinline__ uint32_t silu_from_h(uint32_t h) {
    uint32_t tu;
    asm("tanh.approx.f16x2 %0, %1;" : "=r"(tu) : "r"(h));
    return hfma2u(h, tu, h);
}
__device__ __forceinline__ float2 h22f2(uint32_t u) {
    return __half22float2(*(__half2*)&u);
}
__device__ __forceinline__ uint32_t bcast_h2(float v) {
    __half2 h = __float2half2_rn(v);
    return *(uint32_t*)&h;
}
__device__ __forceinline__ void mma_f16(float c[4], uint32_t a0, uint32_t a1,
                                        uint32_t a2, uint32_t a3,
                                        uint32_t b0, uint32_t b1) {
    asm volatile(
        "mma.sync.aligned.m16n8k16.row.col.f32.f16.f16.f32 "
        "{%0,%1,%2,%3}, {%4,%5,%6,%7}, {%8,%9}, {%0,%1,%2,%3};\n"
        : "+f"(c[0]), "+f"(c[1]), "+f"(c[2]), "+f"(c[3])
        : "r"(a0), "r"(a1), "r"(a2), "r"(a3), "r"(b0), "r"(b1));
}
__device__ __forceinline__ void mma_f16_k8(float c[4], uint32_t a0, uint32_t a1,
                                           uint32_t b0) {
    asm volatile(
        "mma.sync.aligned.m16n8k8.row.col.f32.f16.f16.f32 "
        "{%0,%1,%2,%3}, {%4,%5}, {%6}, {%0,%1,%2,%3};\n"
        : "+f"(c[0]), "+f"(c[1]), "+f"(c[2]), "+f"(c[3])
        : "r"(a0), "r"(a1), "r"(b0));
}

// ---- prep: pack weights to half2 once per launch ----
extern "C" __global__ void prep_pack(const float* __restrict__ eW1,
                                     const float* __restrict__ eW2,
                                     const float* __restrict__ nW1,
                                     const float* __restrict__ nW2) {
    int tid = blockIdx.x * blockDim.x + threadIdx.x;
    int stride = gridDim.x * blockDim.x;
    for (int i = tid; i < NL * 2 * 12 * 64; i += stride) {
        int c = i & 63;
        int p = (i >> 6) % 12;
        int h = ((i >> 6) / 12) & 1;
        int l = (i >> 6) / 24;
        int k0 = 2 * p;
        float v0 = (k0 < DD)     ? eW1[(l * 2 * DD + h * DD + k0) * HDIM + c] : 0.f;
        float v1 = (k0 + 1 < DD) ? eW1[(l * 2 * DD + h * DD + k0 + 1) * HDIM + c] : 0.f;
        g_eW1p[i] = pack_h2(v0, v1);
    }
    for (int i = tid; i < NL * 32 * 64; i += stride) {
        int c = i & 63;
        int p = (i >> 6) & 31;
        int l = i >> 11;
        g_eW2p[i] = pack_h2(eW2[(l * HDIM + 2 * p) * HDIM + c],
                            eW2[(l * HDIM + 2 * p + 1) * HDIM + c]);
    }
    for (int i = tid; i < NL * 44 * 64; i += stride) {
        int c = i & 63;
        int p = (i >> 6) % 44;
        int l = (i >> 6) / 44;
        int k0 = 2 * p;
        const int KT = DD + HDIM;
        float v0 = (k0 < KT)     ? nW1[(l * KT + k0) * HDIM + c] : 0.f;
        float v1 = (k0 + 1 < KT) ? nW1[(l * KT + k0 + 1) * HDIM + c] : 0.f;
        g_nW1p[i] = pack_h2(v0, v1);
    }
    for (int i = tid; i < NL * 32 * 24; i += stride) {
        int d = i % 24;
        int p = (i / 24) & 31;
        int l = i / (32 * 24);
        float v0 = (d < DD) ? nW2[(l * HDIM + 2 * p) * DD + d] : 0.f;
        float v1 = (d < DD) ? nW2[(l * HDIM + 2 * p + 1) * DD + d] : 0.f;
        g_nW2p[i] = pack_h2(v0, v1);
    }
}

extern "C" __global__ void __launch_bounds__(256, 4)
gnn_kernel(const float* __restrict__ x,   const float* __restrict__ ctx,
           const float* __restrict__ eb1, const float* __restrict__ eb2,
           const float* __restrict__ gW,  const float* __restrict__ gb,
           const float* __restrict__ lng, const float* __restrict__ lnb,
           const float* __restrict__ nb1, const float* __restrict__ nb2,
           const float* __restrict__ hW1, const float* __restrict__ hb1,
           const float* __restrict__ hW2, const float* __restrict__ hb2,
           float* __restrict__ out)
{
    extern __shared__ float sh[];
    float*    zsh  = sh + OFF_Z;
    float*    znsh = sh + OFF_ZN;
    uint32_t* piU  = (uint32_t*)(sh + OFF_PI);
    uint32_t* pjU  = (uint32_t*)(sh + OFF_PJ);
    uint32_t* w2hU = (uint32_t*)(sh + OFF_W2H);
    uint32_t* ztU  = (uint32_t*)(sh + OFF_ZT);
    uint32_t* maggU = (uint32_t*)(sh + OFF_MAGG);
    uint32_t* hbufU = (uint32_t*)(sh + OFF_H);
    uint32_t* ebhU = (uint32_t*)(sh + OFF_EBH);
    uint32_t* gwhU = (uint32_t*)(sh + OFF_GWH);
    uint32_t* catshU = (uint32_t*)(sh + OFF_PI);

    const int b = blockIdx.x;
    const int t = threadIdx.x;
    const int w = t >> 5;
    const int lane = t & 31;
    const int lq = lane >> 2;
    const int cq = lane & 3;
    const int i_sel = w >> 1;
    const int jh = w & 1;
    const int r0 = jh * 16 + lq;
    const int r1 = r0 + 8;

    // ---- load z = concat(x, context) ----
    for (int idx = t; idx < NN * DD; idx += 256) {
        int i = idx / DD, d = idx - i * DD;
        float v = (d < NC) ? x[(b * NN + i) * NC + d]
                           : ctx[(b * NN + i) * CDIM + (d - NC)];
        zsh[i * ZROW + d] = v;
    }
    __syncthreads();

    for (int l = 0; l < NL; ++l) {
        const float* eb1l = eb1 + l * HDIM;
        const float* eb2l = eb2 + l * HDIM;
        const float* gWl  = gW  + l * HDIM;
        const float  gbl  = gb[l];
        const float* lngl = lng + l * DD;
        const float* lnbl = lnb + l * DD;
        const float* nb1l = nb1 + l * HDIM;
        const float* nb2l = nb2 + l * DD;
        const uint32_t* eW2p = g_eW2p + l * 2048;
        const uint32_t* nW1p = g_nW1p + l * (44 * 64);
        const uint32_t* nW2p = g_nW2p + l * (32 * 24);

        // ======== staging: w2h (from prepacked), ztU, ebh(*0.5), gwh ========
        for (int e = t; e < 1024; e += 256) {
            int kp = e >> 5, c = e & 31;
            int kk = kp >> 2, cqv = kp & 3;
            int p = kk * 8 + cqv;
            uint4 q;
            q.x = eW2p[p * 64 + c];
            q.y = eW2p[(p + 4) * 64 + c];
            q.z = eW2p[p * 64 + c + 32];
            q.w = eW2p[(p + 4) * 64 + c + 32];
            *(uint4*)(w2hU + kp * W2HW + c * 4) = q;
        }
        for (int idx = t; idx < 32 * 16; idx += 256) {
            int i = idx >> 4, p = idx & 15;
            uint32_t v = 0;
            if (i < NN && p < 11)
                v = pack_h2(zsh[i * ZROW + 2 * p], zsh[i * ZROW + 2 * p + 1]);
            ztU[i * ZTU + p] = v;
        }
        if (t < 32) {
            int cqv = t >> 3, nf = t & 7;
            ebhU[cqv * 8 + nf] = pack_h2(0.5f * eb2l[nf * 8 + 2 * cqv],
                                         0.5f * eb2l[nf * 8 + 2 * cqv + 1]);
        }
        if (t >= 32 && t < 64) {
            int i = t - 32;
            int cqv = i >> 3, nf = i & 7;
            gwhU[cqv * 8 + nf] = pack_h2(gWl[nf * 8 + 2 * cqv],
                                         gWl[nf * 8 + 2 * cqv + 1]);
        }
        __syncthreads();

        // ======== projections via f16 MMA -> piU|pjU (pre-halved) ========
        {
            float pacc[2][2][4];
            #pragma unroll
            for (int mf = 0; mf < 2; ++mf)
                #pragma unroll
                for (int nfi = 0; nfi < 2; ++nfi)
                    #pragma unroll
                    for (int e = 0; e < 4; ++e) pacc[mf][nfi][e] = 0.f;

            const uint32_t* Wp = g_eW1p + (l * 2 + ((w < 4) ? 0 : 1)) * (12 * 64);
            {
                uint32_t aA[2][4];
                #pragma unroll
                for (int mf = 0; mf < 2; ++mf) {
                    int rb = mf * 16;
                    aA[mf][0] = ztU[(rb + lq) * ZTU + cq];
                    aA[mf][1] = ztU[(rb + lq + 8) * ZTU + cq];
                    aA[mf][2] = ztU[(rb + lq) * ZTU + cq + 4];
                    aA[mf][3] = ztU[(rb + lq + 8) * ZTU + cq + 4];
                }
                #pragma unroll
                for (int nfi = 0; nfi < 2; ++nfi) {
                    const int col = (w & 3) * 16 + nfi * 8 + lq;
                    uint32_t b0 = Wp[cq * 64 + col];
                    uint32_t b1 = Wp[(cq + 4) * 64 + col];
                    #pragma unroll
                    for (int mf = 0; mf < 2; ++mf)
                        mma_f16(pacc[mf][nfi], aA[mf][0], aA[mf][1],
                                aA[mf][2], aA[mf][3], b0, b1);
                }
            }
            {
                uint32_t aA[2][2];
                #pragma unroll
                for (int mf = 0; mf < 2; ++mf) {
                    int rb = mf * 16;
                    aA[mf][0] = ztU[(rb + lq) * ZTU + 8 + cq];
                    aA[mf][1] = ztU[(rb + lq + 8) * ZTU + 8 + cq];
                }
                #pragma unroll
                for (int nfi = 0; nfi < 2; ++nfi) {
                    const int col = (w & 3) * 16 + nfi * 8 + lq;
                    uint32_t b0 = Wp[(8 + cq) * 64 + col];   // pair 11 zero-padded
                    #pragma unroll
                    for (int mf = 0; mf < 2; ++mf)
                        mma_f16_k8(pacc[mf][nfi], aA[mf][0], aA[mf][1], b0);
                }
            }
            uint32_t* dstU = (w < 4) ? piU : pjU;
            #pragma unroll
            for (int nfi = 0; nfi < 2; ++nfi) {
                float ex = 0.f, ey = 0.f;
                if (w < 4) {
                    float2 e2 = *(const float2*)(eb1l + (w & 3) * 16 + nfi * 8 + 2 * cq);
                    ex = e2.x; ey = e2.y;
                }
                const int cp = (w & 3) * 8 + cq * 2 + nfi;
                #pragma unroll
                for (int mf = 0; mf < 2; ++mf) {
                    int r = mf * 16 + lq;
                    dstU[r * PRU + cp] =
                        pack_h2((pacc[mf][nfi][0] + ex) * 0.5f,
                                (pacc[mf][nfi][1] + ey) * 0.5f);
                    dstU[(r + 8) * PRU + cp] =
                        pack_h2((pacc[mf][nfi][2] + ex) * 0.5f,
                                (pacc[mf][nfi][3] + ey) * 0.5f);
                }
            }
        }
        // ---- layernorm, parallel: 32 rows x 8 lanes ----
        {
            const int i = t >> 3, j = t & 7;
            float mu = 0.f, sq = 0.f;
            if (i < NN) {
                #pragma unroll
                for (int c = j; c < DD; c += 8) {
                    float v = zsh[i * ZROW + c];
                    mu += v; sq += v * v;
                }
            }
            mu += __shfl_xor_sync(0xffffffffu, mu, 1);
            mu += __shfl_xor_sync(0xffffffffu, mu, 2);
            mu += __shfl_xor_sync(0xffffffffu, mu, 4);
            sq += __shfl_xor_sync(0xffffffffu, sq, 1);
            sq += __shfl_xor_sync(0xffffffffu, sq, 2);
            sq += __shfl_xor_sync(0xffffffffu, sq, 4);
            mu *= (1.0f / DD);
            float var = sq * (1.0f / DD) - mu * mu;
            float rs = rsqrtf(var + 1e-5f);
            if (i < NN) {
                #pragma unroll
                for (int c = j; c < DD; c += 8)
                    znsh[i * ZROW + c] = (zsh[i * ZROW + c] - mu) * rs * lngl[c] + lnbl[c];
            }
        }
        __syncthreads();

        // ---- per-layer hoist: pj pairs ----
        uint2 pj0q[4], pj1q[4];
        {
            const uint2* pj0p = (const uint2*)(pjU + r0 * PRU);
            const uint2* pj1p = (const uint2*)(pjU + r1 * PRU);
            #pragma unroll
            for (int kk = 0; kk < 4; ++kk) {
                pj0q[kk] = pj0p[kk * 4 + cq];
                pj1q[kk] = pj1p[kk * 4 + cq];
            }
        }
        const uint32_t half05 = bcast_h2(0.5f);

        // ======== edge tiles (fp16 MMA + packed epilogue) ========
        for (int ig = 0; ig < 8; ++ig) {
            const int node = ig * 4 + i_sel;
            if (node >= NN) continue;
            const uint2* pi2 = (const uint2*)(piU + node * PRU);

            float acc[8][4];
            #pragma unroll
            for (int nf = 0; nf < 8; ++nf)
                #pragma unroll
                for (int e = 0; e < 4; ++e) acc[nf][e] = 0.f;

            #pragma unroll
            for (int kk = 0; kk < 4; ++kk) {
                uint2 piq = pi2[kk * 4 + cq];
                uint32_t a0 = silu_from_h(hadd2u(piq.x, pj0q[kk].x));
                uint32_t a1 = silu_from_h(hadd2u(piq.x, pj1q[kk].x));
                uint32_t a2 = silu_from_h(hadd2u(piq.y, pj0q[kk].y));
                uint32_t a3 = silu_from_h(hadd2u(piq.y, pj1q[kk].y));
                const uint32_t* wb = w2hU + (kk * 4 + cq) * W2HW + lq * 4;
                #pragma unroll
                for (int nf = 0; nf < 4; ++nf) {
                    uint4 q = *(const uint4*)(wb + nf * 32);
                    mma_f16(acc[nf],     a0, a1, a2, a3, q.x, q.y);
                    mma_f16(acc[nf + 4], a0, a1, a2, a3, q.z, q.w);
                }
            }

            uint32_t ebr[8], gwh[8];
            *(uint4*)(ebr)     = *(const uint4*)(ebhU + cq * 8);
            *(uint4*)(ebr + 4) = *(const uint4*)(ebhU + cq * 8 + 4);
            *(uint4*)(gwh)     = *(const uint4*)(gwhU + cq * 8);
            *(uint4*)(gwh + 4) = *(const uint4*)(gwhU + cq * 8 + 4);

            uint32_t m01[8], m23[8];
            uint32_t gph0 = 0, gph1 = 0;
            #pragma unroll
            for (int nf = 0; nf < 8; ++nf) {
                uint32_t h01 = hfma2u(pack_h2(acc[nf][0], acc[nf][1]), half05, ebr[nf]);
                uint32_t h23 = hfma2u(pack_h2(acc[nf][2], acc[nf][3]), half05, ebr[nf]);
                uint32_t u01 = silu_from_h(h01);
                uint32_t u23 = silu_from_h(h23);
                m01[nf] = u01; m23[nf] = u23;
                gph0 = hfma2u(u01, gwh[nf], gph0);
                gph1 = hfma2u(u23, gwh[nf], gph1);
            }
            float2 gpf0 = h22f2(gph0), gpf1 = h22f2(gph1);
            float gp0 = gpf0.x + gpf0.y;
            float gp1 = gpf1.x + gpf1.y;
            gp0 += __shfl_xor_sync(0xffffffffu, gp0, 1);
            gp0 += __shfl_xor_sync(0xffffffffu, gp0, 2);
            gp1 += __shfl_xor_sync(0xffffffffu, gp1, 1);
            gp1 += __shfl_xor_sync(0xffffffffu, gp1, 2);
            float g0 = sigm_t(gp0 + gbl);
            float g1 = (r1 < NN) ? sigm_t(gp1 + gbl) : 0.f;
            uint32_t g0h = bcast_h2(g0), g1h = bcast_h2(g1);

            uint32_t s8h[8];
            #pragma unroll
            for (int nf = 0; nf < 8; ++nf)
                s8h[nf] = hfma2u(m23[nf], g1h, hmul2u(m01[nf], g0h));

            const int bb0 = lq & 1, bb1 = (lq >> 1) & 1, bb2 = (lq >> 2) & 1;
            uint32_t v4h[4];
            #pragma unroll
            for (int j = 0; j < 4; ++j) {
                uint32_t keep = bb0 ? s8h[4 + j] : s8h[j];
                uint32_t send = bb0 ? s8h[j]     : s8h[4 + j];
                v4h[j] = hadd2u(keep, __shfl_xor_sync(0xffffffffu, send, 4));
            }
            uint32_t v2h[2];
            #pragma unroll
            for (int j = 0; j < 2; ++j) {
                uint32_t keep = bb1 ? v4h[2 + j] : v4h[j];
                uint32_t send = bb1 ? v4h[j]     : v4h[2 + j];
                v2h[j] = hadd2u(keep, __shfl_xor_sync(0xffffffffu, send, 8));
            }
            uint32_t v1h;
            {
                uint32_t keep = bb2 ? v2h[1] : v2h[0];
                uint32_t send = bb2 ? v2h[0] : v2h[1];
                v1h = hadd2u(keep, __shfl_xor_sync(0xffffffffu, send, 16));
            }
            const int nfv = bb0 * 4 + bb1 * 2 + bb2;
            maggU[jh * 1024 + node * MAGU + nfv * 4 + cq] = v1h;
        }
        __syncthreads();

        // ======== concat buffer (packed half2): [zn | m_i | 0-pad] ========
        for (int idx = t; idx < 32 * 32; idx += 256) {
            int i = idx >> 5, p = idx & 31;
            uint32_t v = 0;
            if (i < NN) v = hadd2u(maggU[i * MAGU + p], maggU[1024 + i * MAGU + p]);
            catshU[i * CATU + 11 + p] = v;
        }
        for (int idx = t; idx < 32 * 16; idx += 256) {
            int i = idx >> 4, p = idx & 15;
            if (p < 11) {
                uint32_t v = 0;
                if (i < NN) v = pack_h2(znsh[i * ZROW + 2 * p], znsh[i * ZROW + 2 * p + 1]);
                catshU[i * CATU + p] = v;
            } else {
                catshU[i * CATU + 32 + p] = 0;
            }
        }
        __syncthreads();

        // ======== node MLP layer 1 via f16 MMA: [32x88] @ [86x64] ========
        {
            const int mh  = w & 1;
            const int nh4 = w >> 1;
            const int row0 = mh * 16 + lq, row1 = row0 + 8;
            float c2[2][4];
            #pragma unroll
            for (int nfi = 0; nfi < 2; ++nfi)
                #pragma unroll
                for (int e = 0; e < 4; ++e) c2[nfi][e] = 0.f;

            #pragma unroll
            for (int kk = 0; kk < 5; ++kk) {
                uint32_t a0 = catshU[row0 * CATU + kk * 8 + cq];
                uint32_t a1 = catshU[row1 * CATU + kk * 8 + cq];
                uint32_t a2 = catshU[row0 * CATU + kk * 8 + cq + 4];
                uint32_t a3 = catshU[row1 * CATU + kk * 8 + cq + 4];
                #pragma unroll
                for (int nfi = 0; nfi < 2; ++nfi) {
                    const int col = (nh4 * 2 + nfi) * 8 + lq;
                    uint32_t b0 = nW1p[(kk * 8 + cq) * 64 + col];
                    uint32_t b1 = nW1p[(kk * 8 + cq + 4) * 64 + col];
                    mma_f16(c2[nfi], a0, a1, a2, a3, b0, b1);
                }
            }
            {
                uint32_t a0 = catshU[row0 * CATU + 40 + cq];
                uint32_t a1 = catshU[row1 * CATU + 40 + cq];
                #pragma unroll
                for (int nfi = 0; nfi < 2; ++nfi) {
                    const int col = (nh4 * 2 + nfi) * 8 + lq;
                    uint32_t b0 = nW1p[(40 + cq) * 64 + col];   // pair 43 zero-padded
                    mma_f16_k8(c2[nfi], a0, a1, b0);
                }
            }
            #pragma unroll
            for (int nfi = 0; nfi < 2; ++nfi) {
                const int colb = (nh4 * 2 + nfi) * 8 + 2 * cq;
                float2 nb = *(const float2*)(nb1l + colb);
                const int pid = colb >> 1;
                hbufU[row0 * HBU + pid] =
                    pack_h2(silu_t(c2[nfi][0] + nb.x), silu_t(c2[nfi][1] + nb.y));
                hbufU[row1 * HBU + pid] =
                    pack_h2(silu_t(c2[nfi][2] + nb.x), silu_t(c2[nfi][3] + nb.y));
            }
        }
        __syncthreads();

        // ======== node MLP layer 2 via f16 MMA: [32x64] @ [64x24] + residual ========
        if (w < 6) {
            const int mf = w & 1;
            const int nf = w >> 1;
            const int d0 = nf * 8 + lq;
            const int rr0 = mf * 16 + lq, rr1 = rr0 + 8;
            float c4[4] = {0.f, 0.f, 0.f, 0.f};
            #pragma unroll
            for (int kk = 0; kk < 4; ++kk) {
                uint32_t a0 = hbufU[rr0 * HBU + kk * 8 + cq];
                uint32_t a1 = hbufU[rr1 * HBU + kk * 8 + cq];
                uint32_t a2 = hbufU[rr0 * HBU + kk * 8 + cq + 4];
                uint32_t a3 = hbufU[rr1 * HBU + kk * 8 + cq + 4];
                uint32_t b0 = nW2p[(kk * 8 + cq) * 24 + d0];
                uint32_t b1 = nW2p[(kk * 8 + cq + 4) * 24 + d0];
                mma_f16(c4, a0, a1, a2, a3, b0, b1);
            }
            const int col = nf * 8 + 2 * cq;
            if (col < DD) {
                float nb = nb2l[col];
                if (rr0 < NN) zsh[rr0 * ZROW + col] += c4[0] + nb;
                if (rr1 < NN) zsh[rr1 * ZROW + col] += c4[2] + nb;
            }
            if (col + 1 < DD) {
                float nb = nb2l[col + 1];
                if (rr0 < NN) zsh[rr0 * ZROW + col + 1] += c4[1] + nb;
                if (rr1 < NN) zsh[rr1 * ZROW + col + 1] += c4[3] + nb;
            }
        }
        __syncthreads();
    }

    // ---- mean pool ----
    if (t < DD) {
        float s = 0.f;
        #pragma unroll
        for (int i = 0; i < NN; ++i) s += zsh[i * ZROW + t];
        znsh[t] = s * (1.0f / NN);
    }
    __syncthreads();

    // ---- head MLP ----
    float* hscr = znsh + 64;
    if (t < HDIM) {
        float a = hb1[t];
        #pragma unroll
        for (int d = 0; d < DD; ++d) a += znsh[d] * hW1[d * HDIM + t];
        hscr[t] = fmaxf(a, 0.f);
    }
    __syncthreads();

    float* ob = out + (size_t)b * (NN * OUTROW);
    for (int idx = t; idx < NN * OUTROW; idx += 256) {
        float v = 0.f;
        if (idx < NOUT) {
            v = hb2[idx];
            #pragma unroll
            for (int m2 = 0; m2 < HDIM; ++m2)
                v += hscr[m2] * hW2[m2 * NOUT + idx];
        }
        ob[idx] = v;
    }
}

extern "C" void kernel_launch(void* const* d_in, const int* in_sizes, int n_in,
                              void* d_out, int out_size) {
    (void)in_sizes; (void)n_in; (void)out_size;
    const float* x    = (const float*)d_in[0];
    const float* ctx  = (const float*)d_in[1];
    const float* eW1  = (const float*)d_in[2];
    const float* eb1  = (const float*)d_in[3];
    const float* eW2  = (const float*)d_in[4];
    const float* eb2  = (const float*)d_in[5];
    const float* gW   = (const float*)d_in[6];
    const float* gb   = (const float*)d_in[7];
    const float* lng  = (const float*)d_in[8];
    const float* lnb  = (const float*)d_in[9];
    const float* nW1  = (const float*)d_in[10];
    const float* nb1  = (const float*)d_in[11];
    const float* nW2  = (const float*)d_in[12];
    const float* nb2  = (const float*)d_in[13];
    const float* hW1  = (const float*)d_in[14];
    const float* hb1  = (const float*)d_in[15];
    const float* hW2  = (const float*)d_in[16];
    const float* hb2  = (const float*)d_in[17];
    float* out = (float*)d_out;

    prep_pack<<<32, 256>>>(eW1, eW2, nW1, nW2);
    cudaFuncSetAttribute(gnn_kernel, cudaFuncAttributeMaxDynamicSharedMemorySize,
                         SMEM_FLOATS * sizeof(float));
    gnn_kernel<<<NB, 256, SMEM_FLOATS * sizeof(float)>>>(
        x, ctx, eb1, eb2, gW, gb, lng, lnb,
        nb1, nb2, hW1, hb1, hW2, hb2, out);
}

// round 15
// speedup vs baseline: 2.9243x; 1.0442x over previous
#include <cuda_runtime.h>
#include <cuda_fp16.h>
#include <cstdint>
#include <cstddef>

// Problem constants
#define NB   4096
#define NN   29
#define NC   6
#define CDIM 16
#define DD   22
#define HDIM 64
#define NL   2
#define NOUT 24
#define OUTROW 12
#define ZROW 25
#define PRU  40     // pi/pj row stride (uint32)
#define W2HW 136    // W2 smem row stride (uint32)
#define ZTU  20     // ztU row stride
#define CATU 52     // catshU row stride
#define HBU  36     // hbufU row stride
#define MAGU 32     // maggU row stride

// Shared memory layout (float offsets)
#define OFF_Z    0        // 800
#define OFF_ZN   800      // 800
#define OFF_PI   1600     // 1280
#define OFF_PJ   2880     // 1280
#define OFF_W2H  4160     // 4352
#define OFF_ZT   8512     // 640
#define OFF_MAGG 9152     // 2048
#define OFF_H    11200    // 1152
#define OFF_EBH  12352    // 32
#define OFF_GWH  12384    // 32
#define SMEM_FLOATS 12416 // 49664 bytes -> 4 CTAs/SM

// Prepacked fp16 weights (device scratch; filled by prep_pack each launch)
__device__ uint32_t g_eW1p[NL * 2 * 12 * 64];
__device__ uint32_t g_eW2p[NL * 32 * 64];
__device__ uint32_t g_nW1p[NL * 44 * 64];
__device__ uint32_t g_nW2p[NL * 32 * 24];

__device__ __forceinline__ float tanhfast(float x) {
    float y;
    asm("tanh.approx.f32 %0, %1;" : "=f"(y) : "f"(x));
    return y;
}
__device__ __forceinline__ float silu_t(float v) {
    float h = 0.5f * v;
    return fmaf(h, tanhfast(h), h);
}
__device__ __forceinline__ float sigm_t(float v) {
    return fmaf(0.5f, tanhfast(0.5f * v), 0.5f);
}
__device__ __forceinline__ uint32_t pack_h2(float lo, float hi) {
    __half2 h = __floats2half2_rn(lo, hi);
    return *(uint32_t*)&h;
}
__device__ __forceinline__ uint32_t hadd2u(uint32_t a, uint32_t b) {
    __half2 r = __hadd2(*(__half2*)&a, *(__half2*)&b);
    return *(uint32_t*)&r;
}
__device__ __forceinline__ uint32_t hfma2u(uint32_t a, uint32_t b, uint32_t c) {
    __half2 r = __hfma2(*(__half2*)&a, *(__half2*)&b, *(__half2*)&c);
    return *(uint32_t*)&r;
}
__device__ __forceinline__ uint32_t hmul2u(uint32_t a, uint32_t b) {
    __half2 r = __hmul2(*(__half2*)&a, *(__half2*)&b);
    return *(uint32_t*)&r;
}
// silu(2h) given h: h + h*tanh(h)
__device__ __forceinline__ uint32_t silu_from_h(uint32_t h) {
    uint32_t tu;
    asm("tanh.approx.f16x2 %0, %1;" : "=r"(tu) : "r"(h));
    return hfma2u(h, tu, h);
}
__device__ __forceinline__ float2 h22f2(uint32_t u) {
    return __half22float2(*(__half2*)&u);
}
__device__ __forceinline__ uint32_t bcast_h2(float v) {
    __half2 h = __float2half2_rn(v);
    return *(uint32_t*)&h;
}
__device__ __forceinline__ void mma_f16(float c[4], uint32_t a0, uint32_t a1,
                                        uint32_t a2, uint32_t a3,
                                        uint32_t b0, uint32_t b1) {
    asm volatile(
        "mma.sync.aligned.m16n8k16.row.col.f32.f16.f16.f32 "
        "{%0,%1,%2,%3}, {%4,%5,%6,%7}, {%8,%9}, {%0,%1,%2,%3};\n"
        : "+f"(c[0]), "+f"(c[1]), "+f"(c[2]), "+f"(c[3])
        : "r"(a0), "r"(a1), "r"(a2), "r"(a3), "r"(b0), "r"(b1));
}
__device__ __forceinline__ void mma_f16_k8(float c[4], uint32_t a0, uint32_t a1,
                                           uint32_t b0) {
    asm volatile(
        "mma.sync.aligned.m16n8k8.row.col.f32.f16.f16.f32 "
        "{%0,%1,%2,%3}, {%4,%5}, {%6}, {%0,%1,%2,%3};\n"
        : "+f"(c[0]), "+f"(c[1]), "+f"(c[2]), "+f"(c[3])
        : "r"(a0), "r"(a1), "r"(b0));
}

// ---- prep: pack weights to half2 once per launch ----
extern "C" __global__ void prep_pack(const float* __restrict__ eW1,
                                     const float* __restrict__ eW2,
                                     const float* __restrict__ nW1,
                                     const float* __restrict__ nW2) {
    int tid = blockIdx.x * blockDim.x + threadIdx.x;
    int stride = gridDim.x * blockDim.x;
    for (int i = tid; i < NL * 2 * 12 * 64; i += stride) {
        int c = i & 63;
        int p = (i >> 6) % 12;
        int h = ((i >> 6) / 12) & 1;
        int l = (i >> 6) / 24;
        int k0 = 2 * p;
        float v0 = (k0 < DD)     ? eW1[(l * 2 * DD + h * DD + k0) * HDIM + c] : 0.f;
        float v1 = (k0 + 1 < DD) ? eW1[(l * 2 * DD + h * DD + k0 + 1) * HDIM + c] : 0.f;
        g_eW1p[i] = pack_h2(v0, v1);
    }
    for (int i = tid; i < NL * 32 * 64; i += stride) {
        int c = i & 63;
        int p = (i >> 6) & 31;
        int l = i >> 11;
        g_eW2p[i] = pack_h2(eW2[(l * HDIM + 2 * p) * HDIM + c],
                            eW2[(l * HDIM + 2 * p + 1) * HDIM + c]);
    }
    for (int i = tid; i < NL * 44 * 64; i += stride) {
        int c = i & 63;
        int p = (i >> 6) % 44;
        int l = (i >> 6) / 44;
        int k0 = 2 * p;
        const int KT = DD + HDIM;
        float v0 = (k0 < KT)     ? nW1[(l * KT + k0) * HDIM + c] : 0.f;
        float v1 = (k0 + 1 < KT) ? nW1[(l * KT + k0 + 1) * HDIM + c] : 0.f;
        g_nW1p[i] = pack_h2(v0, v1);
    }
    for (int i = tid; i < NL * 32 * 24; i += stride) {
        int d = i % 24;
        int p = (i / 24) & 31;
        int l = i / (32 * 24);
        float v0 = (d < DD) ? nW2[(l * HDIM + 2 * p) * DD + d] : 0.f;
        float v1 = (d < DD) ? nW2[(l * HDIM + 2 * p + 1) * DD + d] : 0.f;
        g_nW2p[i] = pack_h2(v0, v1);
    }
}

extern "C" __global__ void __launch_bounds__(256, 4)
gnn_kernel(const float* __restrict__ x,   const float* __restrict__ ctx,
           const float* __restrict__ eb1, const float* __restrict__ eb2,
           const float* __restrict__ gW,  const float* __restrict__ gb,
           const float* __restrict__ lng, const float* __restrict__ lnb,
           const float* __restrict__ nb1, const float* __restrict__ nb2,
           const float* __restrict__ hW1, const float* __restrict__ hb1,
           const float* __restrict__ hW2, const float* __restrict__ hb2,
           float* __restrict__ out)
{
    extern __shared__ float sh[];
    float*    zsh  = sh + OFF_Z;
    float*    znsh = sh + OFF_ZN;
    uint32_t* piU  = (uint32_t*)(sh + OFF_PI);
    uint32_t* pjU  = (uint32_t*)(sh + OFF_PJ);
    uint32_t* w2hU = (uint32_t*)(sh + OFF_W2H);
    uint32_t* ztU  = (uint32_t*)(sh + OFF_ZT);
    uint32_t* maggU = (uint32_t*)(sh + OFF_MAGG);
    uint32_t* hbufU = (uint32_t*)(sh + OFF_H);
    uint32_t* ebhU = (uint32_t*)(sh + OFF_EBH);
    uint32_t* gwhU = (uint32_t*)(sh + OFF_GWH);
    uint32_t* catshU = (uint32_t*)(sh + OFF_PI);

    const int b = blockIdx.x;
    const int t = threadIdx.x;
    const int w = t >> 5;
    const int lane = t & 31;
    const int lq = lane >> 2;
    const int cq = lane & 3;
    const int i_sel = w >> 1;
    const int jh = w & 1;
    const int r0 = jh * 16 + lq;
    const int r1 = r0 + 8;

    // ---- load z = concat(x, context) ----
    for (int idx = t; idx < NN * DD; idx += 256) {
        int i = idx / DD, d = idx - i * DD;
        float v = (d < NC) ? x[(b * NN + i) * NC + d]
                           : ctx[(b * NN + i) * CDIM + (d - NC)];
        zsh[i * ZROW + d] = v;
    }
    __syncthreads();

    for (int l = 0; l < NL; ++l) {
        const float* eb1l = eb1 + l * HDIM;
        const float* eb2l = eb2 + l * HDIM;
        const float* gWl  = gW  + l * HDIM;
        const float  gbl  = gb[l];
        const float* lngl = lng + l * DD;
        const float* lnbl = lnb + l * DD;
        const float* nb1l = nb1 + l * HDIM;
        const float* nb2l = nb2 + l * DD;
        const uint32_t* eW2p = g_eW2p + l * 2048;
        const uint32_t* nW1p = g_nW1p + l * (44 * 64);
        const uint32_t* nW2p = g_nW2p + l * (32 * 24);

        // ======== staging: w2h (prepacked), ztU (l==0 only), ebh(*0.5), gwh ========
        for (int e = t; e < 1024; e += 256) {
            int kp = e >> 5, c = e & 31;
            int kk = kp >> 2, cqv = kp & 3;
            int p = kk * 8 + cqv;
            uint4 q;
            q.x = eW2p[p * 64 + c];
            q.y = eW2p[(p + 4) * 64 + c];
            q.z = eW2p[p * 64 + c + 32];
            q.w = eW2p[(p + 4) * 64 + c + 32];
            *(uint4*)(w2hU + kp * W2HW + c * 4) = q;
        }
        if (l == 0) {
            for (int idx = t; idx < 32 * 16; idx += 256) {
                int i = idx >> 4, p = idx & 15;
                uint32_t v = 0;
                if (i < NN && p < 11)
                    v = pack_h2(zsh[i * ZROW + 2 * p], zsh[i * ZROW + 2 * p + 1]);
                ztU[i * ZTU + p] = v;
            }
        }
        if (t < 32) {
            int cqv = t >> 3, nf = t & 7;
            ebhU[cqv * 8 + nf] = pack_h2(0.5f * eb2l[nf * 8 + 2 * cqv],
                                         0.5f * eb2l[nf * 8 + 2 * cqv + 1]);
        }
        if (t >= 32 && t < 64) {
            int i = t - 32;
            int cqv = i >> 3, nf = i & 7;
            gwhU[cqv * 8 + nf] = pack_h2(gWl[nf * 8 + 2 * cqv],
                                         gWl[nf * 8 + 2 * cqv + 1]);
        }
        __syncthreads();

        // ======== projections via f16 MMA -> piU|pjU (pre-halved) ========
        {
            float pacc[2][2][4];
            #pragma unroll
            for (int mf = 0; mf < 2; ++mf)
                #pragma unroll
                for (int nfi = 0; nfi < 2; ++nfi)
                    #pragma unroll
                    for (int e = 0; e < 4; ++e) pacc[mf][nfi][e] = 0.f;

            const uint32_t* Wp = g_eW1p + (l * 2 + ((w < 4) ? 0 : 1)) * (12 * 64);
            {
                uint32_t aA[2][4];
                #pragma unroll
                for (int mf = 0; mf < 2; ++mf) {
                    int rb = mf * 16;
                    aA[mf][0] = ztU[(rb + lq) * ZTU + cq];
                    aA[mf][1] = ztU[(rb + lq + 8) * ZTU + cq];
                    aA[mf][2] = ztU[(rb + lq) * ZTU + cq + 4];
                    aA[mf][3] = ztU[(rb + lq + 8) * ZTU + cq + 4];
                }
                #pragma unroll
                for (int nfi = 0; nfi < 2; ++nfi) {
                    const int col = (w & 3) * 16 + nfi * 8 + lq;
                    uint32_t b0 = Wp[cq * 64 + col];
                    uint32_t b1 = Wp[(cq + 4) * 64 + col];
                    #pragma unroll
                    for (int mf = 0; mf < 2; ++mf)
                        mma_f16(pacc[mf][nfi], aA[mf][0], aA[mf][1],
                                aA[mf][2], aA[mf][3], b0, b1);
                }
            }
            {
                uint32_t aA[2][2];
                #pragma unroll
                for (int mf = 0; mf < 2; ++mf) {
                    int rb = mf * 16;
                    aA[mf][0] = ztU[(rb + lq) * ZTU + 8 + cq];
                    aA[mf][1] = ztU[(rb + lq + 8) * ZTU + 8 + cq];
                }
                #pragma unroll
                for (int nfi = 0; nfi < 2; ++nfi) {
                    const int col = (w & 3) * 16 + nfi * 8 + lq;
                    uint32_t b0 = Wp[(8 + cq) * 64 + col];
                    #pragma unroll
                    for (int mf = 0; mf < 2; ++mf)
                        mma_f16_k8(pacc[mf][nfi], aA[mf][0], aA[mf][1], b0);
                }
            }
            uint32_t* dstU = (w < 4) ? piU : pjU;
            #pragma unroll
            for (int nfi = 0; nfi < 2; ++nfi) {
                float ex = 0.f, ey = 0.f;
                if (w < 4) {
                    float2 e2 = *(const float2*)(eb1l + (w & 3) * 16 + nfi * 8 + 2 * cq);
                    ex = e2.x; ey = e2.y;
                }
                const int cp = (w & 3) * 8 + cq * 2 + nfi;
                #pragma unroll
                for (int mf = 0; mf < 2; ++mf) {
                    int r = mf * 16 + lq;
                    dstU[r * PRU + cp] =
                        pack_h2((pacc[mf][nfi][0] + ex) * 0.5f,
                                (pacc[mf][nfi][1] + ey) * 0.5f);
                    dstU[(r + 8) * PRU + cp] =
                        pack_h2((pacc[mf][nfi][2] + ex) * 0.5f,
                                (pacc[mf][nfi][3] + ey) * 0.5f);
                }
            }
        }
        // ---- layernorm, parallel: 32 rows x 8 lanes ----
        {
            const int i = t >> 3, j = t & 7;
            float mu = 0.f, sq = 0.f;
            if (i < NN) {
                #pragma unroll
                for (int c = j; c < DD; c += 8) {
                    float v = zsh[i * ZROW + c];
                    mu += v; sq += v * v;
                }
            }
            mu += __shfl_xor_sync(0xffffffffu, mu, 1);
            mu += __shfl_xor_sync(0xffffffffu, mu, 2);
            mu += __shfl_xor_sync(0xffffffffu, mu, 4);
            sq += __shfl_xor_sync(0xffffffffu, sq, 1);
            sq += __shfl_xor_sync(0xffffffffu, sq, 2);
            sq += __shfl_xor_sync(0xffffffffu, sq, 4);
            mu *= (1.0f / DD);
            float var = sq * (1.0f / DD) - mu * mu;
            float rs = rsqrtf(var + 1e-5f);
            if (i < NN) {
                #pragma unroll
                for (int c = j; c < DD; c += 8)
                    znsh[i * ZROW + c] = (zsh[i * ZROW + c] - mu) * rs * lngl[c] + lnbl[c];
            }
        }
        __syncthreads();

        // ---- per-layer hoist: pj pairs ----
        uint2 pj0q[4], pj1q[4];
        {
            const uint2* pj0p = (const uint2*)(pjU + r0 * PRU);
            const uint2* pj1p = (const uint2*)(pjU + r1 * PRU);
            #pragma unroll
            for (int kk = 0; kk < 4; ++kk) {
                pj0q[kk] = pj0p[kk * 4 + cq];
                pj1q[kk] = pj1p[kk * 4 + cq];
            }
        }
        const uint32_t half05 = bcast_h2(0.5f);

        // ======== edge tiles (fully unrolled, predicated body) ========
        #pragma unroll
        for (int ig = 0; ig < 8; ++ig) {
            const int node = ig * 4 + i_sel;
            if (node < NN) {
                const uint2* pi2 = (const uint2*)(piU + node * PRU);

                float acc[8][4];
                #pragma unroll
                for (int nf = 0; nf < 8; ++nf)
                    #pragma unroll
                    for (int e = 0; e < 4; ++e) acc[nf][e] = 0.f;

                #pragma unroll
                for (int kk = 0; kk < 4; ++kk) {
                    uint2 piq = pi2[kk * 4 + cq];
                    uint32_t a0 = silu_from_h(hadd2u(piq.x, pj0q[kk].x));
                    uint32_t a1 = silu_from_h(hadd2u(piq.x, pj1q[kk].x));
                    uint32_t a2 = silu_from_h(hadd2u(piq.y, pj0q[kk].y));
                    uint32_t a3 = silu_from_h(hadd2u(piq.y, pj1q[kk].y));
                    const uint32_t* wb = w2hU + (kk * 4 + cq) * W2HW + lq * 4;
                    #pragma unroll
                    for (int nf = 0; nf < 4; ++nf) {
                        uint4 q = *(const uint4*)(wb + nf * 32);
                        mma_f16(acc[nf],     a0, a1, a2, a3, q.x, q.y);
                        mma_f16(acc[nf + 4], a0, a1, a2, a3, q.z, q.w);
                    }
                }

                uint32_t ebr[8], gwh[8];
                *(uint4*)(ebr)     = *(const uint4*)(ebhU + cq * 8);
                *(uint4*)(ebr + 4) = *(const uint4*)(ebhU + cq * 8 + 4);
                *(uint4*)(gwh)     = *(const uint4*)(gwhU + cq * 8);
                *(uint4*)(gwh + 4) = *(const uint4*)(gwhU + cq * 8 + 4);

                uint32_t m01[8], m23[8];
                uint32_t gph0 = 0, gph1 = 0;
                #pragma unroll
                for (int nf = 0; nf < 8; ++nf) {
                    uint32_t h01 = hfma2u(pack_h2(acc[nf][0], acc[nf][1]), half05, ebr[nf]);
                    uint32_t h23 = hfma2u(pack_h2(acc[nf][2], acc[nf][3]), half05, ebr[nf]);
                    uint32_t u01 = silu_from_h(h01);
                    uint32_t u23 = silu_from_h(h23);
                    m01[nf] = u01; m23[nf] = u23;
                    gph0 = hfma2u(u01, gwh[nf], gph0);
                    gph1 = hfma2u(u23, gwh[nf], gph1);
                }
                float2 gpf0 = h22f2(gph0), gpf1 = h22f2(gph1);
                float gp0 = gpf0.x + gpf0.y;
                float gp1 = gpf1.x + gpf1.y;
                gp0 += __shfl_xor_sync(0xffffffffu, gp0, 1);
                gp0 += __shfl_xor_sync(0xffffffffu, gp0, 2);
                gp1 += __shfl_xor_sync(0xffffffffu, gp1, 1);
                gp1 += __shfl_xor_sync(0xffffffffu, gp1, 2);
                float g0 = sigm_t(gp0 + gbl);
                float g1 = (r1 < NN) ? sigm_t(gp1 + gbl) : 0.f;
                uint32_t g0h = bcast_h2(g0), g1h = bcast_h2(g1);

                uint32_t s8h[8];
                #pragma unroll
                for (int nf = 0; nf < 8; ++nf)
                    s8h[nf] = hfma2u(m23[nf], g1h, hmul2u(m01[nf], g0h));

                const int bb0 = lq & 1, bb1 = (lq >> 1) & 1, bb2 = (lq >> 2) & 1;
                uint32_t v4h[4];
                #pragma unroll
                for (int j = 0; j < 4; ++j) {
                    uint32_t keep = bb0 ? s8h[4 + j] : s8h[j];
                    uint32_t send = bb0 ? s8h[j]     : s8h[4 + j];
                    v4h[j] = hadd2u(keep, __shfl_xor_sync(0xffffffffu, send, 4));
                }
                uint32_t v2h[2];
                #pragma unroll
                for (int j = 0; j < 2; ++j) {
                    uint32_t keep = bb1 ? v4h[2 + j] : v4h[j];
                    uint32_t send = bb1 ? v4h[j]     : v4h[2 + j];
                    v2h[j] = hadd2u(keep, __shfl_xor_sync(0xffffffffu, send, 8));
                }
                uint32_t v1h;
                {
                    uint32_t keep = bb2 ? v2h[1] : v2h[0];
                    uint32_t send = bb2 ? v2h[0] : v2h[1];
                    v1h = hadd2u(keep, __shfl_xor_sync(0xffffffffu, send, 16));
                }
                const int nfv = bb0 * 4 + bb1 * 2 + bb2;
                maggU[jh * 1024 + node * MAGU + nfv * 4 + cq] = v1h;
            }
        }
        __syncthreads();

        // ======== concat buffer (packed half2): [zn | m_i | 0-pad] ========
        for (int idx = t; idx < 32 * 32; idx += 256) {
            int i = idx >> 5, p = idx & 31;
            uint32_t v = 0;
            if (i < NN) v = hadd2u(maggU[i * MAGU + p], maggU[1024 + i * MAGU + p]);
            catshU[i * CATU + 11 + p] = v;
        }
        for (int idx = t; idx < 32 * 16; idx += 256) {
            int i = idx >> 4, p = idx & 15;
            if (p < 11) {
                uint32_t v = 0;
                if (i < NN) v = pack_h2(znsh[i * ZROW + 2 * p], znsh[i * ZROW + 2 * p + 1]);
                catshU[i * CATU + p] = v;
            } else {
                catshU[i * CATU + 32 + p] = 0;
            }
        }
        __syncthreads();

        // ======== node MLP layer 1 via f16 MMA: [32x88] @ [86x64] ========
        {
            const int mh  = w & 1;
            const int nh4 = w >> 1;
            const int row0 = mh * 16 + lq, row1 = row0 + 8;
            float c2[2][4];
            #pragma unroll
            for (int nfi = 0; nfi < 2; ++nfi)
                #pragma unroll
                for (int e = 0; e < 4; ++e) c2[nfi][e] = 0.f;

            #pragma unroll
            for (int kk = 0; kk < 5; ++kk) {
                uint32_t a0 = catshU[row0 * CATU + kk * 8 + cq];
                uint32_t a1 = catshU[row1 * CATU + kk * 8 + cq];
                uint32_t a2 = catshU[row0 * CATU + kk * 8 + cq + 4];
                uint32_t a3 = catshU[row1 * CATU + kk * 8 + cq + 4];
                #pragma unroll
                for (int nfi = 0; nfi < 2; ++nfi) {
                    const int col = (nh4 * 2 + nfi) * 8 + lq;
                    uint32_t b0 = nW1p[(kk * 8 + cq) * 64 + col];
                    uint32_t b1 = nW1p[(kk * 8 + cq + 4) * 64 + col];
                    mma_f16(c2[nfi], a0, a1, a2, a3, b0, b1);
                }
            }
            {
                uint32_t a0 = catshU[row0 * CATU + 40 + cq];
                uint32_t a1 = catshU[row1 * CATU + 40 + cq];
                #pragma unroll
                for (int nfi = 0; nfi < 2; ++nfi) {
                    const int col = (nh4 * 2 + nfi) * 8 + lq;
                    uint32_t b0 = nW1p[(40 + cq) * 64 + col];
                    mma_f16_k8(c2[nfi], a0, a1, b0);
                }
            }
            #pragma unroll
            for (int nfi = 0; nfi < 2; ++nfi) {
                const int colb = (nh4 * 2 + nfi) * 8 + 2 * cq;
                float2 nb = *(const float2*)(nb1l + colb);
                const int pid = colb >> 1;
                hbufU[row0 * HBU + pid] =
                    pack_h2(silu_t(c2[nfi][0] + nb.x), silu_t(c2[nfi][1] + nb.y));
                hbufU[row1 * HBU + pid] =
                    pack_h2(silu_t(c2[nfi][2] + nb.x), silu_t(c2[nfi][3] + nb.y));
            }
        }
        __syncthreads();

        // ======== node MLP layer 2 via f16 MMA + residual; writes zsh AND ztU ========
        if (w < 6) {
            const int mf = w & 1;
            const int nf = w >> 1;
            const int d0 = nf * 8 + lq;
            const int rr0 = mf * 16 + lq, rr1 = rr0 + 8;
            float c4[4] = {0.f, 0.f, 0.f, 0.f};
            #pragma unroll
            for (int kk = 0; kk < 4; ++kk) {
                uint32_t a0 = hbufU[rr0 * HBU + kk * 8 + cq];
                uint32_t a1 = hbufU[rr1 * HBU + kk * 8 + cq];
                uint32_t a2 = hbufU[rr0 * HBU + kk * 8 + cq + 4];
                uint32_t a3 = hbufU[rr1 * HBU + kk * 8 + cq + 4];
                uint32_t b0 = nW2p[(kk * 8 + cq) * 24 + d0];
                uint32_t b1 = nW2p[(kk * 8 + cq + 4) * 24 + d0];
                mma_f16(c4, a0, a1, a2, a3, b0, b1);
            }
            const int col = nf * 8 + 2 * cq;
            if (col < DD) {                          // cols 0..21; col+1 <= 21 too
                float nb0 = nb2l[col];
                float nb1v = nb2l[col + 1];
                if (rr0 < NN) {
                    float z0 = zsh[rr0 * ZROW + col] + c4[0] + nb0;
                    float z1 = zsh[rr0 * ZROW + col + 1] + c4[1] + nb1v;
                    zsh[rr0 * ZROW + col] = z0;
                    zsh[rr0 * ZROW + col + 1] = z1;
                    ztU[rr0 * ZTU + (col >> 1)] = pack_h2(z0, z1);
                }
                if (rr1 < NN) {
                    float z0 = zsh[rr1 * ZROW + col] + c4[2] + nb0;
                    float z1 = zsh[rr1 * ZROW + col + 1] + c4[3] + nb1v;
                    zsh[rr1 * ZROW + col] = z0;
                    zsh[rr1 * ZROW + col + 1] = z1;
                    ztU[rr1 * ZTU + (col >> 1)] = pack_h2(z0, z1);
                }
            }
        }
        __syncthreads();
    }

    // ---- mean pool ----
    if (t < DD) {
        float s = 0.f;
        #pragma unroll
        for (int i = 0; i < NN; ++i) s += zsh[i * ZROW + t];
        znsh[t] = s * (1.0f / NN);
    }
    __syncthreads();

    // ---- head MLP ----
    float* hscr = znsh + 64;
    if (t < HDIM) {
        float a = hb1[t];
        #pragma unroll
        for (int d = 0; d < DD; ++d) a += znsh[d] * hW1[d * HDIM + t];
        hscr[t] = fmaxf(a, 0.f);
    }
    __syncthreads();

    float* ob = out + (size_t)b * (NN * OUTROW);
    for (int idx = t; idx < NN * OUTROW; idx += 256) {
        float v = 0.f;
        if (idx < NOUT) {
            v = hb2[idx];
            #pragma unroll
            for (int m2 = 0; m2 < HDIM; ++m2)
                v += hscr[m2] * hW2[m2 * NOUT + idx];
        }
        ob[idx] = v;
    }
}

extern "C" void kernel_launch(void* const* d_in, const int* in_sizes, int n_in,
                              void* d_out, int out_size) {
    (void)in_sizes; (void)n_in; (void)out_size;
    const float* x    = (const float*)d_in[0];
    const float* ctx  = (const float*)d_in[1];
    const float* eW1  = (const float*)d_in[2];
    const float* eb1  = (const float*)d_in[3];
    const float* eW2  = (const float*)d_in[4];
    const float* eb2  = (const float*)d_in[5];
    const float* gW   = (const float*)d_in[6];
    const float* gb   = (const float*)d_in[7];
    const float* lng  = (const float*)d_in[8];
    const float* lnb  = (const float*)d_in[9];
    const float* nW1  = (const float*)d_in[10];
    const float* nb1  = (const float*)d_in[11];
    const float* nW2  = (const float*)d_in[12];
    const float* nb2  = (const float*)d_in[13];
    const float* hW1  = (const float*)d_in[14];
    const float* hb1  = (const float*)d_in[15];
    const float* hW2  = (const float*)d_in[16];
    const float* hb2  = (const float*)d_in[17];
    float* out = (float*)d_out;

    prep_pack<<<32, 256>>>(eW1, eW2, nW1, nW2);
    cudaFuncSetAttribute(gnn_kernel, cudaFuncAttributeMaxDynamicSharedMemorySize,
                         SMEM_FLOATS * sizeof(float));
    gnn_kernel<<<NB, 256, SMEM_FLOATS * sizeof(float)>>>(
        x, ctx, eb1, eb2, gW, gb, lng, lnb,
        nb1, nb2, hW1, hb1, hW2, hb2, out);
}

// round 16
// speedup vs baseline: 2.9552x; 1.0106x over previous
#include <cuda_runtime.h>
#include <cuda_fp16.h>
#include <cstdint>
#include <cstddef>

// Problem constants
#define NB   4096
#define NN   29
#define NC   6
#define CDIM 16
#define DD   22
#define HDIM 64
#define NL   2
#define NOUT 24
#define OUTROW 12
#define ZROW 25
#define PRU  40     // pi/pj row stride (uint32)
#define W2HW 136    // W2 smem row stride (uint32)
#define ZTU  20     // ztU row stride
#define CATU 52     // catshU row stride
#define HBU  36     // hbufU row stride
#define MAGU 32     // maggU row stride within plane
#define MPL  932    // magg plane stride (932 % 32 == 4 -> plane-pair stores conflict-free)

// Shared memory layout (float offsets)
#define OFF_Z    0        // 736 (29*25=725 used)
#define OFF_ZN   736      // 736
#define OFF_PI   1472     // 1280
#define OFF_PJ   2752     // 1280
#define OFF_W2H  4032     // 4352
#define OFF_ZT   8384     // 640
#define OFF_MAGG 9024     // 4*932 = 3728
#define OFF_H    12752    // 1152
#define OFF_EBH  13904    // 32
#define OFF_GWH  13936    // 32
#define SMEM_FLOATS 13968 // 55872 bytes -> 4 CTAs/SM
// catshU [32][52]=1664 uint aliases OFF_PI..3136 (pi/pj dead after tile loop)

// Prepacked fp16 weights (device scratch; filled by prep_pack each launch)
__device__ uint32_t g_eW1p[NL * 2 * 12 * 64];
__device__ uint32_t g_eW2p[NL * 32 * 64];
__device__ uint32_t g_nW1p[NL * 44 * 64];
__device__ uint32_t g_nW2p[NL * 32 * 24];

__device__ __forceinline__ float tanhfast(float x) {
    float y;
    asm("tanh.approx.f32 %0, %1;" : "=f"(y) : "f"(x));
    return y;
}
__device__ __forceinline__ float silu_t(float v) {
    float h = 0.5f * v;
    return fmaf(h, tanhfast(h), h);
}
__device__ __forceinline__ float sigm_t(float v) {
    return fmaf(0.5f, tanhfast(0.5f * v), 0.5f);
}
__device__ __forceinline__ uint32_t pack_h2(float lo, float hi) {
    __half2 h = __floats2half2_rn(lo, hi);
    return *(uint32_t*)&h;
}
__device__ __forceinline__ uint32_t hadd2u(uint32_t a, uint32_t b) {
    __half2 r = __hadd2(*(__half2*)&a, *(__half2*)&b);
    return *(uint32_t*)&r;
}
__device__ __forceinline__ uint32_t hfma2u(uint32_t a, uint32_t b, uint32_t c) {
    __half2 r = __hfma2(*(__half2*)&a, *(__half2*)&b, *(__half2*)&c);
    return *(uint32_t*)&r;
}
__device__ __forceinline__ uint32_t hmul2u(uint32_t a, uint32_t b) {
    __half2 r = __hmul2(*(__half2*)&a, *(__half2*)&b);
    return *(uint32_t*)&r;
}
// silu(2h) given h: h + h*tanh(h)
__device__ __forceinline__ uint32_t silu_from_h(uint32_t h) {
    uint32_t tu;
    asm("tanh.approx.f16x2 %0, %1;" : "=r"(tu) : "r"(h));
    return hfma2u(h, tu, h);
}
__device__ __forceinline__ float2 h22f2(uint32_t u) {
    return __half22float2(*(__half2*)&u);
}
__device__ __forceinline__ uint32_t bcast_h2(float v) {
    __half2 h = __float2half2_rn(v);
    return *(uint32_t*)&h;
}
__device__ __forceinline__ void mma_f16(float c[4], uint32_t a0, uint32_t a1,
                                        uint32_t a2, uint32_t a3,
                                        uint32_t b0, uint32_t b1) {
    asm volatile(
        "mma.sync.aligned.m16n8k16.row.col.f32.f16.f16.f32 "
        "{%0,%1,%2,%3}, {%4,%5,%6,%7}, {%8,%9}, {%0,%1,%2,%3};\n"
        : "+f"(c[0]), "+f"(c[1]), "+f"(c[2]), "+f"(c[3])
        : "r"(a0), "r"(a1), "r"(a2), "r"(a3), "r"(b0), "r"(b1));
}
__device__ __forceinline__ void mma_f16_k8(float c[4], uint32_t a0, uint32_t a1,
                                           uint32_t b0) {
    asm volatile(
        "mma.sync.aligned.m16n8k8.row.col.f32.f16.f16.f32 "
        "{%0,%1,%2,%3}, {%4,%5}, {%6}, {%0,%1,%2,%3};\n"
        : "+f"(c[0]), "+f"(c[1]), "+f"(c[2]), "+f"(c[3])
        : "r"(a0), "r"(a1), "r"(b0));
}

// ---- prep: pack weights to half2 once per launch ----
extern "C" __global__ void prep_pack(const float* __restrict__ eW1,
                                     const float* __restrict__ eW2,
                                     const float* __restrict__ nW1,
                                     const float* __restrict__ nW2) {
    int tid = blockIdx.x * blockDim.x + threadIdx.x;
    int stride = gridDim.x * blockDim.x;
    for (int i = tid; i < NL * 2 * 12 * 64; i += stride) {
        int c = i & 63;
        int p = (i >> 6) % 12;
        int h = ((i >> 6) / 12) & 1;
        int l = (i >> 6) / 24;
        int k0 = 2 * p;
        float v0 = (k0 < DD)     ? eW1[(l * 2 * DD + h * DD + k0) * HDIM + c] : 0.f;
        float v1 = (k0 + 1 < DD) ? eW1[(l * 2 * DD + h * DD + k0 + 1) * HDIM + c] : 0.f;
        g_eW1p[i] = pack_h2(v0, v1);
    }
    for (int i = tid; i < NL * 32 * 64; i += stride) {
        int c = i & 63;
        int p = (i >> 6) & 31;
        int l = i >> 11;
        g_eW2p[i] = pack_h2(eW2[(l * HDIM + 2 * p) * HDIM + c],
                            eW2[(l * HDIM + 2 * p + 1) * HDIM + c]);
    }
    for (int i = tid; i < NL * 44 * 64; i += stride) {
        int c = i & 63;
        int p = (i >> 6) % 44;
        int l = (i >> 6) / 44;
        int k0 = 2 * p;
        const int KT = DD + HDIM;
        float v0 = (k0 < KT)     ? nW1[(l * KT + k0) * HDIM + c] : 0.f;
        float v1 = (k0 + 1 < KT) ? nW1[(l * KT + k0 + 1) * HDIM + c] : 0.f;
        g_nW1p[i] = pack_h2(v0, v1);
    }
    for (int i = tid; i < NL * 32 * 24; i += stride) {
        int d = i % 24;
        int p = (i / 24) & 31;
        int l = i / (32 * 24);
        float v0 = (d < DD) ? nW2[(l * HDIM + 2 * p) * DD + d] : 0.f;
        float v1 = (d < DD) ? nW2[(l * HDIM + 2 * p + 1) * DD + d] : 0.f;
        g_nW2p[i] = pack_h2(v0, v1);
    }
}

extern "C" __global__ void __launch_bounds__(256, 4)
gnn_kernel(const float* __restrict__ x,   const float* __restrict__ ctx,
           const float* __restrict__ eb1, const float* __restrict__ eb2,
           const float* __restrict__ gW,  const float* __restrict__ gb,
           const float* __restrict__ lng, const float* __restrict__ lnb,
           const float* __restrict__ nb1, const float* __restrict__ nb2,
           const float* __restrict__ hW1, const float* __restrict__ hb1,
           const float* __restrict__ hW2, const float* __restrict__ hb2,
           float* __restrict__ out)
{
    extern __shared__ float sh[];
    float*    zsh  = sh + OFF_Z;
    float*    znsh = sh + OFF_ZN;
    uint32_t* piU  = (uint32_t*)(sh + OFF_PI);
    uint32_t* pjU  = (uint32_t*)(sh + OFF_PJ);
    uint32_t* w2hU = (uint32_t*)(sh + OFF_W2H);
    uint32_t* ztU  = (uint32_t*)(sh + OFF_ZT);
    uint32_t* maggU = (uint32_t*)(sh + OFF_MAGG);   // [4 planes][29][32], stride MPL
    uint32_t* hbufU = (uint32_t*)(sh + OFF_H);
    uint32_t* ebhU = (uint32_t*)(sh + OFF_EBH);
    uint32_t* gwhU = (uint32_t*)(sh + OFF_GWH);
    uint32_t* catshU = (uint32_t*)(sh + OFF_PI);

    const int b = blockIdx.x;
    const int t = threadIdx.x;
    const int w = t >> 5;
    const int lane = t & 31;
    const int lq = lane >> 2;
    const int cq = lane & 3;
    const int i_sel = w >> 1;
    const int jh = w & 1;
    const int r0 = jh * 16 + lq;
    const int r1 = r0 + 8;

    // ---- load z = concat(x, context) ----
    for (int idx = t; idx < NN * DD; idx += 256) {
        int i = idx / DD, d = idx - i * DD;
        float v = (d < NC) ? x[(b * NN + i) * NC + d]
                           : ctx[(b * NN + i) * CDIM + (d - NC)];
        zsh[i * ZROW + d] = v;
    }
    __syncthreads();

    for (int l = 0; l < NL; ++l) {
        const float* eb1l = eb1 + l * HDIM;
        const float* eb2l = eb2 + l * HDIM;
        const float* gWl  = gW  + l * HDIM;
        const float  gbl  = gb[l];
        const float* lngl = lng + l * DD;
        const float* lnbl = lnb + l * DD;
        const float* nb1l = nb1 + l * HDIM;
        const float* nb2l = nb2 + l * DD;
        const uint32_t* eW2p = g_eW2p + l * 2048;
        const uint32_t* nW1p = g_nW1p + l * (44 * 64);
        const uint32_t* nW2p = g_nW2p + l * (32 * 24);

        // ======== staging: w2h (prepacked), ztU (l==0 only), ebh(*0.5), gwh ========
        for (int e = t; e < 1024; e += 256) {
            int kp = e >> 5, c = e & 31;
            int kk = kp >> 2, cqv = kp & 3;
            int p = kk * 8 + cqv;
            uint4 q;
            q.x = eW2p[p * 64 + c];
            q.y = eW2p[(p + 4) * 64 + c];
            q.z = eW2p[p * 64 + c + 32];
            q.w = eW2p[(p + 4) * 64 + c + 32];
            *(uint4*)(w2hU + kp * W2HW + c * 4) = q;
        }
        if (l == 0) {
            for (int idx = t; idx < 32 * 16; idx += 256) {
                int i = idx >> 4, p = idx & 15;
                uint32_t v = 0;
                if (i < NN && p < 11)
                    v = pack_h2(zsh[i * ZROW + 2 * p], zsh[i * ZROW + 2 * p + 1]);
                ztU[i * ZTU + p] = v;
            }
        }
        if (t < 32) {
            int cqv = t >> 3, nf = t & 7;
            ebhU[cqv * 8 + nf] = pack_h2(0.5f * eb2l[nf * 8 + 2 * cqv],
                                         0.5f * eb2l[nf * 8 + 2 * cqv + 1]);
        }
        if (t >= 32 && t < 64) {
            int i = t - 32;
            int cqv = i >> 3, nf = i & 7;
            gwhU[cqv * 8 + nf] = pack_h2(gWl[nf * 8 + 2 * cqv],
                                         gWl[nf * 8 + 2 * cqv + 1]);
        }
        __syncthreads();

        // ======== projections via f16 MMA -> piU|pjU (pre-halved) ========
        {
            float pacc[2][2][4];
            #pragma unroll
            for (int mf = 0; mf < 2; ++mf)
                #pragma unroll
                for (int nfi = 0; nfi < 2; ++nfi)
                    #pragma unroll
                    for (int e = 0; e < 4; ++e) pacc[mf][nfi][e] = 0.f;

            const uint32_t* Wp = g_eW1p + (l * 2 + ((w < 4) ? 0 : 1)) * (12 * 64);
            {
                uint32_t aA[2][4];
                #pragma unroll
                for (int mf = 0; mf < 2; ++mf) {
                    int rb = mf * 16;
                    aA[mf][0] = ztU[(rb + lq) * ZTU + cq];
                    aA[mf][1] = ztU[(rb + lq + 8) * ZTU + cq];
                    aA[mf][2] = ztU[(rb + lq) * ZTU + cq + 4];
                    aA[mf][3] = ztU[(rb + lq + 8) * ZTU + cq + 4];
                }
                #pragma unroll
                for (int nfi = 0; nfi < 2; ++nfi) {
                    const int col = (w & 3) * 16 + nfi * 8 + lq;
                    uint32_t b0 = Wp[cq * 64 + col];
                    uint32_t b1 = Wp[(cq + 4) * 64 + col];
                    #pragma unroll
                    for (int mf = 0; mf < 2; ++mf)
                        mma_f16(pacc[mf][nfi], aA[mf][0], aA[mf][1],
                                aA[mf][2], aA[mf][3], b0, b1);
                }
            }
            {
                uint32_t aA[2][2];
                #pragma unroll
                for (int mf = 0; mf < 2; ++mf) {
                    int rb = mf * 16;
                    aA[mf][0] = ztU[(rb + lq) * ZTU + 8 + cq];
                    aA[mf][1] = ztU[(rb + lq + 8) * ZTU + 8 + cq];
                }
                #pragma unroll
                for (int nfi = 0; nfi < 2; ++nfi) {
                    const int col = (w & 3) * 16 + nfi * 8 + lq;
                    uint32_t b0 = Wp[(8 + cq) * 64 + col];
                    #pragma unroll
                    for (int mf = 0; mf < 2; ++mf)
                        mma_f16_k8(pacc[mf][nfi], aA[mf][0], aA[mf][1], b0);
                }
            }
            uint32_t* dstU = (w < 4) ? piU : pjU;
            #pragma unroll
            for (int nfi = 0; nfi < 2; ++nfi) {
                float ex = 0.f, ey = 0.f;
                if (w < 4) {
                    float2 e2 = *(const float2*)(eb1l + (w & 3) * 16 + nfi * 8 + 2 * cq);
                    ex = e2.x; ey = e2.y;
                }
                const int cp = (w & 3) * 8 + cq * 2 + nfi;
                #pragma unroll
                for (int mf = 0; mf < 2; ++mf) {
                    int r = mf * 16 + lq;
                    dstU[r * PRU + cp] =
                        pack_h2((pacc[mf][nfi][0] + ex) * 0.5f,
                                (pacc[mf][nfi][1] + ey) * 0.5f);
                    dstU[(r + 8) * PRU + cp] =
                        pack_h2((pacc[mf][nfi][2] + ex) * 0.5f,
                                (pacc[mf][nfi][3] + ey) * 0.5f);
                }
            }
        }
        // ---- layernorm, parallel: 32 rows x 8 lanes ----
        {
            const int i = t >> 3, j = t & 7;
            float mu = 0.f, sq = 0.f;
            if (i < NN) {
                #pragma unroll
                for (int c = j; c < DD; c += 8) {
                    float v = zsh[i * ZROW + c];
                    mu += v; sq += v * v;
                }
            }
            mu += __shfl_xor_sync(0xffffffffu, mu, 1);
            mu += __shfl_xor_sync(0xffffffffu, mu, 2);
            mu += __shfl_xor_sync(0xffffffffu, mu, 4);
            sq += __shfl_xor_sync(0xffffffffu, sq, 1);
            sq += __shfl_xor_sync(0xffffffffu, sq, 2);
            sq += __shfl_xor_sync(0xffffffffu, sq, 4);
            mu *= (1.0f / DD);
            float var = sq * (1.0f / DD) - mu * mu;
            float rs = rsqrtf(var + 1e-5f);
            if (i < NN) {
                #pragma unroll
                for (int c = j; c < DD; c += 8)
                    znsh[i * ZROW + c] = (zsh[i * ZROW + c] - mu) * rs * lngl[c] + lnbl[c];
            }
        }
        __syncthreads();

        // ---- per-layer hoist: pj pairs ----
        uint2 pj0q[4], pj1q[4];
        {
            const uint2* pj0p = (const uint2*)(pjU + r0 * PRU);
            const uint2* pj1p = (const uint2*)(pjU + r1 * PRU);
            #pragma unroll
            for (int kk = 0; kk < 4; ++kk) {
                pj0q[kk] = pj0p[kk * 4 + cq];
                pj1q[kk] = pj1p[kk * 4 + cq];
            }
        }
        const uint32_t half05 = bcast_h2(0.5f);

        // ======== edge tiles (fully unrolled, predicated body) ========
        #pragma unroll
        for (int ig = 0; ig < 8; ++ig) {
            const int node = ig * 4 + i_sel;
            if (node < NN) {
                const uint2* pi2 = (const uint2*)(piU + node * PRU);

                // epilogue constants loaded early (broadcast; latency hides under MMAs)
                uint32_t ebr[8], gwh[8];
                *(uint4*)(ebr)     = *(const uint4*)(ebhU + cq * 8);
                *(uint4*)(ebr + 4) = *(const uint4*)(ebhU + cq * 8 + 4);
                *(uint4*)(gwh)     = *(const uint4*)(gwhU + cq * 8);
                *(uint4*)(gwh + 4) = *(const uint4*)(gwhU + cq * 8 + 4);

                float acc[8][4];
                #pragma unroll
                for (int nf = 0; nf < 8; ++nf)
                    #pragma unroll
                    for (int e = 0; e < 4; ++e) acc[nf][e] = 0.f;

                #pragma unroll
                for (int kk = 0; kk < 4; ++kk) {
                    uint2 piq = pi2[kk * 4 + cq];
                    uint32_t a0 = silu_from_h(hadd2u(piq.x, pj0q[kk].x));
                    uint32_t a1 = silu_from_h(hadd2u(piq.x, pj1q[kk].x));
                    uint32_t a2 = silu_from_h(hadd2u(piq.y, pj0q[kk].y));
                    uint32_t a3 = silu_from_h(hadd2u(piq.y, pj1q[kk].y));
                    const uint32_t* wb = w2hU + (kk * 4 + cq) * W2HW + lq * 4;
                    #pragma unroll
                    for (int nf = 0; nf < 4; ++nf) {
                        uint4 q = *(const uint4*)(wb + nf * 32);
                        mma_f16(acc[nf],     a0, a1, a2, a3, q.x, q.y);
                        mma_f16(acc[nf + 4], a0, a1, a2, a3, q.z, q.w);
                    }
                }

                uint32_t m01[8], m23[8];
                uint32_t gph0 = 0, gph1 = 0;
                #pragma unroll
                for (int nf = 0; nf < 8; ++nf) {
                    uint32_t h01 = hfma2u(pack_h2(acc[nf][0], acc[nf][1]), half05, ebr[nf]);
                    uint32_t h23 = hfma2u(pack_h2(acc[nf][2], acc[nf][3]), half05, ebr[nf]);
                    uint32_t u01 = silu_from_h(h01);
                    uint32_t u23 = silu_from_h(h23);
                    m01[nf] = u01; m23[nf] = u23;
                    gph0 = hfma2u(u01, gwh[nf], gph0);
                    gph1 = hfma2u(u23, gwh[nf], gph1);
                }
                float2 gpf0 = h22f2(gph0), gpf1 = h22f2(gph1);
                float gp0 = gpf0.x + gpf0.y;
                float gp1 = gpf1.x + gpf1.y;
                gp0 += __shfl_xor_sync(0xffffffffu, gp0, 1);
                gp0 += __shfl_xor_sync(0xffffffffu, gp0, 2);
                gp1 += __shfl_xor_sync(0xffffffffu, gp1, 1);
                gp1 += __shfl_xor_sync(0xffffffffu, gp1, 2);
                float g0 = sigm_t(gp0 + gbl);
                float g1 = (r1 < NN) ? sigm_t(gp1 + gbl) : 0.f;
                uint32_t g0h = bcast_h2(g0), g1h = bcast_h2(g1);

                uint32_t s8h[8];
                #pragma unroll
                for (int nf = 0; nf < 8; ++nf)
                    s8h[nf] = hfma2u(m23[nf], g1h, hmul2u(m01[nf], g0h));

                // 2-level value-splitting reduction; bb2 deferred to combine pass
                const int bb0 = lq & 1, bb1 = (lq >> 1) & 1, bb2 = (lq >> 2) & 1;
                uint32_t v4h[4];
                #pragma unroll
                for (int j = 0; j < 4; ++j) {
                    uint32_t keep = bb0 ? s8h[4 + j] : s8h[j];
                    uint32_t send = bb0 ? s8h[j]     : s8h[4 + j];
                    v4h[j] = hadd2u(keep, __shfl_xor_sync(0xffffffffu, send, 4));
                }
                uint32_t v2h[2];
                #pragma unroll
                for (int j = 0; j < 2; ++j) {
                    uint32_t keep = bb1 ? v4h[2 + j] : v4h[j];
                    uint32_t send = bb1 ? v4h[j]     : v4h[2 + j];
                    v2h[j] = hadd2u(keep, __shfl_xor_sync(0xffffffffu, send, 8));
                }
                // store both pair-partials to plane (jh*2 + bb2)
                const int pbase = bb0 * 4 + bb1 * 2;
                uint32_t* mg = maggU + (jh * 2 + bb2) * MPL + node * MAGU;
                mg[pbase * 4 + cq]       = v2h[0];
                mg[(pbase + 1) * 4 + cq] = v2h[1];
            }
        }
        __syncthreads();

        // ======== combine 4 planes + concat buffer (packed half2) ========
        for (int idx = t; idx < NN * 32; idx += 256) {   // m_i pairs, rows < NN
            uint32_t v = hadd2u(hadd2u(maggU[idx],           maggU[MPL + idx]),
                                hadd2u(maggU[2 * MPL + idx], maggU[3 * MPL + idx]));
            int i = idx >> 5, p = idx & 31;
            catshU[i * CATU + 11 + p] = v;
        }
        for (int idx = t; idx < 3 * 32; idx += 256) {    // zero m_i rows 29..31
            int i = NN + (idx >> 5), p = idx & 31;
            catshU[i * CATU + 11 + p] = 0;
        }
        for (int idx = t; idx < 32 * 16; idx += 256) {   // zn pairs + tail zeros
            int i = idx >> 4, p = idx & 15;
            if (p < 11) {
                uint32_t v = 0;
                if (i < NN) v = pack_h2(znsh[i * ZROW + 2 * p], znsh[i * ZROW + 2 * p + 1]);
                catshU[i * CATU + p] = v;
            } else {
                catshU[i * CATU + 32 + p] = 0;
            }
        }
        __syncthreads();

        // ======== node MLP layer 1 via f16 MMA: [32x88] @ [86x64] ========
        {
            const int mh  = w & 1;
            const int nh4 = w >> 1;
            const int row0 = mh * 16 + lq, row1 = row0 + 8;
            float c2[2][4];
            #pragma unroll
            for (int nfi = 0; nfi < 2; ++nfi)
                #pragma unroll
                for (int e = 0; e < 4; ++e) c2[nfi][e] = 0.f;

            #pragma unroll
            for (int kk = 0; kk < 5; ++kk) {
                uint32_t a0 = catshU[row0 * CATU + kk * 8 + cq];
                uint32_t a1 = catshU[row1 * CATU + kk * 8 + cq];
                uint32_t a2 = catshU[row0 * CATU + kk * 8 + cq + 4];
                uint32_t a3 = catshU[row1 * CATU + kk * 8 + cq + 4];
                #pragma unroll
                for (int nfi = 0; nfi < 2; ++nfi) {
                    const int col = (nh4 * 2 + nfi) * 8 + lq;
                    uint32_t b0 = nW1p[(kk * 8 + cq) * 64 + col];
                    uint32_t b1 = nW1p[(kk * 8 + cq + 4) * 64 + col];
                    mma_f16(c2[nfi], a0, a1, a2, a3, b0, b1);
                }
            }
            {
                uint32_t a0 = catshU[row0 * CATU + 40 + cq];
                uint32_t a1 = catshU[row1 * CATU + 40 + cq];
                #pragma unroll
                for (int nfi = 0; nfi < 2; ++nfi) {
                    const int col = (nh4 * 2 + nfi) * 8 + lq;
                    uint32_t b0 = nW1p[(40 + cq) * 64 + col];
                    mma_f16_k8(c2[nfi], a0, a1, b0);
                }
            }
            #pragma unroll
            for (int nfi = 0; nfi < 2; ++nfi) {
                const int colb = (nh4 * 2 + nfi) * 8 + 2 * cq;
                float2 nb = *(const float2*)(nb1l + colb);
                const int pid = colb >> 1;
                hbufU[row0 * HBU + pid] =
                    pack_h2(silu_t(c2[nfi][0] + nb.x), silu_t(c2[nfi][1] + nb.y));
                hbufU[row1 * HBU + pid] =
                    pack_h2(silu_t(c2[nfi][2] + nb.x), silu_t(c2[nfi][3] + nb.y));
            }
        }
        __syncthreads();

        // ======== node MLP layer 2 via f16 MMA + residual; writes zsh AND ztU ========
        if (w < 6) {
            const int mf = w & 1;
            const int nf = w >> 1;
            const int d0 = nf * 8 + lq;
            const int rr0 = mf * 16 + lq, rr1 = rr0 + 8;
            float c4[4] = {0.f, 0.f, 0.f, 0.f};
            #pragma unroll
            for (int kk = 0; kk < 4; ++kk) {
                uint32_t a0 = hbufU[rr0 * HBU + kk * 8 + cq];
                uint32_t a1 = hbufU[rr1 * HBU + kk * 8 + cq];
                uint32_t a2 = hbufU[rr0 * HBU + kk * 8 + cq + 4];
                uint32_t a3 = hbufU[rr1 * HBU + kk * 8 + cq + 4];
                uint32_t b0 = nW2p[(kk * 8 + cq) * 24 + d0];
                uint32_t b1 = nW2p[(kk * 8 + cq + 4) * 24 + d0];
                mma_f16(c4, a0, a1, a2, a3, b0, b1);
            }
            const int col = nf * 8 + 2 * cq;
            if (col < DD) {
                float nb0 = nb2l[col];
                float nb1v = nb2l[col + 1];
                if (rr0 < NN) {
                    float z0 = zsh[rr0 * ZROW + col] + c4[0] + nb0;
                    float z1 = zsh[rr0 * ZROW + col + 1] + c4[1] + nb1v;
                    zsh[rr0 * ZROW + col] = z0;
                    zsh[rr0 * ZROW + col + 1] = z1;
                    ztU[rr0 * ZTU + (col >> 1)] = pack_h2(z0, z1);
                }
                if (rr1 < NN) {
                    float z0 = zsh[rr1 * ZROW + col] + c4[2] + nb0;
                    float z1 = zsh[rr1 * ZROW + col + 1] + c4[3] + nb1v;
                    zsh[rr1 * ZROW + col] = z0;
                    zsh[rr1 * ZROW + col + 1] = z1;
                    ztU[rr1 * ZTU + (col >> 1)] = pack_h2(z0, z1);
                }
            }
        }
        __syncthreads();
    }

    // ---- mean pool ----
    if (t < DD) {
        float s = 0.f;
        #pragma unroll
        for (int i = 0; i < NN; ++i) s += zsh[i * ZROW + t];
        znsh[t] = s * (1.0f / NN);
    }
    __syncthreads();

    // ---- head MLP ----
    float* hscr = znsh + 64;
    if (t < HDIM) {
        float a = hb1[t];
        #pragma unroll
        for (int d = 0; d < DD; ++d) a += znsh[d] * hW1[d * HDIM + t];
        hscr[t] = fmaxf(a, 0.f);
    }
    __syncthreads();

    float* ob = out + (size_t)b * (NN * OUTROW);
    for (int idx = t; idx < NN * OUTROW; idx += 256) {
        float v = 0.f;
        if (idx < NOUT) {
            v = hb2[idx];
            #pragma unroll
            for (int m2 = 0; m2 < HDIM; ++m2)
                v += hscr[m2] * hW2[m2 * NOUT + idx];
        }
        ob[idx] = v;
    }
}

extern "C" void kernel_launch(void* const* d_in, const int* in_sizes, int n_in,
                              void* d_out, int out_size) {
    (void)in_sizes; (void)n_in; (void)out_size;
    const float* x    = (const float*)d_in[0];
    const float* ctx  = (const float*)d_in[1];
    const float* eW1  = (const float*)d_in[2];
    const float* eb1  = (const float*)d_in[3];
    const float* eW2  = (const float*)d_in[4];
    const float* eb2  = (const float*)d_in[5];
    const float* gW   = (const float*)d_in[6];
    const float* gb   = (const float*)d_in[7];
    const float* lng  = (const float*)d_in[8];
    const float* lnb  = (const float*)d_in[9];
    const float* nW1  = (const float*)d_in[10];
    const float* nb1  = (const float*)d_in[11];
    const float* nW2  = (const float*)d_in[12];
    const float* nb2  = (const float*)d_in[13];
    const float* hW1  = (const float*)d_in[14];
    const float* hb1  = (const float*)d_in[15];
    const float* hW2  = (const float*)d_in[16];
    const float* hb2  = (const float*)d_in[17];
    float* out = (float*)d_out;

    prep_pack<<<32, 256>>>(eW1, eW2, nW1, nW2);
    cudaFuncSetAttribute(gnn_kernel, cudaFuncAttributeMaxDynamicSharedMemorySize,
                         SMEM_FLOATS * sizeof(float));
    gnn_kernel<<<NB, 256, SMEM_FLOATS * sizeof(float)>>>(
        x, ctx, eb1, eb2, gW, gb, lng, lnb,
        nb1, nb2, hW1, hb1, hW2, hb2, out);
}